// round 1
// baseline (speedup 1.0000x reference)
#include <cuda_runtime.h>
#include <cuda_bf16.h>

#define M_VOX 100000
#define NQ    8192
#define KNN   32
#define C     256
#define HH    8
#define DHD   32
#define FF    512

// ---------------- scratch (device globals; no allocations allowed) ----------------
__device__ float g_ln[(size_t)M_VOX * C];      // LN(voxel_features)
__device__ float g_q [(size_t)NQ * C];         // q projections
__device__ float g_qp[(size_t)NQ * HH * 37];   // q-side positional bias, x[0..14] y[15..29] z[30..36]
__device__ float g_k [(size_t)NQ * KNN * C];   // k projections
__device__ float g_v [(size_t)NQ * KNN * C];   // v projections
__device__ float g_ao[(size_t)NQ * C];         // attention output (pre-proj)

// ---------------- f32x2 packed-FMA helpers (sm_103a) ----------------
__device__ __forceinline__ unsigned long long pack2(float lo, float hi) {
    unsigned long long r;
    asm("mov.b64 %0, {%1, %2};" : "=l"(r) : "r"(__float_as_uint(lo)), "r"(__float_as_uint(hi)));
    return r;
}
__device__ __forceinline__ void fma2(unsigned long long& d, unsigned long long a, unsigned long long b) {
    asm("fma.rn.f32x2 %0, %1, %2, %3;" : "=l"(d) : "l"(a), "l"(b), "l"(d));
}
__device__ __forceinline__ float2 unpack2(unsigned long long v) {
    unsigned int lo, hi;
    asm("mov.b64 {%0, %1}, %2;" : "=r"(lo), "=r"(hi) : "l"(v));
    return make_float2(__uint_as_float(lo), __uint_as_float(hi));
}

// ---------------- kernel 1: LayerNorm over all M voxels ----------------
__global__ void ln_kernel(const float* __restrict__ x,
                          const float* __restrict__ g,
                          const float* __restrict__ b) {
    int row = blockIdx.x * 8 + (threadIdx.x >> 5);
    if (row >= M_VOX) return;
    int lane = threadIdx.x & 31;
    const float4* xr = (const float4*)(x + (size_t)row * C);
    float4 v0 = xr[lane];
    float4 v1 = xr[lane + 32];
    float s = v0.x + v0.y + v0.z + v0.w + v1.x + v1.y + v1.z + v1.w;
    float q = v0.x*v0.x + v0.y*v0.y + v0.z*v0.z + v0.w*v0.w
            + v1.x*v1.x + v1.y*v1.y + v1.z*v1.z + v1.w*v1.w;
#pragma unroll
    for (int o = 16; o > 0; o >>= 1) {
        s += __shfl_xor_sync(0xffffffffu, s, o);
        q += __shfl_xor_sync(0xffffffffu, q, o);
    }
    float mu = s * (1.0f / C);
    float rs = rsqrtf(q * (1.0f / C) - mu * mu + 1e-5f);
    int c0 = lane * 4, c1 = 128 + lane * 4;
    float4 o0, o1;
    o0.x = (v0.x - mu) * rs * g[c0+0] + b[c0+0];
    o0.y = (v0.y - mu) * rs * g[c0+1] + b[c0+1];
    o0.z = (v0.z - mu) * rs * g[c0+2] + b[c0+2];
    o0.w = (v0.w - mu) * rs * g[c0+3] + b[c0+3];
    o1.x = (v1.x - mu) * rs * g[c1+0] + b[c1+0];
    o1.y = (v1.y - mu) * rs * g[c1+1] + b[c1+1];
    o1.z = (v1.z - mu) * rs * g[c1+2] + b[c1+2];
    o1.w = (v1.w - mu) * rs * g[c1+3] + b[c1+3];
    float4* orow = (float4*)(g_ln + (size_t)row * C);
    orow[lane]      = o0;
    orow[lane + 32] = o1;
}

// ---------------- kernel 2: q projection + q-side positional bias ----------------
// block handles 32 queries; smem: qin[32][256], qs[32][256]  (64KB dynamic)
__global__ void q_kernel(const float* __restrict__ coords, const int* __restrict__ qidx,
                         const float* __restrict__ w_pos, const float* __restrict__ b_pos,
                         const float* __restrict__ w_q,   const float* __restrict__ b_q,
                         const float* __restrict__ pqx, const float* __restrict__ pqy,
                         const float* __restrict__ pqz) {
    extern __shared__ float sm2[];
    float* qin = sm2;              // 32*256
    float* qs  = sm2 + 32 * C;     // 32*256
    int t = threadIdx.x;
    int n0 = blockIdx.x * 32;
    // stage 1: qin = ln[qidx] + relu(coords @ w_pos + b_pos)
    for (int r = 0; r < 32; r++) {
        int n = n0 + r;
        float cx = coords[n*3+0], cy = coords[n*3+1], cz = coords[n*3+2];
        float p = cx * w_pos[t] + cy * w_pos[C + t] + cz * w_pos[2*C + t] + b_pos[t];
        p = fmaxf(p, 0.0f);
        qin[r*C + t] = g_ln[(size_t)qidx[n]*C + t] + p;
    }
    __syncthreads();
    // stage 2: q = qin @ w_q + b_q  (thread t = output column)
    float acc[32];
#pragma unroll
    for (int r = 0; r < 32; r++) acc[r] = 0.0f;
    for (int c = 0; c < C; c++) {
        float w = w_q[c*C + t];
#pragma unroll
        for (int r = 0; r < 32; r++) acc[r] = fmaf(qin[r*C + c], w, acc[r]);
    }
    float bb = b_q[t];
    for (int r = 0; r < 32; r++) {
        float v = acc[r] + bb;
        qs[r*C + t] = v;
        g_q[(size_t)(n0 + r)*C + t] = v;
    }
    __syncthreads();
    // stage 3: qp[n,h,j] = sum_d q[n,h,d] * pos_q(axis)[h,d,rr]
    for (int idx = t; idx < 32 * HH * 37; idx += 256) {
        int r   = idx / (HH * 37);
        int rem = idx - r * (HH * 37);
        int h   = rem / 37;
        int j   = rem - h * 37;
        const float* tab; int rr, stride;
        if (j < 15)      { tab = pqx + h * DHD * 15; rr = j;      stride = 15; }
        else if (j < 30) { tab = pqy + h * DHD * 15; rr = j - 15; stride = 15; }
        else             { tab = pqz + h * DHD * 7;  rr = j - 30; stride = 7;  }
        float s = 0.0f;
        const float* qrow = qs + r*C + h*DHD;
#pragma unroll
        for (int d = 0; d < DHD; d++) s = fmaf(qrow[d], __ldg(&tab[d*stride + rr]), s);
        g_qp[((size_t)(n0 + r)*HH + h)*37 + j] = s;
    }
}

// ---------------- kernel 3: fused K/V GEMM with gather + mask ----------------
// A: [N*K, 256] gathered ln rows (masked->0); output 512 cols = [w_k | w_v]
// tile: 128 rows x 128 cols, 256 threads, 8x(4 f32x2) micro-tile, f32x2 FMA
__global__ __launch_bounds__(256, 2)
void kv_kernel(const int* __restrict__ gidx, const int* __restrict__ gmask,
               const float* __restrict__ w_k, const float* __restrict__ b_k,
               const float* __restrict__ w_v, const float* __restrict__ b_v) {
    __shared__ __align__(16) float A_s[128 * 12];  // row stride 12 (pad)
    __shared__ __align__(16) float B_s[8 * 128];
    __shared__ int src_s[128];
    __shared__ int msk_s[128];
    int t = threadIdx.x;
    int bx = blockIdx.x;                 // 0,1 -> k cols; 2,3 -> v cols
    int rowStart = blockIdx.y * 128;
    if (t < 128) {
        src_s[t] = gidx[rowStart + t];
        msk_s[t] = gmask[rowStart + t];
    }
    const float* W; const float* bias; int colOff;
    if (bx < 2) { W = w_k; bias = b_k; colOff = bx * 128; }
    else        { W = w_v; bias = b_v; colOff = (bx - 2) * 128; }
    __syncthreads();
    int tx = t & 15, ty = t >> 4;        // 16x16 thread grid
    int arow = t >> 1, apart = t & 1;    // A loader: 128 rows x 2 float4
    const float* aptr = g_ln + (size_t)src_s[arow] * C + apart * 4;
    bool am = (msk_s[arow] != 0);
    int bkk = t >> 5, bc = (t & 31) * 4; // B loader: 8 k-rows x 32 float4

    unsigned long long acc[8][4];
#pragma unroll
    for (int i = 0; i < 8; i++)
#pragma unroll
        for (int j = 0; j < 4; j++) acc[i][j] = 0ull;

    for (int kt = 0; kt < C; kt += 8) {
        float4 av = am ? make_float4(0.f,0.f,0.f,0.f) : *(const float4*)(aptr + kt);
        float4 bv = *(const float4*)(W + (size_t)(kt + bkk) * C + colOff + bc);
        __syncthreads();
        *(float4*)&A_s[arow * 12 + apart * 4] = av;
        *(float4*)&B_s[bkk * 128 + bc] = bv;
        __syncthreads();
        const unsigned long long* B2 = (const unsigned long long*)B_s;
#pragma unroll
        for (int kk = 0; kk < 8; kk++) {
            float a[8];
#pragma unroll
            for (int i = 0; i < 8; i++) a[i] = A_s[(ty * 8 + i) * 12 + kk];
            unsigned long long b2[4];
#pragma unroll
            for (int j = 0; j < 4; j++) b2[j] = B2[kk * 64 + tx + 16 * j];
#pragma unroll
            for (int i = 0; i < 8; i++) {
                unsigned long long a2 = pack2(a[i], a[i]);
#pragma unroll
                for (int j = 0; j < 4; j++) fma2(acc[i][j], a2, b2[j]);
            }
        }
    }
    float* dstBase = (bx < 2) ? g_k : g_v;
#pragma unroll
    for (int i = 0; i < 8; i++) {
        int grow = rowStart + ty * 8 + i;
#pragma unroll
        for (int j = 0; j < 4; j++) {
            int gcol = colOff + tx * 2 + 32 * j;   // column within W (0..255)
            float2 v = unpack2(acc[i][j]);
            v.x += bias[gcol];
            v.y += bias[gcol + 1];
            *(float2*)(dstBase + (size_t)grow * C + gcol) = v;
        }
    }
}

// ---------------- kernel 4: attention per query ----------------
// block = 1 query, 8 warps = 8 heads; smem k[32][256] + v[32][256] + q[256]
__global__ void attn_kernel(const int* __restrict__ gmask,
                            const int* __restrict__ rel_x, const int* __restrict__ rel_y,
                            const int* __restrict__ rel_z,
                            const float* __restrict__ pkx, const float* __restrict__ pky,
                            const float* __restrict__ pkz) {
    extern __shared__ float sm4[];
    float* k_s = sm4;            // 8192
    float* v_s = sm4 + 8192;     // 8192
    float* q_s = sm4 + 16384;    // 256
    __shared__ float attn_s[HH][KNN];
    int n = blockIdx.x, t = threadIdx.x;
    const float4* ksrc = (const float4*)(g_k + (size_t)n * KNN * C);
    const float4* vsrc = (const float4*)(g_v + (size_t)n * KNN * C);
    float4* kd = (float4*)k_s;
    float4* vd = (float4*)v_s;
#pragma unroll
    for (int i = 0; i < 8; i++) {
        kd[t + 256 * i] = ksrc[t + 256 * i];
        vd[t + 256 * i] = vsrc[t + 256 * i];
    }
    if (t < 64) ((float4*)q_s)[t] = ((const float4*)(g_q + (size_t)n * C))[t];
    __syncthreads();

    int h = t >> 5, lane = t & 31;
    // ---- logits: lane = key index ----
    int gi = n * KNN + lane;
    int rx = rel_x[gi], ry = rel_y[gi], rz = rel_z[gi];
    bool msk = (gmask[gi] != 0);
    const float* pbx = pkx + h * DHD * 15 + rx;
    const float* pby = pky + h * DHD * 15 + ry;
    const float* pbz = pkz + h * DHD * 7  + rz;
    const float* krow = k_s + lane * C + h * DHD;
    const float* qh   = q_s + h * DHD;
    float qk = 0.0f, bias = 0.0f;
#pragma unroll
    for (int d = 0; d < DHD; d++) {
        float kv = krow[d];
        qk = fmaf(qh[d], kv, qk);
        float pw = __ldg(pbx + d * 15) + __ldg(pby + d * 15) + __ldg(pbz + d * 7);
        bias = fmaf(kv, pw, bias);
    }
    const float* qpn = g_qp + ((size_t)n * HH + h) * 37;
    float logit = qk * 0.17677669529663687f + qpn[rx] + qpn[15 + ry] + qpn[30 + rz] + bias;
    if (msk) logit = -1e9f;
    // warp softmax over 32 keys
    float m = logit;
#pragma unroll
    for (int o = 16; o > 0; o >>= 1) m = fmaxf(m, __shfl_xor_sync(0xffffffffu, m, o));
    float p = expf(logit - m);
    float s = p;
#pragma unroll
    for (int o = 16; o > 0; o >>= 1) s += __shfl_xor_sync(0xffffffffu, s, o);
    attn_s[h][lane] = p / s;
    __syncwarp();
    // ---- output: lane = d ----
    float o = 0.0f;
    const float* vcol = v_s + h * DHD + lane;
#pragma unroll
    for (int kk = 0; kk < KNN; kk++) o = fmaf(attn_s[h][kk], vcol[kk * C], o);
    g_ao[(size_t)n * C + h * DHD + lane] = o;
}

// ---------------- kernel 5: proj + residual + LN2 + FFN ----------------
// block handles 16 queries; smem: X[16*256] (ao->norm), ACT[16*256], F[16*512] = 64KB
__global__ void ffn_kernel(const float* __restrict__ voxel, const int* __restrict__ qidx,
                           const float* __restrict__ w_proj, const float* __restrict__ b_proj,
                           const float* __restrict__ ln2g,   const float* __restrict__ ln2b,
                           const float* __restrict__ w_ff1,  const float* __restrict__ b_ff1,
                           const float* __restrict__ w_ff2,  const float* __restrict__ b_ff2,
                           float* __restrict__ out) {
    extern __shared__ float sm5[];
    float* X   = sm5;                 // 16*256
    float* ACT = sm5 + 16 * C;        // 16*256
    float* F   = sm5 + 32 * C;        // 16*512
    __shared__ float mu_s[16], rs_s[16];
    int t = threadIdx.x;
    int n0 = blockIdx.x * 16;
    for (int r = 0; r < 16; r++) X[r*C + t] = g_ao[(size_t)(n0 + r)*C + t];
    __syncthreads();
    // GEMM1: proj
    float acc[16];
#pragma unroll
    for (int r = 0; r < 16; r++) acc[r] = 0.0f;
    for (int c = 0; c < C; c++) {
        float w = w_proj[c*C + t];
#pragma unroll
        for (int r = 0; r < 16; r++) acc[r] = fmaf(X[r*C + c], w, acc[r]);
    }
    float bp = b_proj[t];
    for (int r = 0; r < 16; r++)
        ACT[r*C + t] = voxel[(size_t)qidx[n0 + r]*C + t] + acc[r] + bp;
    __syncthreads();
    // LN2 per row (warp w handles rows w, w+8)
    int wid = t >> 5, lane = t & 31;
#pragma unroll
    for (int rr = 0; rr < 2; rr++) {
        int r = wid + rr * 8;
        const float* ar = ACT + r*C;
        float s = 0.0f, q = 0.0f;
#pragma unroll
        for (int i = 0; i < 8; i++) { float v = ar[lane + 32*i]; s += v; q += v*v; }
#pragma unroll
        for (int o = 16; o > 0; o >>= 1) {
            s += __shfl_xor_sync(0xffffffffu, s, o);
            q += __shfl_xor_sync(0xffffffffu, q, o);
        }
        if (lane == 0) {
            float mu = s * (1.0f / C);
            mu_s[r] = mu;
            rs_s[r] = rsqrtf(q * (1.0f / C) - mu * mu + 1e-5f);
        }
    }
    __syncthreads();
    float g2 = ln2g[t], b2 = ln2b[t];
    for (int r = 0; r < 16; r++)
        X[r*C + t] = (ACT[r*C + t] - mu_s[r]) * rs_s[r] * g2 + b2;
    __syncthreads();
    // GEMM2: ff1 + relu (thread t covers cols t and t+256 of FF=512)
    float f1[16], f2[16];
#pragma unroll
    for (int r = 0; r < 16; r++) { f1[r] = 0.0f; f2[r] = 0.0f; }
    for (int c = 0; c < C; c++) {
        float w1 = w_ff1[c*FF + t];
        float w2 = w_ff1[c*FF + t + 256];
#pragma unroll
        for (int r = 0; r < 16; r++) {
            float x = X[r*C + c];
            f1[r] = fmaf(x, w1, f1[r]);
            f2[r] = fmaf(x, w2, f2[r]);
        }
    }
    float bfa = b_ff1[t], bfb = b_ff1[t + 256];
    for (int r = 0; r < 16; r++) {
        F[r*FF + t]       = fmaxf(f1[r] + bfa, 0.0f);
        F[r*FF + t + 256] = fmaxf(f2[r] + bfb, 0.0f);
    }
    __syncthreads();
    // GEMM3: ff2 + residual
#pragma unroll
    for (int r = 0; r < 16; r++) acc[r] = 0.0f;
    for (int j = 0; j < FF; j++) {
        float w = w_ff2[j*C + t];
#pragma unroll
        for (int r = 0; r < 16; r++) acc[r] = fmaf(F[r*FF + j], w, acc[r]);
    }
    float bo = b_ff2[t];
    for (int r = 0; r < 16; r++)
        out[(size_t)(n0 + r)*C + t] = ACT[r*C + t] + acc[r] + bo;
}

// ---------------- launch ----------------
extern "C" void kernel_launch(void* const* d_in, const int* in_sizes, int n_in,
                              void* d_out, int out_size) {
    const float* voxel  = (const float*)d_in[0];
    const float* coords = (const float*)d_in[1];
    const int*   qidx   = (const int*)d_in[2];
    const int*   gidx   = (const int*)d_in[3];
    const int*   gmask  = (const int*)d_in[4];
    const int*   rel_x  = (const int*)d_in[5];
    const int*   rel_y  = (const int*)d_in[6];
    const int*   rel_z  = (const int*)d_in[7];
    const float* w_pos  = (const float*)d_in[8];
    const float* b_pos  = (const float*)d_in[9];
    const float* w_q    = (const float*)d_in[10];
    const float* b_q    = (const float*)d_in[11];
    const float* w_k    = (const float*)d_in[12];
    const float* b_k    = (const float*)d_in[13];
    const float* w_v    = (const float*)d_in[14];
    const float* b_v    = (const float*)d_in[15];
    const float* w_proj = (const float*)d_in[16];
    const float* b_proj = (const float*)d_in[17];
    const float* ln1g   = (const float*)d_in[18];
    const float* ln1b   = (const float*)d_in[19];
    const float* ln2g   = (const float*)d_in[20];
    const float* ln2b   = (const float*)d_in[21];
    const float* w_ff1  = (const float*)d_in[22];
    const float* b_ff1  = (const float*)d_in[23];
    const float* w_ff2  = (const float*)d_in[24];
    const float* b_ff2  = (const float*)d_in[25];
    const float* pqx    = (const float*)d_in[26];
    const float* pqy    = (const float*)d_in[27];
    const float* pqz    = (const float*)d_in[28];
    const float* pkx    = (const float*)d_in[29];
    const float* pky    = (const float*)d_in[30];
    const float* pkz    = (const float*)d_in[31];
    float* out = (float*)d_out;

    cudaFuncSetAttribute(q_kernel,    cudaFuncAttributeMaxDynamicSharedMemorySize, 65536);
    cudaFuncSetAttribute(attn_kernel, cudaFuncAttributeMaxDynamicSharedMemorySize, 66560);
    cudaFuncSetAttribute(ffn_kernel,  cudaFuncAttributeMaxDynamicSharedMemorySize, 65536);

    ln_kernel<<<(M_VOX + 7) / 8, 256>>>(voxel, ln1g, ln1b);
    q_kernel<<<NQ / 32, 256, 65536>>>(coords, qidx, w_pos, b_pos, w_q, b_q, pqx, pqy, pqz);
    kv_kernel<<<dim3(4, (NQ * KNN) / 128), 256>>>(gidx, gmask, w_k, b_k, w_v, b_v);
    attn_kernel<<<NQ, 256, 66560>>>(gmask, rel_x, rel_y, rel_z, pkx, pky, pkz);
    ffn_kernel<<<NQ / 16, 256, 65536>>>(voxel, qidx, w_proj, b_proj, ln2g, ln2b,
                                        w_ff1, b_ff1, w_ff2, b_ff2, out);
}

// round 3
// speedup vs baseline: 2.3193x; 2.3193x over previous
#include <cuda_runtime.h>
#include <cuda_bf16.h>
#include <cstdint>

#define M_VOX 100000
#define NQ    8192
#define KNN   32
#define C     256
#define HH    8
#define DHD   32
#define FF    512

// ---------------- scratch (device globals; no allocations allowed) ----------------
__device__ float g_ln[(size_t)M_VOX * C];              // LN(voxel_features) fp32
__device__ __nv_bfloat16 g_lnh[(size_t)M_VOX * C];     // bf16 hi of LN
__device__ __nv_bfloat16 g_lnl[(size_t)M_VOX * C];     // bf16 lo (residual) of LN
__device__ float g_kall[(size_t)M_VOX * C];            // k projection of ALL voxels
__device__ float g_vall[(size_t)M_VOX * C];            // v projection of ALL voxels
__device__ float g_q [(size_t)NQ * C];                 // q projections
__device__ float g_qp[(size_t)NQ * HH * 37];           // q-side pos bias x[0..14] y[15..29] z[30..36]
__device__ float g_ao[(size_t)NQ * C];                 // attention output (pre-proj)
// W = [w_k | w_v] transposed + bf16-split: [n(512)][k(256)]
__device__ __nv_bfloat16 g_Bh[512 * 256];
__device__ __nv_bfloat16 g_Bl[512 * 256];

// ---------------- helpers ----------------
__device__ __forceinline__ uint32_t smem_u32(const void* p) {
    uint32_t a;
    asm("{ .reg .u64 t; cvta.to.shared.u64 t, %1; cvt.u32.u64 %0, t; }" : "=r"(a) : "l"(p));
    return a;
}
__device__ __forceinline__ void cpasync16(uint32_t dst, const void* src) {
    asm volatile("cp.async.cg.shared.global [%0], [%1], 16;" :: "r"(dst), "l"(src));
}
#define CP_COMMIT()  asm volatile("cp.async.commit_group;" ::: "memory")
#define CP_WAIT(n)   asm volatile("cp.async.wait_group %0;" :: "n"(n) : "memory")

__device__ __forceinline__ void ldsm4(uint32_t* r, uint32_t addr) {
    asm volatile("ldmatrix.sync.aligned.m8n8.x4.shared.b16 {%0,%1,%2,%3}, [%4];"
        : "=r"(r[0]), "=r"(r[1]), "=r"(r[2]), "=r"(r[3]) : "r"(addr));
}
__device__ __forceinline__ void mma16816(float* c, const uint32_t* a, const uint32_t* b) {
    asm volatile(
        "mma.sync.aligned.m16n8k16.row.col.f32.bf16.bf16.f32 "
        "{%0,%1,%2,%3}, {%4,%5,%6,%7}, {%8,%9}, {%0,%1,%2,%3};"
        : "+f"(c[0]), "+f"(c[1]), "+f"(c[2]), "+f"(c[3])
        : "r"(a[0]), "r"(a[1]), "r"(a[2]), "r"(a[3]), "r"(b[0]), "r"(b[1]));
}

// ---------------- kernel 0: prep split/transposed B ----------------
__global__ void bprep_kernel(const float* __restrict__ wk, const float* __restrict__ wv) {
    int idx = blockIdx.x * 256 + threadIdx.x;   // 512*256
    int n = idx >> 8, k = idx & 255;
    float val = (n < 256) ? wk[k * 256 + n] : wv[k * 256 + (n - 256)];
    __nv_bfloat16 h = __float2bfloat16(val);
    float lo = val - __bfloat162float(h);
    g_Bh[idx] = h;
    g_Bl[idx] = __float2bfloat16(lo);
}

// ---------------- kernel 1: LayerNorm over all M voxels (+bf16 split outputs) ------
__global__ void ln_kernel(const float* __restrict__ x,
                          const float* __restrict__ g,
                          const float* __restrict__ b) {
    int row = blockIdx.x * 8 + (threadIdx.x >> 5);
    if (row >= M_VOX) return;
    int lane = threadIdx.x & 31;
    const float4* xr = (const float4*)(x + (size_t)row * C);
    float4 v0 = xr[lane];
    float4 v1 = xr[lane + 32];
    float s = v0.x + v0.y + v0.z + v0.w + v1.x + v1.y + v1.z + v1.w;
    float q = v0.x*v0.x + v0.y*v0.y + v0.z*v0.z + v0.w*v0.w
            + v1.x*v1.x + v1.y*v1.y + v1.z*v1.z + v1.w*v1.w;
#pragma unroll
    for (int o = 16; o > 0; o >>= 1) {
        s += __shfl_xor_sync(0xffffffffu, s, o);
        q += __shfl_xor_sync(0xffffffffu, q, o);
    }
    float mu = s * (1.0f / C);
    float rs = rsqrtf(q * (1.0f / C) - mu * mu + 1e-5f);
    int c0 = lane * 4, c1 = 128 + lane * 4;
    float o0[4], o1[4];
    o0[0] = (v0.x - mu) * rs * g[c0+0] + b[c0+0];
    o0[1] = (v0.y - mu) * rs * g[c0+1] + b[c0+1];
    o0[2] = (v0.z - mu) * rs * g[c0+2] + b[c0+2];
    o0[3] = (v0.w - mu) * rs * g[c0+3] + b[c0+3];
    o1[0] = (v1.x - mu) * rs * g[c1+0] + b[c1+0];
    o1[1] = (v1.y - mu) * rs * g[c1+1] + b[c1+1];
    o1[2] = (v1.z - mu) * rs * g[c1+2] + b[c1+2];
    o1[3] = (v1.w - mu) * rs * g[c1+3] + b[c1+3];
    float4* orow = (float4*)(g_ln + (size_t)row * C);
    orow[lane]      = make_float4(o0[0], o0[1], o0[2], o0[3]);
    orow[lane + 32] = make_float4(o1[0], o1[1], o1[2], o1[3]);
    // bf16 split
    __nv_bfloat162* hrow = (__nv_bfloat162*)(g_lnh + (size_t)row * C);
    __nv_bfloat162* lrow = (__nv_bfloat162*)(g_lnl + (size_t)row * C);
    __nv_bfloat16 h0[4], h1[4];
    __nv_bfloat16 l0[4], l1[4];
#pragma unroll
    for (int i = 0; i < 4; i++) {
        h0[i] = __float2bfloat16(o0[i]);
        l0[i] = __float2bfloat16(o0[i] - __bfloat162float(h0[i]));
        h1[i] = __float2bfloat16(o1[i]);
        l1[i] = __float2bfloat16(o1[i] - __bfloat162float(h1[i]));
    }
    hrow[lane*2+0]  = __nv_bfloat162{h0[0], h0[1]};
    hrow[lane*2+1]  = __nv_bfloat162{h0[2], h0[3]};
    hrow[64+lane*2] = __nv_bfloat162{h1[0], h1[1]};
    hrow[65+lane*2] = __nv_bfloat162{h1[2], h1[3]};
    lrow[lane*2+0]  = __nv_bfloat162{l0[0], l0[1]};
    lrow[lane*2+1]  = __nv_bfloat162{l0[2], l0[3]};
    lrow[64+lane*2] = __nv_bfloat162{l1[0], l1[1]};
    lrow[65+lane*2] = __nv_bfloat162{l1[2], l1[3]};
}

// ---------------- kernel 2: q projection + q-side positional bias ----------------
__global__ void q_kernel(const float* __restrict__ coords, const int* __restrict__ qidx,
                         const float* __restrict__ w_pos, const float* __restrict__ b_pos,
                         const float* __restrict__ w_q,   const float* __restrict__ b_q,
                         const float* __restrict__ pqx, const float* __restrict__ pqy,
                         const float* __restrict__ pqz) {
    extern __shared__ float sm2[];
    float* qin = sm2;
    float* qs  = sm2 + 32 * C;
    int t = threadIdx.x;
    int n0 = blockIdx.x * 32;
    for (int r = 0; r < 32; r++) {
        int n = n0 + r;
        float cx = coords[n*3+0], cy = coords[n*3+1], cz = coords[n*3+2];
        float p = cx * w_pos[t] + cy * w_pos[C + t] + cz * w_pos[2*C + t] + b_pos[t];
        p = fmaxf(p, 0.0f);
        qin[r*C + t] = g_ln[(size_t)qidx[n]*C + t] + p;
    }
    __syncthreads();
    float acc[32];
#pragma unroll
    for (int r = 0; r < 32; r++) acc[r] = 0.0f;
    for (int c = 0; c < C; c++) {
        float w = w_q[c*C + t];
#pragma unroll
        for (int r = 0; r < 32; r++) acc[r] = fmaf(qin[r*C + c], w, acc[r]);
    }
    float bb = b_q[t];
    for (int r = 0; r < 32; r++) {
        float v = acc[r] + bb;
        qs[r*C + t] = v;
        g_q[(size_t)(n0 + r)*C + t] = v;
    }
    __syncthreads();
    for (int idx = t; idx < 32 * HH * 37; idx += 256) {
        int r   = idx / (HH * 37);
        int rem = idx - r * (HH * 37);
        int h   = rem / 37;
        int j   = rem - h * 37;
        const float* tab; int rr, stride;
        if (j < 15)      { tab = pqx + h * DHD * 15; rr = j;      stride = 15; }
        else if (j < 30) { tab = pqy + h * DHD * 15; rr = j - 15; stride = 15; }
        else             { tab = pqz + h * DHD * 7;  rr = j - 30; stride = 7;  }
        float s = 0.0f;
        const float* qrow = qs + r*C + h*DHD;
#pragma unroll
        for (int d = 0; d < DHD; d++) s = fmaf(qrow[d], __ldg(&tab[d*stride + rr]), s);
        g_qp[((size_t)(n0 + r)*HH + h)*37 + j] = s;
    }
}

// ---------------- kernel 3: K/V projection GEMM for ALL voxels (tensor cores) ------
// out[100000+pad, 512] = lnh/lnl[100000,256] @ Bh/Bl[256,512]  with 3-term bf16 split
// CTA tile 128x128, k-chunk 32, 8 warps (2m x 4n), warp tile 64x32, cp.async 2-stage.
#define APITCH 40            // bf16 elems per smem row (80B, conflict-free ldmatrix)
#define MAT_BYTES (128 * APITCH * 2)        // 10240
#define STAGE_BYTES (4 * MAT_BYTES)         // Ah, Al, Bh, Bl = 40960
// dynamic smem = 2 stages = 81920

__global__ __launch_bounds__(256)
void kvgemm_kernel(const float* __restrict__ bk, const float* __restrict__ bv) {
    extern __shared__ __align__(16) char gsm[];
    uint32_t sb = smem_u32(gsm);
    int t = threadIdx.x;
    int warp = t >> 5, lane = t & 31;
    int n0 = blockIdx.x * 128;           // 0..511 over [wk|wv] cols
    int m0 = blockIdx.y * 128;

    // loader lambda: 4 matrices x 512 16B-units; 256 threads x 2 units each
    auto load_chunk = [&](int kc, int buf) {
        uint32_t base = sb + buf * STAGE_BYTES;
#pragma unroll
        for (int i = 0; i < 2; i++) {
            int u = t + i * 256;         // 0..511
            int row = u >> 2, seg = u & 3;
            int gr = m0 + row; if (gr >= M_VOX) gr = 0;
            size_t go = (size_t)gr * 256 + kc * 32 + seg * 8;
            uint32_t so = base + (row * APITCH + seg * 8) * 2;
            cpasync16(so,                 g_lnh + go);
            cpasync16(so + MAT_BYTES,     g_lnl + go);
            size_t gb = (size_t)(n0 + row) * 256 + kc * 32 + seg * 8;
            uint32_t sob = base + 2 * MAT_BYTES + (row * APITCH + seg * 8) * 2;
            cpasync16(sob,                g_Bh + gb);
            cpasync16(sob + MAT_BYTES,    g_Bl + gb);
        }
    };

    int wm = warp & 1, wn = warp >> 1;   // 2 x 4
    float acc[4][4][4];
#pragma unroll
    for (int a = 0; a < 4; a++)
#pragma unroll
        for (int bq = 0; bq < 4; bq++)
#pragma unroll
            for (int cq = 0; cq < 4; cq++) acc[a][bq][cq] = 0.0f;

    load_chunk(0, 0); CP_COMMIT();

    for (int kc = 0; kc < 8; kc++) {
        int buf = kc & 1;
        if (kc < 7) { load_chunk(kc + 1, buf ^ 1); CP_COMMIT(); CP_WAIT(1); }
        else        { CP_WAIT(0); }
        __syncthreads();

        uint32_t abase = sb + buf * STAGE_BYTES;
        uint32_t bbase = abase + 2 * MAT_BYTES;
        // B fragments: ldmatrix x4 covers n8 x k32
        uint32_t bh[4][4], bl[4][4];
#pragma unroll
        for (int ni = 0; ni < 4; ni++) {
            int nrow = wn * 32 + ni * 8 + (lane & 7);
            int koff = (lane >> 3) * 8;
            uint32_t ad = bbase + (nrow * APITCH + koff) * 2;
            ldsm4(bh[ni], ad);
            ldsm4(bl[ni], ad + MAT_BYTES);
        }
#pragma unroll
        for (int s = 0; s < 2; s++) {
#pragma unroll
            for (int mi = 0; mi < 4; mi++) {
                int arow = wm * 64 + mi * 16 + (lane & 15);
                int koff = s * 16 + (lane >> 4) * 8;
                uint32_t ad = abase + (arow * APITCH + koff) * 2;
                uint32_t ah[4], al[4];
                ldsm4(ah, ad);
                ldsm4(al, ad + MAT_BYTES);
#pragma unroll
                for (int ni = 0; ni < 4; ni++) {
                    mma16816(acc[mi][ni], ah, &bh[ni][s*2]);
                    mma16816(acc[mi][ni], ah, &bl[ni][s*2]);
                    mma16816(acc[mi][ni], al, &bh[ni][s*2]);
                }
            }
        }
        __syncthreads();
    }

    // epilogue: bias + store (n0<256 -> k, else v); uniform per CTA
    float* dst = (n0 < 256) ? g_kall : g_vall;
    const float* bias = (n0 < 256) ? bk : bv;
    int cb = n0 & 255;
#pragma unroll
    for (int mi = 0; mi < 4; mi++) {
#pragma unroll
        for (int ni = 0; ni < 4; ni++) {
            int col = cb + wn * 32 + ni * 8 + (lane & 3) * 2;
            float b0 = bias[col], b1 = bias[col + 1];
            int r0 = m0 + wm * 64 + mi * 16 + (lane >> 2);
            if (r0 < M_VOX)
                *(float2*)(dst + (size_t)r0 * 256 + col) =
                    make_float2(acc[mi][ni][0] + b0, acc[mi][ni][1] + b1);
            int r1 = r0 + 8;
            if (r1 < M_VOX)
                *(float2*)(dst + (size_t)r1 * 256 + col) =
                    make_float2(acc[mi][ni][2] + b0, acc[mi][ni][3] + b1);
        }
    }
}

// ---------------- kernel 4: attention per query (gather precomputed k/v) ----------
#define KPITCH 260
__global__ __launch_bounds__(256)
void attn_kernel(const int* __restrict__ gidx, const int* __restrict__ gmask,
                 const int* __restrict__ rel_x, const int* __restrict__ rel_y,
                 const int* __restrict__ rel_z,
                 const float* __restrict__ bk, const float* __restrict__ bv,
                 const float* __restrict__ pkx, const float* __restrict__ pky,
                 const float* __restrict__ pkz) {
    extern __shared__ float sm4[];
    float* k_s = sm4;                    // 32 x KPITCH
    float* v_s = sm4 + 32 * KPITCH;
    __shared__ float q_s[256];
    __shared__ float qp_s[296];
    __shared__ float attn_s[HH][KNN];
    __shared__ int idx_s[32], msk_s[32], rx_s[32], ry_s[32], rz_s[32];
    int n = blockIdx.x, t = threadIdx.x;
    if (t < 32) {
        idx_s[t] = gidx[n*KNN + t];
        msk_s[t] = gmask[n*KNN + t];
        rx_s[t]  = rel_x[n*KNN + t];
        ry_s[t]  = rel_y[n*KNN + t];
        rz_s[t]  = rel_z[n*KNN + t];
    } else if (t < 96) {
        int i = t - 32;
        ((float4*)q_s)[i] = ((const float4*)(g_q + (size_t)n * C))[i];
    } else if (t < 170) {
        int i = t - 96;
        ((float4*)qp_s)[i] = ((const float4*)(g_qp + (size_t)n * 296))[i];
    }
    __syncthreads();
#pragma unroll
    for (int i = 0; i < 8; i++) {
        int u = t + i * 256;
        int row = u >> 6, seg = u & 63;
        bool m = (msk_s[row] != 0);
        const float4* ks = m ? (const float4*)bk
                             : (const float4*)(g_kall + (size_t)idx_s[row] * C);
        const float4* vs = m ? (const float4*)bv
                             : (const float4*)(g_vall + (size_t)idx_s[row] * C);
        ((float4*)(k_s + row * KPITCH))[seg] = __ldg(&ks[seg]);
        ((float4*)(v_s + row * KPITCH))[seg] = __ldg(&vs[seg]);
    }
    __syncthreads();

    int h = t >> 5, lane = t & 31;
    // logits: lane = key
    {
        int rx = rx_s[lane], ry = ry_s[lane], rz = rz_s[lane];
        bool msk = (msk_s[lane] != 0);
        const float* krow = k_s + lane * KPITCH + h * DHD;
        const float* qh   = q_s + h * DHD;
        const float* pbx = pkx + h * DHD * 15 + rx;
        const float* pby = pky + h * DHD * 15 + ry;
        const float* pbz = pkz + h * DHD * 7  + rz;
        float qk = 0.0f, bias = 0.0f;
#pragma unroll
        for (int d = 0; d < DHD; d++) {
            float kv = krow[d];
            qk = fmaf(qh[d], kv, qk);
            float pw = __ldg(pbx + d * 15) + __ldg(pby + d * 15) + __ldg(pbz + d * 7);
            bias = fmaf(kv, pw, bias);
        }
        const float* qpn = qp_s + h * 37;
        float logit = qk * 0.17677669529663687f + qpn[rx] + qpn[15 + ry] + qpn[30 + rz] + bias;
        if (msk) logit = -1e9f;
        float m = logit;
#pragma unroll
        for (int o = 16; o > 0; o >>= 1) m = fmaxf(m, __shfl_xor_sync(0xffffffffu, m, o));
        float p = expf(logit - m);
        float s = p;
#pragma unroll
        for (int o = 16; o > 0; o >>= 1) s += __shfl_xor_sync(0xffffffffu, s, o);
        attn_s[h][lane] = p / s;
    }
    __syncwarp();
    // output: lane = d
    {
        float o = 0.0f;
        const float* vcol = v_s + h * DHD + lane;
        const float* aw = attn_s[h];
#pragma unroll
        for (int kk = 0; kk < KNN; kk++) o = fmaf(aw[kk], vcol[kk * KPITCH], o);
        g_ao[(size_t)n * C + h * DHD + lane] = o;
    }
}

// ---------------- kernel 5: proj + residual + LN2 + FFN ----------------
__global__ void ffn_kernel(const float* __restrict__ voxel, const int* __restrict__ qidx,
                           const float* __restrict__ w_proj, const float* __restrict__ b_proj,
                           const float* __restrict__ ln2g,   const float* __restrict__ ln2b,
                           const float* __restrict__ w_ff1,  const float* __restrict__ b_ff1,
                           const float* __restrict__ w_ff2,  const float* __restrict__ b_ff2,
                           float* __restrict__ out) {
    extern __shared__ float sm5[];
    float* X   = sm5;
    float* ACT = sm5 + 16 * C;
    float* F   = sm5 + 32 * C;
    __shared__ float mu_s[16], rs_s[16];
    int t = threadIdx.x;
    int n0 = blockIdx.x * 16;
    for (int r = 0; r < 16; r++) X[r*C + t] = g_ao[(size_t)(n0 + r)*C + t];
    __syncthreads();
    float acc[16];
#pragma unroll
    for (int r = 0; r < 16; r++) acc[r] = 0.0f;
    for (int c = 0; c < C; c++) {
        float w = w_proj[c*C + t];
#pragma unroll
        for (int r = 0; r < 16; r++) acc[r] = fmaf(X[r*C + c], w, acc[r]);
    }
    float bp = b_proj[t];
    for (int r = 0; r < 16; r++)
        ACT[r*C + t] = voxel[(size_t)qidx[n0 + r]*C + t] + acc[r] + bp;
    __syncthreads();
    int wid = t >> 5, lane = t & 31;
#pragma unroll
    for (int rr = 0; rr < 2; rr++) {
        int r = wid + rr * 8;
        const float* ar = ACT + r*C;
        float s = 0.0f, q = 0.0f;
#pragma unroll
        for (int i = 0; i < 8; i++) { float v = ar[lane + 32*i]; s += v; q += v*v; }
#pragma unroll
        for (int o = 16; o > 0; o >>= 1) {
            s += __shfl_xor_sync(0xffffffffu, s, o);
            q += __shfl_xor_sync(0xffffffffu, q, o);
        }
        if (lane == 0) {
            float mu = s * (1.0f / C);
            mu_s[r] = mu;
            rs_s[r] = rsqrtf(q * (1.0f / C) - mu * mu + 1e-5f);
        }
    }
    __syncthreads();
    float g2 = ln2g[t], b2 = ln2b[t];
    for (int r = 0; r < 16; r++)
        X[r*C + t] = (ACT[r*C + t] - mu_s[r]) * rs_s[r] * g2 + b2;
    __syncthreads();
    float f1[16], f2[16];
#pragma unroll
    for (int r = 0; r < 16; r++) { f1[r] = 0.0f; f2[r] = 0.0f; }
    for (int c = 0; c < C; c++) {
        float w1 = w_ff1[c*FF + t];
        float w2 = w_ff1[c*FF + t + 256];
#pragma unroll
        for (int r = 0; r < 16; r++) {
            float x = X[r*C + c];
            f1[r] = fmaf(x, w1, f1[r]);
            f2[r] = fmaf(x, w2, f2[r]);
        }
    }
    float bfa = b_ff1[t], bfb = b_ff1[t + 256];
    for (int r = 0; r < 16; r++) {
        F[r*FF + t]       = fmaxf(f1[r] + bfa, 0.0f);
        F[r*FF + t + 256] = fmaxf(f2[r] + bfb, 0.0f);
    }
    __syncthreads();
#pragma unroll
    for (int r = 0; r < 16; r++) acc[r] = 0.0f;
    for (int j = 0; j < FF; j++) {
        float w = w_ff2[j*C + t];
#pragma unroll
        for (int r = 0; r < 16; r++) acc[r] = fmaf(F[r*FF + j], w, acc[r]);
    }
    float bo = b_ff2[t];
    for (int r = 0; r < 16; r++)
        out[(size_t)(n0 + r)*C + t] = ACT[r*C + t] + acc[r] + bo;
}

// ---------------- launch ----------------
extern "C" void kernel_launch(void* const* d_in, const int* in_sizes, int n_in,
                              void* d_out, int out_size) {
    const float* voxel  = (const float*)d_in[0];
    const float* coords = (const float*)d_in[1];
    const int*   qidx   = (const int*)d_in[2];
    const int*   gidx   = (const int*)d_in[3];
    const int*   gmask  = (const int*)d_in[4];
    const int*   rel_x  = (const int*)d_in[5];
    const int*   rel_y  = (const int*)d_in[6];
    const int*   rel_z  = (const int*)d_in[7];
    const float* w_pos  = (const float*)d_in[8];
    const float* b_pos  = (const float*)d_in[9];
    const float* w_q    = (const float*)d_in[10];
    const float* b_q    = (const float*)d_in[11];
    const float* w_k    = (const float*)d_in[12];
    const float* b_k    = (const float*)d_in[13];
    const float* w_v    = (const float*)d_in[14];
    const float* b_v    = (const float*)d_in[15];
    const float* w_proj = (const float*)d_in[16];
    const float* b_proj = (const float*)d_in[17];
    const float* ln1g   = (const float*)d_in[18];
    const float* ln1b   = (const float*)d_in[19];
    const float* ln2g   = (const float*)d_in[20];
    const float* ln2b   = (const float*)d_in[21];
    const float* w_ff1  = (const float*)d_in[22];
    const float* b_ff1  = (const float*)d_in[23];
    const float* w_ff2  = (const float*)d_in[24];
    const float* b_ff2  = (const float*)d_in[25];
    const float* pqx    = (const float*)d_in[26];
    const float* pqy    = (const float*)d_in[27];
    const float* pqz    = (const float*)d_in[28];
    const float* pkx    = (const float*)d_in[29];
    const float* pky    = (const float*)d_in[30];
    const float* pkz    = (const float*)d_in[31];
    float* out = (float*)d_out;

    cudaFuncSetAttribute(q_kernel,      cudaFuncAttributeMaxDynamicSharedMemorySize, 65536);
    cudaFuncSetAttribute(kvgemm_kernel, cudaFuncAttributeMaxDynamicSharedMemorySize, 2 * STAGE_BYTES);
    cudaFuncSetAttribute(attn_kernel,   cudaFuncAttributeMaxDynamicSharedMemorySize, 2 * 32 * KPITCH * 4);
    cudaFuncSetAttribute(ffn_kernel,    cudaFuncAttributeMaxDynamicSharedMemorySize, 65536);

    bprep_kernel<<<512, 256>>>(w_k, w_v);
    ln_kernel<<<(M_VOX + 7) / 8, 256>>>(voxel, ln1g, ln1b);
    q_kernel<<<NQ / 32, 256, 65536>>>(coords, qidx, w_pos, b_pos, w_q, b_q, pqx, pqy, pqz);
    kvgemm_kernel<<<dim3(4, (M_VOX + 127) / 128), 256, 2 * STAGE_BYTES>>>(b_k, b_v);
    attn_kernel<<<NQ, 256, 2 * 32 * KPITCH * 4>>>(gidx, gmask, rel_x, rel_y, rel_z,
                                                  b_k, b_v, pkx, pky, pkz);
    ffn_kernel<<<NQ / 16, 256, 65536>>>(voxel, qidx, w_proj, b_proj, ln2g, ln2b,
                                        w_ff1, b_ff1, w_ff2, b_ff2, out);
}

// round 4
// speedup vs baseline: 3.0000x; 1.2935x over previous
#include <cuda_runtime.h>
#include <cuda_bf16.h>
#include <cstdint>

#define M_VOX 100000
#define NQ    8192
#define KNN   32
#define C     256
#define HH    8
#define DHD   32
#define FF    512

// ---------------- scratch (device globals; no allocations allowed) ----------------
__device__ __nv_bfloat16 g_lnh[(size_t)M_VOX * C];     // bf16 hi of LN
__device__ __nv_bfloat16 g_lnl[(size_t)M_VOX * C];     // bf16 lo (residual) of LN
__device__ float g_kall[(size_t)M_VOX * C];            // k projection of ALL voxels
__device__ float g_vall[(size_t)M_VOX * C];            // v projection of ALL voxels
__device__ float g_q [(size_t)NQ * C];                 // q projections
__device__ float g_qp[(size_t)NQ * HH * 37];           // q-side pos bias
__device__ __nv_bfloat16 g_aoh[(size_t)NQ * C];        // attention out bf16 hi
__device__ __nv_bfloat16 g_aol[(size_t)NQ * C];        // attention out bf16 lo
__device__ float g_act[(size_t)NQ * C];                // ACT = voxel[qidx] + proj(ao)
__device__ __nv_bfloat16 g_xh[(size_t)NQ * C];         // LN2(ACT) bf16 hi
__device__ __nv_bfloat16 g_xl[(size_t)NQ * C];
__device__ __nv_bfloat16 g_fh[(size_t)NQ * FF];        // relu(ff1) bf16 hi
__device__ __nv_bfloat16 g_fl[(size_t)NQ * FF];
// weights transposed + bf16-split, layout [n][k]
__device__ __nv_bfloat16 g_Bh[512 * 256];              // [wk|wv]
__device__ __nv_bfloat16 g_Bl[512 * 256];
__device__ __nv_bfloat16 g_Wph[256 * 256];             // w_proj
__device__ __nv_bfloat16 g_Wpl[256 * 256];
__device__ __nv_bfloat16 g_W1h[512 * 256];             // w_ff1
__device__ __nv_bfloat16 g_W1l[512 * 256];
__device__ __nv_bfloat16 g_W2h[256 * 512];             // w_ff2
__device__ __nv_bfloat16 g_W2l[256 * 512];

// ---------------- helpers ----------------
__device__ __forceinline__ uint32_t smem_u32(const void* p) {
    uint32_t a;
    asm("{ .reg .u64 t; cvta.to.shared.u64 t, %1; cvt.u32.u64 %0, t; }" : "=r"(a) : "l"(p));
    return a;
}
__device__ __forceinline__ void cpasync16(uint32_t dst, const void* src) {
    asm volatile("cp.async.cg.shared.global [%0], [%1], 16;" :: "r"(dst), "l"(src));
}
#define CP_COMMIT()  asm volatile("cp.async.commit_group;" ::: "memory")
#define CP_WAIT(n)   asm volatile("cp.async.wait_group %0;" :: "n"(n) : "memory")

__device__ __forceinline__ void ldsm4(uint32_t* r, uint32_t addr) {
    asm volatile("ldmatrix.sync.aligned.m8n8.x4.shared.b16 {%0,%1,%2,%3}, [%4];"
        : "=r"(r[0]), "=r"(r[1]), "=r"(r[2]), "=r"(r[3]) : "r"(addr));
}
__device__ __forceinline__ void mma16816(float* c, const uint32_t* a, const uint32_t* b) {
    asm volatile(
        "mma.sync.aligned.m16n8k16.row.col.f32.bf16.bf16.f32 "
        "{%0,%1,%2,%3}, {%4,%5,%6,%7}, {%8,%9}, {%0,%1,%2,%3};"
        : "+f"(c[0]), "+f"(c[1]), "+f"(c[2]), "+f"(c[3])
        : "r"(a[0]), "r"(a[1]), "r"(a[2]), "r"(a[3]), "r"(b[0]), "r"(b[1]));
}

// ---------------- weight prep: transpose + bf16 split ----------------
__global__ void bprep_kernel(const float* __restrict__ wk, const float* __restrict__ wv) {
    int idx = blockIdx.x * 256 + threadIdx.x;   // 512*256
    int n = idx >> 8, k = idx & 255;
    float val = (n < 256) ? wk[k * 256 + n] : wv[k * 256 + (n - 256)];
    __nv_bfloat16 h = __float2bfloat16(val);
    g_Bh[idx] = h;
    g_Bl[idx] = __float2bfloat16(val - __bfloat162float(h));
}
// src [K][N] row-major -> dst [N][K]
__global__ void wprep_kernel(const float* __restrict__ src, int N, int K,
                             __nv_bfloat16* __restrict__ dh, __nv_bfloat16* __restrict__ dl) {
    int idx = blockIdx.x * 256 + threadIdx.x;   // N*K total
    int n = idx / K, k = idx - n * K;
    float val = src[k * N + n];
    __nv_bfloat16 h = __float2bfloat16(val);
    dh[idx] = h;
    dl[idx] = __float2bfloat16(val - __bfloat162float(h));
}

// ---------------- kernel 1: LayerNorm over all M voxels -> bf16 split only --------
__global__ void ln_kernel(const float* __restrict__ x,
                          const float* __restrict__ g,
                          const float* __restrict__ b) {
    int row = blockIdx.x * 8 + (threadIdx.x >> 5);
    if (row >= M_VOX) return;
    int lane = threadIdx.x & 31;
    const float4* xr = (const float4*)(x + (size_t)row * C);
    float4 v0 = xr[lane];
    float4 v1 = xr[lane + 32];
    float s = v0.x + v0.y + v0.z + v0.w + v1.x + v1.y + v1.z + v1.w;
    float q = v0.x*v0.x + v0.y*v0.y + v0.z*v0.z + v0.w*v0.w
            + v1.x*v1.x + v1.y*v1.y + v1.z*v1.z + v1.w*v1.w;
#pragma unroll
    for (int o = 16; o > 0; o >>= 1) {
        s += __shfl_xor_sync(0xffffffffu, s, o);
        q += __shfl_xor_sync(0xffffffffu, q, o);
    }
    float mu = s * (1.0f / C);
    float rs = rsqrtf(q * (1.0f / C) - mu * mu + 1e-5f);
    int c0 = lane * 4, c1 = 128 + lane * 4;
    float o0[4], o1[4];
    o0[0] = (v0.x - mu) * rs * g[c0+0] + b[c0+0];
    o0[1] = (v0.y - mu) * rs * g[c0+1] + b[c0+1];
    o0[2] = (v0.z - mu) * rs * g[c0+2] + b[c0+2];
    o0[3] = (v0.w - mu) * rs * g[c0+3] + b[c0+3];
    o1[0] = (v1.x - mu) * rs * g[c1+0] + b[c1+0];
    o1[1] = (v1.y - mu) * rs * g[c1+1] + b[c1+1];
    o1[2] = (v1.z - mu) * rs * g[c1+2] + b[c1+2];
    o1[3] = (v1.w - mu) * rs * g[c1+3] + b[c1+3];
    __nv_bfloat162* hrow = (__nv_bfloat162*)(g_lnh + (size_t)row * C);
    __nv_bfloat162* lrow = (__nv_bfloat162*)(g_lnl + (size_t)row * C);
    __nv_bfloat16 h0[4], h1[4], l0[4], l1[4];
#pragma unroll
    for (int i = 0; i < 4; i++) {
        h0[i] = __float2bfloat16(o0[i]);
        l0[i] = __float2bfloat16(o0[i] - __bfloat162float(h0[i]));
        h1[i] = __float2bfloat16(o1[i]);
        l1[i] = __float2bfloat16(o1[i] - __bfloat162float(h1[i]));
    }
    hrow[lane*2+0]  = __nv_bfloat162{h0[0], h0[1]};
    hrow[lane*2+1]  = __nv_bfloat162{h0[2], h0[3]};
    hrow[64+lane*2] = __nv_bfloat162{h1[0], h1[1]};
    hrow[65+lane*2] = __nv_bfloat162{h1[2], h1[3]};
    lrow[lane*2+0]  = __nv_bfloat162{l0[0], l0[1]};
    lrow[lane*2+1]  = __nv_bfloat162{l0[2], l0[3]};
    lrow[64+lane*2] = __nv_bfloat162{l1[0], l1[1]};
    lrow[65+lane*2] = __nv_bfloat162{l1[2], l1[3]};
}

// ---------------- kernel 2: q projection + q-side positional bias ----------------
__global__ void q_kernel(const float* __restrict__ coords, const int* __restrict__ qidx,
                         const float* __restrict__ w_pos, const float* __restrict__ b_pos,
                         const float* __restrict__ w_q,   const float* __restrict__ b_q,
                         const float* __restrict__ pqx, const float* __restrict__ pqy,
                         const float* __restrict__ pqz) {
    extern __shared__ float sm2[];
    float* qin = sm2;
    float* qs  = sm2 + 32 * C;
    int t = threadIdx.x;
    int n0 = blockIdx.x * 32;
    for (int r = 0; r < 32; r++) {
        int n = n0 + r;
        float cx = coords[n*3+0], cy = coords[n*3+1], cz = coords[n*3+2];
        float p = cx * w_pos[t] + cy * w_pos[C + t] + cz * w_pos[2*C + t] + b_pos[t];
        p = fmaxf(p, 0.0f);
        size_t off = (size_t)qidx[n] * C + t;
        float lnv = __bfloat162float(g_lnh[off]) + __bfloat162float(g_lnl[off]);
        qin[r*C + t] = lnv + p;
    }
    __syncthreads();
    float acc[32];
#pragma unroll
    for (int r = 0; r < 32; r++) acc[r] = 0.0f;
    for (int c = 0; c < C; c++) {
        float w = w_q[c*C + t];
#pragma unroll
        for (int r = 0; r < 32; r++) acc[r] = fmaf(qin[r*C + c], w, acc[r]);
    }
    float bb = b_q[t];
    for (int r = 0; r < 32; r++) {
        float v = acc[r] + bb;
        qs[r*C + t] = v;
        g_q[(size_t)(n0 + r)*C + t] = v;
    }
    __syncthreads();
    for (int idx = t; idx < 32 * HH * 37; idx += 256) {
        int r   = idx / (HH * 37);
        int rem = idx - r * (HH * 37);
        int h   = rem / 37;
        int j   = rem - h * 37;
        const float* tab; int rr, stride;
        if (j < 15)      { tab = pqx + h * DHD * 15; rr = j;      stride = 15; }
        else if (j < 30) { tab = pqy + h * DHD * 15; rr = j - 15; stride = 15; }
        else             { tab = pqz + h * DHD * 7;  rr = j - 30; stride = 7;  }
        float s = 0.0f;
        const float* qrow = qs + r*C + h*DHD;
#pragma unroll
        for (int d = 0; d < DHD; d++) s = fmaf(qrow[d], __ldg(&tab[d*stride + rr]), s);
        g_qp[((size_t)(n0 + r)*HH + h)*37 + j] = s;
    }
}

// ---------------- shared MMA tile config ----------------
#define APITCH 40
#define MAT_BYTES (128 * APITCH * 2)        // 10240
#define STAGE_BYTES (4 * MAT_BYTES)         // 40960; 2 stages = 81920

// ---------------- kernel 3: K/V projection GEMM for ALL voxels ----------------
__global__ __launch_bounds__(256, 2)
void kvgemm_kernel(const float* __restrict__ bk, const float* __restrict__ bv) {
    extern __shared__ __align__(16) char gsm[];
    uint32_t sb = smem_u32(gsm);
    int t = threadIdx.x;
    int warp = t >> 5, lane = t & 31;
    int n0 = blockIdx.x * 128;
    int m0 = blockIdx.y * 128;

    auto load_chunk = [&](int kc, int buf) {
        uint32_t base = sb + buf * STAGE_BYTES;
#pragma unroll
        for (int i = 0; i < 2; i++) {
            int u = t + i * 256;
            int row = u >> 2, seg = u & 3;
            int gr = m0 + row; if (gr >= M_VOX) gr = 0;
            size_t go = (size_t)gr * 256 + kc * 32 + seg * 8;
            uint32_t so = base + (row * APITCH + seg * 8) * 2;
            cpasync16(so,             g_lnh + go);
            cpasync16(so + MAT_BYTES, g_lnl + go);
            size_t gb = (size_t)(n0 + row) * 256 + kc * 32 + seg * 8;
            uint32_t sob = base + 2 * MAT_BYTES + (row * APITCH + seg * 8) * 2;
            cpasync16(sob,             g_Bh + gb);
            cpasync16(sob + MAT_BYTES, g_Bl + gb);
        }
    };

    int wm = warp & 1, wn = warp >> 1;
    float acc[4][4][4];
#pragma unroll
    for (int a = 0; a < 4; a++)
#pragma unroll
        for (int bq = 0; bq < 4; bq++)
#pragma unroll
            for (int cq = 0; cq < 4; cq++) acc[a][bq][cq] = 0.0f;

    load_chunk(0, 0); CP_COMMIT();

    for (int kc = 0; kc < 8; kc++) {
        int buf = kc & 1;
        if (kc < 7) { load_chunk(kc + 1, buf ^ 1); CP_COMMIT(); CP_WAIT(1); }
        else        { CP_WAIT(0); }
        __syncthreads();

        uint32_t abase = sb + buf * STAGE_BYTES;
        uint32_t bbase = abase + 2 * MAT_BYTES;
        uint32_t bh[4][4], bl[4][4];
#pragma unroll
        for (int ni = 0; ni < 4; ni++) {
            int nrow = wn * 32 + ni * 8 + (lane & 7);
            int koff = (lane >> 3) * 8;
            uint32_t ad = bbase + (nrow * APITCH + koff) * 2;
            ldsm4(bh[ni], ad);
            ldsm4(bl[ni], ad + MAT_BYTES);
        }
#pragma unroll
        for (int s = 0; s < 2; s++) {
#pragma unroll
            for (int mi = 0; mi < 4; mi++) {
                int arow = wm * 64 + mi * 16 + (lane & 15);
                int koff = s * 16 + (lane >> 4) * 8;
                uint32_t ad = abase + (arow * APITCH + koff) * 2;
                uint32_t ah[4], al[4];
                ldsm4(ah, ad);
                ldsm4(al, ad + MAT_BYTES);
#pragma unroll
                for (int ni = 0; ni < 4; ni++) {
                    mma16816(acc[mi][ni], ah, &bh[ni][s*2]);
                    mma16816(acc[mi][ni], ah, &bl[ni][s*2]);
                    mma16816(acc[mi][ni], al, &bh[ni][s*2]);
                }
            }
        }
        __syncthreads();
    }

    float* dst = (n0 < 256) ? g_kall : g_vall;
    const float* bias = (n0 < 256) ? bk : bv;
    int cb = n0 & 255;
#pragma unroll
    for (int mi = 0; mi < 4; mi++) {
#pragma unroll
        for (int ni = 0; ni < 4; ni++) {
            int col = cb + wn * 32 + ni * 8 + (lane & 3) * 2;
            float b0 = bias[col], b1 = bias[col + 1];
            int r0 = m0 + wm * 64 + mi * 16 + (lane >> 2);
            if (r0 < M_VOX)
                *(float2*)(dst + (size_t)r0 * 256 + col) =
                    make_float2(acc[mi][ni][0] + b0, acc[mi][ni][1] + b1);
            int r1 = r0 + 8;
            if (r1 < M_VOX)
                *(float2*)(dst + (size_t)r1 * 256 + col) =
                    make_float2(acc[mi][ni][2] + b0, acc[mi][ni][3] + b1);
        }
    }
}

// ---------------- generic bf16-split MMA GEMM (M=8192 rows), fused epilogues ------
// EPI 0: g_act = acc + bias + voxel[qidx[row]]         (proj)
// EPI 1: relu(acc + bias) -> bf16 split outh/outl      (ff1), pitch opitch
// EPI 2: outf = acc + bias + add_src[row]              (ff2 -> d_out)
template<int EPI>
__global__ __launch_bounds__(256, 2)
void mmagemm_kernel(const __nv_bfloat16* __restrict__ Ah, const __nv_bfloat16* __restrict__ Al,
                    int K,
                    const __nv_bfloat16* __restrict__ Bh, const __nv_bfloat16* __restrict__ Bl,
                    const float* __restrict__ bias,
                    const float* __restrict__ add_src, const int* __restrict__ qidx,
                    float* __restrict__ outf,
                    __nv_bfloat16* __restrict__ outh, __nv_bfloat16* __restrict__ outl,
                    int opitch) {
    extern __shared__ __align__(16) char gsm[];
    uint32_t sb = smem_u32(gsm);
    int t = threadIdx.x;
    int warp = t >> 5, lane = t & 31;
    int n0 = blockIdx.x * 128;
    int m0 = blockIdx.y * 128;

    auto load_chunk = [&](int kc, int buf) {
        uint32_t base = sb + buf * STAGE_BYTES;
#pragma unroll
        for (int i = 0; i < 2; i++) {
            int u = t + i * 256;
            int row = u >> 2, seg = u & 3;
            size_t go = (size_t)(m0 + row) * K + kc * 32 + seg * 8;
            uint32_t so = base + (row * APITCH + seg * 8) * 2;
            cpasync16(so,             Ah + go);
            cpasync16(so + MAT_BYTES, Al + go);
            size_t gb = (size_t)(n0 + row) * K + kc * 32 + seg * 8;
            uint32_t sob = base + 2 * MAT_BYTES + (row * APITCH + seg * 8) * 2;
            cpasync16(sob,             Bh + gb);
            cpasync16(sob + MAT_BYTES, Bl + gb);
        }
    };

    int wm = warp & 1, wn = warp >> 1;
    float acc[4][4][4];
#pragma unroll
    for (int a = 0; a < 4; a++)
#pragma unroll
        for (int bq = 0; bq < 4; bq++)
#pragma unroll
            for (int cq = 0; cq < 4; cq++) acc[a][bq][cq] = 0.0f;

    int nchunks = K >> 5;
    load_chunk(0, 0); CP_COMMIT();

    for (int kc = 0; kc < nchunks; kc++) {
        int buf = kc & 1;
        if (kc < nchunks - 1) { load_chunk(kc + 1, buf ^ 1); CP_COMMIT(); CP_WAIT(1); }
        else                  { CP_WAIT(0); }
        __syncthreads();

        uint32_t abase = sb + buf * STAGE_BYTES;
        uint32_t bbase = abase + 2 * MAT_BYTES;
        uint32_t bh[4][4], bl[4][4];
#pragma unroll
        for (int ni = 0; ni < 4; ni++) {
            int nrow = wn * 32 + ni * 8 + (lane & 7);
            int koff = (lane >> 3) * 8;
            uint32_t ad = bbase + (nrow * APITCH + koff) * 2;
            ldsm4(bh[ni], ad);
            ldsm4(bl[ni], ad + MAT_BYTES);
        }
#pragma unroll
        for (int s = 0; s < 2; s++) {
#pragma unroll
            for (int mi = 0; mi < 4; mi++) {
                int arow = wm * 64 + mi * 16 + (lane & 15);
                int koff = s * 16 + (lane >> 4) * 8;
                uint32_t ad = abase + (arow * APITCH + koff) * 2;
                uint32_t ah[4], al[4];
                ldsm4(ah, ad);
                ldsm4(al, ad + MAT_BYTES);
#pragma unroll
                for (int ni = 0; ni < 4; ni++) {
                    mma16816(acc[mi][ni], ah, &bh[ni][s*2]);
                    mma16816(acc[mi][ni], ah, &bl[ni][s*2]);
                    mma16816(acc[mi][ni], al, &bh[ni][s*2]);
                }
            }
        }
        __syncthreads();
    }

#pragma unroll
    for (int mi = 0; mi < 4; mi++) {
#pragma unroll
        for (int ni = 0; ni < 4; ni++) {
            int col = n0 + wn * 32 + ni * 8 + (lane & 3) * 2;
            float b0 = bias[col], b1 = bias[col + 1];
#pragma unroll
            for (int half = 0; half < 2; half++) {
                int r = m0 + wm * 64 + mi * 16 + (lane >> 2) + half * 8;
                float v0 = acc[mi][ni][half*2+0] + b0;
                float v1 = acc[mi][ni][half*2+1] + b1;
                if (EPI == 0) {
                    size_t voff = (size_t)qidx[r] * 256 + col;
                    v0 += add_src[voff];
                    v1 += add_src[voff + 1];
                    *(float2*)(outf + (size_t)r * 256 + col) = make_float2(v0, v1);
                } else if (EPI == 1) {
                    v0 = fmaxf(v0, 0.0f);
                    v1 = fmaxf(v1, 0.0f);
                    __nv_bfloat16 h0 = __float2bfloat16(v0);
                    __nv_bfloat16 h1 = __float2bfloat16(v1);
                    __nv_bfloat16 l0 = __float2bfloat16(v0 - __bfloat162float(h0));
                    __nv_bfloat16 l1 = __float2bfloat16(v1 - __bfloat162float(h1));
                    *(__nv_bfloat162*)(outh + (size_t)r * opitch + col) = __nv_bfloat162{h0, h1};
                    *(__nv_bfloat162*)(outl + (size_t)r * opitch + col) = __nv_bfloat162{l0, l1};
                } else {
                    size_t aoff = (size_t)r * 256 + col;
                    v0 += add_src[aoff];
                    v1 += add_src[aoff + 1];
                    *(float2*)(outf + aoff) = make_float2(v0, v1);
                }
            }
        }
    }
}

// ---------------- kernel 4: attention per query ----------------
#define KPITCH 260
__global__ __launch_bounds__(256)
void attn_kernel(const int* __restrict__ gidx, const int* __restrict__ gmask,
                 const int* __restrict__ rel_x, const int* __restrict__ rel_y,
                 const int* __restrict__ rel_z,
                 const float* __restrict__ bk, const float* __restrict__ bv,
                 const float* __restrict__ pkx, const float* __restrict__ pky,
                 const float* __restrict__ pkz) {
    extern __shared__ float sm4[];
    float* k_s = sm4;
    float* v_s = sm4 + 32 * KPITCH;
    __shared__ float q_s[256];
    __shared__ float qp_s[296];
    __shared__ float attn_s[HH][KNN];
    __shared__ int idx_s[32], msk_s[32], rx_s[32], ry_s[32], rz_s[32];
    int n = blockIdx.x, t = threadIdx.x;
    if (t < 32) {
        idx_s[t] = gidx[n*KNN + t];
        msk_s[t] = gmask[n*KNN + t];
        rx_s[t]  = rel_x[n*KNN + t];
        ry_s[t]  = rel_y[n*KNN + t];
        rz_s[t]  = rel_z[n*KNN + t];
    } else if (t < 96) {
        int i = t - 32;
        ((float4*)q_s)[i] = ((const float4*)(g_q + (size_t)n * C))[i];
    } else if (t < 170) {
        int i = t - 96;
        ((float4*)qp_s)[i] = ((const float4*)(g_qp + (size_t)n * 296))[i];
    }
    __syncthreads();
#pragma unroll
    for (int i = 0; i < 8; i++) {
        int u = t + i * 256;
        int row = u >> 6, seg = u & 63;
        bool m = (msk_s[row] != 0);
        const float4* ks = m ? (const float4*)bk
                             : (const float4*)(g_kall + (size_t)idx_s[row] * C);
        const float4* vs = m ? (const float4*)bv
                             : (const float4*)(g_vall + (size_t)idx_s[row] * C);
        ((float4*)(k_s + row * KPITCH))[seg] = __ldg(&ks[seg]);
        ((float4*)(v_s + row * KPITCH))[seg] = __ldg(&vs[seg]);
    }
    __syncthreads();

    int h = t >> 5, lane = t & 31;
    {
        int rx = rx_s[lane], ry = ry_s[lane], rz = rz_s[lane];
        bool msk = (msk_s[lane] != 0);
        const float* krow = k_s + lane * KPITCH + h * DHD;
        const float* qh   = q_s + h * DHD;
        const float* pbx = pkx + h * DHD * 15 + rx;
        const float* pby = pky + h * DHD * 15 + ry;
        const float* pbz = pkz + h * DHD * 7  + rz;
        float qk = 0.0f, bias = 0.0f;
#pragma unroll
        for (int d = 0; d < DHD; d++) {
            float kv = krow[d];
            qk = fmaf(qh[d], kv, qk);
            float pw = __ldg(pbx + d * 15) + __ldg(pby + d * 15) + __ldg(pbz + d * 7);
            bias = fmaf(kv, pw, bias);
        }
        const float* qpn = qp_s + h * 37;
        float logit = qk * 0.17677669529663687f + qpn[rx] + qpn[15 + ry] + qpn[30 + rz] + bias;
        if (msk) logit = -1e9f;
        float m = logit;
#pragma unroll
        for (int o = 16; o > 0; o >>= 1) m = fmaxf(m, __shfl_xor_sync(0xffffffffu, m, o));
        float p = expf(logit - m);
        float s = p;
#pragma unroll
        for (int o = 16; o > 0; o >>= 1) s += __shfl_xor_sync(0xffffffffu, s, o);
        attn_s[h][lane] = p / s;
    }
    __syncwarp();
    {
        float o = 0.0f;
        const float* vcol = v_s + h * DHD + lane;
        const float* aw = attn_s[h];
#pragma unroll
        for (int kk = 0; kk < KNN; kk++) o = fmaf(aw[kk], vcol[kk * KPITCH], o);
        size_t off = (size_t)n * C + h * DHD + lane;
        __nv_bfloat16 hh = __float2bfloat16(o);
        g_aoh[off] = hh;
        g_aol[off] = __float2bfloat16(o - __bfloat162float(hh));
    }
}

// ---------------- kernel: LN2 over ACT -> bf16 split ----------------
__global__ void ln2_kernel(const float* __restrict__ g, const float* __restrict__ b) {
    int row = blockIdx.x * 8 + (threadIdx.x >> 5);
    int lane = threadIdx.x & 31;
    const float4* xr = (const float4*)(g_act + (size_t)row * C);
    float4 v0 = xr[lane];
    float4 v1 = xr[lane + 32];
    float s = v0.x + v0.y + v0.z + v0.w + v1.x + v1.y + v1.z + v1.w;
    float q = v0.x*v0.x + v0.y*v0.y + v0.z*v0.z + v0.w*v0.w
            + v1.x*v1.x + v1.y*v1.y + v1.z*v1.z + v1.w*v1.w;
#pragma unroll
    for (int o = 16; o > 0; o >>= 1) {
        s += __shfl_xor_sync(0xffffffffu, s, o);
        q += __shfl_xor_sync(0xffffffffu, q, o);
    }
    float mu = s * (1.0f / C);
    float rs = rsqrtf(q * (1.0f / C) - mu * mu + 1e-5f);
    int c0 = lane * 4, c1 = 128 + lane * 4;
    float o0[4], o1[4];
    o0[0] = (v0.x - mu) * rs * g[c0+0] + b[c0+0];
    o0[1] = (v0.y - mu) * rs * g[c0+1] + b[c0+1];
    o0[2] = (v0.z - mu) * rs * g[c0+2] + b[c0+2];
    o0[3] = (v0.w - mu) * rs * g[c0+3] + b[c0+3];
    o1[0] = (v1.x - mu) * rs * g[c1+0] + b[c1+0];
    o1[1] = (v1.y - mu) * rs * g[c1+1] + b[c1+1];
    o1[2] = (v1.z - mu) * rs * g[c1+2] + b[c1+2];
    o1[3] = (v1.w - mu) * rs * g[c1+3] + b[c1+3];
    __nv_bfloat162* hrow = (__nv_bfloat162*)(g_xh + (size_t)row * C);
    __nv_bfloat162* lrow = (__nv_bfloat162*)(g_xl + (size_t)row * C);
    __nv_bfloat16 h0[4], h1[4], l0[4], l1[4];
#pragma unroll
    for (int i = 0; i < 4; i++) {
        h0[i] = __float2bfloat16(o0[i]);
        l0[i] = __float2bfloat16(o0[i] - __bfloat162float(h0[i]));
        h1[i] = __float2bfloat16(o1[i]);
        l1[i] = __float2bfloat16(o1[i] - __bfloat162float(h1[i]));
    }
    hrow[lane*2+0]  = __nv_bfloat162{h0[0], h0[1]};
    hrow[lane*2+1]  = __nv_bfloat162{h0[2], h0[3]};
    hrow[64+lane*2] = __nv_bfloat162{h1[0], h1[1]};
    hrow[65+lane*2] = __nv_bfloat162{h1[2], h1[3]};
    lrow[lane*2+0]  = __nv_bfloat162{l0[0], l0[1]};
    lrow[lane*2+1]  = __nv_bfloat162{l0[2], l0[3]};
    lrow[64+lane*2] = __nv_bfloat162{l1[0], l1[1]};
    lrow[65+lane*2] = __nv_bfloat162{l1[2], l1[3]};
}

// ---------------- launch ----------------
extern "C" void kernel_launch(void* const* d_in, const int* in_sizes, int n_in,
                              void* d_out, int out_size) {
    const float* voxel  = (const float*)d_in[0];
    const float* coords = (const float*)d_in[1];
    const int*   qidx   = (const int*)d_in[2];
    const int*   gidx   = (const int*)d_in[3];
    const int*   gmask  = (const int*)d_in[4];
    const int*   rel_x  = (const int*)d_in[5];
    const int*   rel_y  = (const int*)d_in[6];
    const int*   rel_z  = (const int*)d_in[7];
    const float* w_pos  = (const float*)d_in[8];
    const float* b_pos  = (const float*)d_in[9];
    const float* w_q    = (const float*)d_in[10];
    const float* b_q    = (const float*)d_in[11];
    const float* w_k    = (const float*)d_in[12];
    const float* b_k    = (const float*)d_in[13];
    const float* w_v    = (const float*)d_in[14];
    const float* b_v    = (const float*)d_in[15];
    const float* w_proj = (const float*)d_in[16];
    const float* b_proj = (const float*)d_in[17];
    const float* ln1g   = (const float*)d_in[18];
    const float* ln1b   = (const float*)d_in[19];
    const float* ln2g   = (const float*)d_in[20];
    const float* ln2b   = (const float*)d_in[21];
    const float* w_ff1  = (const float*)d_in[22];
    const float* b_ff1  = (const float*)d_in[23];
    const float* w_ff2  = (const float*)d_in[24];
    const float* b_ff2  = (const float*)d_in[25];
    const float* pqx    = (const float*)d_in[26];
    const float* pqy    = (const float*)d_in[27];
    const float* pqz    = (const float*)d_in[28];
    const float* pkx    = (const float*)d_in[29];
    const float* pky    = (const float*)d_in[30];
    const float* pkz    = (const float*)d_in[31];
    float* out = (float*)d_out;

    cudaFuncSetAttribute(q_kernel,       cudaFuncAttributeMaxDynamicSharedMemorySize, 65536);
    cudaFuncSetAttribute(kvgemm_kernel,  cudaFuncAttributeMaxDynamicSharedMemorySize, 2 * STAGE_BYTES);
    cudaFuncSetAttribute(mmagemm_kernel<0>, cudaFuncAttributeMaxDynamicSharedMemorySize, 2 * STAGE_BYTES);
    cudaFuncSetAttribute(mmagemm_kernel<1>, cudaFuncAttributeMaxDynamicSharedMemorySize, 2 * STAGE_BYTES);
    cudaFuncSetAttribute(mmagemm_kernel<2>, cudaFuncAttributeMaxDynamicSharedMemorySize, 2 * STAGE_BYTES);
    cudaFuncSetAttribute(attn_kernel,    cudaFuncAttributeMaxDynamicSharedMemorySize, 2 * 32 * KPITCH * 4);

    __nv_bfloat16 *Bh, *Bl, *Wph, *Wpl, *W1h, *W1l, *W2h, *W2l;
    __nv_bfloat16 *lnh, *lnl, *aoh, *aol, *xh, *xl, *fh, *fl;
    float *act;
    cudaGetSymbolAddress((void**)&Bh, g_Bh);   cudaGetSymbolAddress((void**)&Bl, g_Bl);
    cudaGetSymbolAddress((void**)&Wph, g_Wph); cudaGetSymbolAddress((void**)&Wpl, g_Wpl);
    cudaGetSymbolAddress((void**)&W1h, g_W1h); cudaGetSymbolAddress((void**)&W1l, g_W1l);
    cudaGetSymbolAddress((void**)&W2h, g_W2h); cudaGetSymbolAddress((void**)&W2l, g_W2l);
    cudaGetSymbolAddress((void**)&lnh, g_lnh); cudaGetSymbolAddress((void**)&lnl, g_lnl);
    cudaGetSymbolAddress((void**)&aoh, g_aoh); cudaGetSymbolAddress((void**)&aol, g_aol);
    cudaGetSymbolAddress((void**)&xh, g_xh);   cudaGetSymbolAddress((void**)&xl, g_xl);
    cudaGetSymbolAddress((void**)&fh, g_fh);   cudaGetSymbolAddress((void**)&fl, g_fl);
    cudaGetSymbolAddress((void**)&act, g_act);

    bprep_kernel<<<512, 256>>>(w_k, w_v);
    wprep_kernel<<<256, 256>>>(w_proj, 256, 256, Wph, Wpl);
    wprep_kernel<<<512, 256>>>(w_ff1, 512, 256, W1h, W1l);
    wprep_kernel<<<512, 256>>>(w_ff2, 256, 512, W2h, W2l);
    ln_kernel<<<(M_VOX + 7) / 8, 256>>>(voxel, ln1g, ln1b);
    q_kernel<<<NQ / 32, 256, 65536>>>(coords, qidx, w_pos, b_pos, w_q, b_q, pqx, pqy, pqz);
    kvgemm_kernel<<<dim3(4, (M_VOX + 127) / 128), 256, 2 * STAGE_BYTES>>>(b_k, b_v);
    attn_kernel<<<NQ, 256, 2 * 32 * KPITCH * 4>>>(gidx, gmask, rel_x, rel_y, rel_z,
                                                  b_k, b_v, pkx, pky, pkz);
    // proj: ACT = ao @ w_proj + b_proj + voxel[qidx]
    mmagemm_kernel<0><<<dim3(2, NQ / 128), 256, 2 * STAGE_BYTES>>>(
        aoh, aol, 256, Wph, Wpl, b_proj, voxel, qidx, act, nullptr, nullptr, 0);
    ln2_kernel<<<NQ / 8, 256>>>(ln2g, ln2b);
    // ff1: F = relu(X @ w_ff1 + b_ff1)
    mmagemm_kernel<1><<<dim3(4, NQ / 128), 256, 2 * STAGE_BYTES>>>(
        xh, xl, 256, W1h, W1l, b_ff1, nullptr, nullptr, nullptr, fh, fl, 512);
    // ff2: out = ACT + F @ w_ff2 + b_ff2
    mmagemm_kernel<2><<<dim3(2, NQ / 128), 256, 2 * STAGE_BYTES>>>(
        fh, fl, 512, W2h, W2l, b_ff2, act, nullptr, out, nullptr, nullptr, 0);
}

// round 6
// speedup vs baseline: 4.0649x; 1.3550x over previous
#include <cuda_runtime.h>
#include <cuda_fp16.h>
#include <cstdint>

#define M_VOX 100000
#define NQ    8192
#define KNN   32
#define C     256
#define HH    8
#define DHD   32
#define FF    512

// ---------------- scratch (device globals; no allocations allowed) ----------------
__device__ __half g_lnh[(size_t)M_VOX * C];      // fp16 LN(voxel_features)
__device__ float g_kall[(size_t)M_VOX * C];      // k projection of ALL voxels
__device__ float g_vall[(size_t)M_VOX * C];      // v projection of ALL voxels
__device__ __half g_qin[(size_t)NQ * C];         // q-input fp16
__device__ float g_q [(size_t)NQ * C];           // q projections fp32
__device__ float g_qp[(size_t)NQ * HH * 37];     // q-side pos bias
__device__ __half g_ao[(size_t)NQ * C];          // attention out fp16
__device__ float g_act[(size_t)NQ * C];          // ACT = voxel[qidx] + proj(ao)
__device__ __half g_x[(size_t)NQ * C];           // LN2(ACT) fp16
__device__ __half g_f[(size_t)NQ * FF];          // relu(ff1) fp16
// weights transposed + fp16-split, layout [n][k]
__device__ __half g_Bh[512 * 256];               // [wk|wv]
__device__ __half g_Bl[512 * 256];
__device__ __half g_Wqh[256 * 256];
__device__ __half g_Wql[256 * 256];
__device__ __half g_Wph[256 * 256];
__device__ __half g_Wpl[256 * 256];
__device__ __half g_W1h[512 * 256];
__device__ __half g_W1l[512 * 256];
__device__ __half g_W2h[256 * 512];
__device__ __half g_W2l[256 * 512];

// ---------------- helpers ----------------
__device__ __forceinline__ uint32_t smem_u32(const void* p) {
    uint32_t a;
    asm("{ .reg .u64 t; cvta.to.shared.u64 t, %1; cvt.u32.u64 %0, t; }" : "=r"(a) : "l"(p));
    return a;
}
__device__ __forceinline__ void cpasync16(uint32_t dst, const void* src) {
    asm volatile("cp.async.cg.shared.global [%0], [%1], 16;" :: "r"(dst), "l"(src));
}
#define CP_COMMIT()  asm volatile("cp.async.commit_group;" ::: "memory")
#define CP_WAIT(n)   asm volatile("cp.async.wait_group %0;" :: "n"(n) : "memory")

__device__ __forceinline__ void ldsm4(uint32_t* r, uint32_t addr) {
    asm volatile("ldmatrix.sync.aligned.m8n8.x4.shared.b16 {%0,%1,%2,%3}, [%4];"
        : "=r"(r[0]), "=r"(r[1]), "=r"(r[2]), "=r"(r[3]) : "r"(addr));
}
__device__ __forceinline__ void mma16816(float* c, const uint32_t* a, const uint32_t* b) {
    asm volatile(
        "mma.sync.aligned.m16n8k16.row.col.f32.f16.f16.f32 "
        "{%0,%1,%2,%3}, {%4,%5,%6,%7}, {%8,%9}, {%0,%1,%2,%3};"
        : "+f"(c[0]), "+f"(c[1]), "+f"(c[2]), "+f"(c[3])
        : "r"(a[0]), "r"(a[1]), "r"(a[2]), "r"(a[3]), "r"(b[0]), "r"(b[1]));
}

// ---------------- weight prep: transpose + fp16 split ----------------
__global__ void bprep_kernel(const float* __restrict__ wk, const float* __restrict__ wv) {
    int idx = blockIdx.x * 256 + threadIdx.x;   // 512*256
    int n = idx >> 8, k = idx & 255;
    float val = (n < 256) ? wk[k * 256 + n] : wv[k * 256 + (n - 256)];
    __half h = __float2half(val);
    g_Bh[idx] = h;
    g_Bl[idx] = __float2half(val - __half2float(h));
}
// src [K][N] row-major -> dst [N][K]
__global__ void wprep_kernel(const float* __restrict__ src, int N, int K,
                             __half* __restrict__ dh, __half* __restrict__ dl) {
    int idx = blockIdx.x * 256 + threadIdx.x;
    int n = idx / K, k = idx - n * K;
    float val = src[k * N + n];
    __half h = __float2half(val);
    dh[idx] = h;
    dl[idx] = __float2half(val - __half2float(h));
}

// ---------------- kernel 1: LayerNorm over all M voxels -> fp16 ----------------
__global__ void ln_kernel(const float* __restrict__ x,
                          const float* __restrict__ g,
                          const float* __restrict__ b) {
    int row = blockIdx.x * 8 + (threadIdx.x >> 5);
    if (row >= M_VOX) return;
    int lane = threadIdx.x & 31;
    const float4* xr = (const float4*)(x + (size_t)row * C);
    float4 v0 = xr[lane];
    float4 v1 = xr[lane + 32];
    float s = v0.x + v0.y + v0.z + v0.w + v1.x + v1.y + v1.z + v1.w;
    float q = v0.x*v0.x + v0.y*v0.y + v0.z*v0.z + v0.w*v0.w
            + v1.x*v1.x + v1.y*v1.y + v1.z*v1.z + v1.w*v1.w;
#pragma unroll
    for (int o = 16; o > 0; o >>= 1) {
        s += __shfl_xor_sync(0xffffffffu, s, o);
        q += __shfl_xor_sync(0xffffffffu, q, o);
    }
    float mu = s * (1.0f / C);
    float rs = rsqrtf(q * (1.0f / C) - mu * mu + 1e-5f);
    int c0 = lane * 4, c1 = 128 + lane * 4;
    __half2* hrow = (__half2*)(g_lnh + (size_t)row * C);
    hrow[lane*2+0]  = __floats2half2_rn((v0.x - mu) * rs * g[c0+0] + b[c0+0],
                                        (v0.y - mu) * rs * g[c0+1] + b[c0+1]);
    hrow[lane*2+1]  = __floats2half2_rn((v0.z - mu) * rs * g[c0+2] + b[c0+2],
                                        (v0.w - mu) * rs * g[c0+3] + b[c0+3]);
    hrow[64+lane*2] = __floats2half2_rn((v1.x - mu) * rs * g[c1+0] + b[c1+0],
                                        (v1.y - mu) * rs * g[c1+1] + b[c1+1]);
    hrow[65+lane*2] = __floats2half2_rn((v1.z - mu) * rs * g[c1+2] + b[c1+2],
                                        (v1.w - mu) * rs * g[c1+3] + b[c1+3]);
}

// ---------------- kernel: qin = ln[qidx] + relu(coords @ w_pos + b_pos) ---------
__global__ void qin_kernel(const float* __restrict__ coords, const int* __restrict__ qidx,
                           const float* __restrict__ w_pos, const float* __restrict__ b_pos) {
    int n = blockIdx.x, t = threadIdx.x;
    float cx = coords[n*3+0], cy = coords[n*3+1], cz = coords[n*3+2];
    float p = cx * w_pos[t] + cy * w_pos[C + t] + cz * w_pos[2*C + t] + b_pos[t];
    p = fmaxf(p, 0.0f);
    float lnv = __half2float(g_lnh[(size_t)qidx[n] * C + t]);
    g_qin[(size_t)n * C + t] = __float2half(lnv + p);
}

// ---------------- kernel: q-side positional bias (reads g_q) ----------------
__global__ void qp_kernel(const float* __restrict__ pqx, const float* __restrict__ pqy,
                          const float* __restrict__ pqz) {
    __shared__ float qs[32 * C];
    int t = threadIdx.x;
    int n0 = blockIdx.x * 32;
    for (int i = t; i < 32 * C; i += 256) qs[i] = g_q[(size_t)n0 * C + i];
    __syncthreads();
    for (int idx = t; idx < 32 * HH * 37; idx += 256) {
        int r   = idx / (HH * 37);
        int rem = idx - r * (HH * 37);
        int h   = rem / 37;
        int j   = rem - h * 37;
        const float* tab; int rr, stride;
        if (j < 15)      { tab = pqx + h * DHD * 15; rr = j;      stride = 15; }
        else if (j < 30) { tab = pqy + h * DHD * 15; rr = j - 15; stride = 15; }
        else             { tab = pqz + h * DHD * 7;  rr = j - 30; stride = 7;  }
        float s = 0.0f;
        const float* qrow = qs + r*C + h*DHD;
#pragma unroll
        for (int d = 0; d < DHD; d++) s = fmaf(qrow[d], __ldg(&tab[d*stride + rr]), s);
        g_qp[((size_t)(n0 + r)*HH + h)*37 + j] = s;
    }
}

// ---------------- shared MMA tile config (2-term fp16: A, Bh, Bl) ----------------
#define APITCH 40
#define MAT_BYTES (128 * APITCH * 2)        // 10240
#define STAGE_BYTES (3 * MAT_BYTES)         // 30720; 2 stages = 61440

// ---------------- kernel 3: K/V projection GEMM for ALL voxels ----------------
__global__ __launch_bounds__(256, 2)
void kvgemm_kernel(const float* __restrict__ bk, const float* __restrict__ bv) {
    extern __shared__ __align__(16) char gsm[];
    uint32_t sb = smem_u32(gsm);
    int t = threadIdx.x;
    int warp = t >> 5, lane = t & 31;
    int n0 = blockIdx.x * 128;
    int m0 = blockIdx.y * 128;

    auto load_chunk = [&](int kc, int buf) {
        uint32_t base = sb + buf * STAGE_BYTES;
#pragma unroll
        for (int i = 0; i < 2; i++) {
            int u = t + i * 256;
            int row = u >> 2, seg = u & 3;
            int gr = m0 + row; if (gr >= M_VOX) gr = 0;
            size_t go = (size_t)gr * 256 + kc * 32 + seg * 8;
            uint32_t so = base + (row * APITCH + seg * 8) * 2;
            cpasync16(so, g_lnh + go);
            size_t gb = (size_t)(n0 + row) * 256 + kc * 32 + seg * 8;
            uint32_t sob = base + MAT_BYTES + (row * APITCH + seg * 8) * 2;
            cpasync16(sob,             g_Bh + gb);
            cpasync16(sob + MAT_BYTES, g_Bl + gb);
        }
    };

    int wm = warp & 1, wn = warp >> 1;
    float acc[4][4][4];
#pragma unroll
    for (int a = 0; a < 4; a++)
#pragma unroll
        for (int bq = 0; bq < 4; bq++)
#pragma unroll
            for (int cq = 0; cq < 4; cq++) acc[a][bq][cq] = 0.0f;

    load_chunk(0, 0); CP_COMMIT();

    for (int kc = 0; kc < 8; kc++) {
        int buf = kc & 1;
        if (kc < 7) { load_chunk(kc + 1, buf ^ 1); CP_COMMIT(); CP_WAIT(1); }
        else        { CP_WAIT(0); }
        __syncthreads();

        uint32_t abase = sb + buf * STAGE_BYTES;
        uint32_t bbase = abase + MAT_BYTES;
        uint32_t bh[4][4], bl[4][4];
#pragma unroll
        for (int ni = 0; ni < 4; ni++) {
            int nrow = wn * 32 + ni * 8 + (lane & 7);
            int koff = (lane >> 3) * 8;
            uint32_t ad = bbase + (nrow * APITCH + koff) * 2;
            ldsm4(bh[ni], ad);
            ldsm4(bl[ni], ad + MAT_BYTES);
        }
#pragma unroll
        for (int s = 0; s < 2; s++) {
#pragma unroll
            for (int mi = 0; mi < 4; mi++) {
                int arow = wm * 64 + mi * 16 + (lane & 15);
                int koff = s * 16 + (lane >> 4) * 8;
                uint32_t ah[4];
                ldsm4(ah, abase + (arow * APITCH + koff) * 2);
#pragma unroll
                for (int ni = 0; ni < 4; ni++) {
                    mma16816(acc[mi][ni], ah, &bh[ni][s*2]);
                    mma16816(acc[mi][ni], ah, &bl[ni][s*2]);
                }
            }
        }
        __syncthreads();
    }

    float* dst = (n0 < 256) ? g_kall : g_vall;
    const float* bias = (n0 < 256) ? bk : bv;
    int cb = n0 & 255;
#pragma unroll
    for (int mi = 0; mi < 4; mi++) {
#pragma unroll
        for (int ni = 0; ni < 4; ni++) {
            int col = cb + wn * 32 + ni * 8 + (lane & 3) * 2;
            float b0 = bias[col], b1 = bias[col + 1];
            int r0 = m0 + wm * 64 + mi * 16 + (lane >> 2);
            if (r0 < M_VOX)
                *(float2*)(dst + (size_t)r0 * 256 + col) =
                    make_float2(acc[mi][ni][0] + b0, acc[mi][ni][1] + b1);
            int r1 = r0 + 8;
            if (r1 < M_VOX)
                *(float2*)(dst + (size_t)r1 * 256 + col) =
                    make_float2(acc[mi][ni][2] + b0, acc[mi][ni][3] + b1);
        }
    }
}

// ---------------- generic 2-term fp16 MMA GEMM (8192 rows), fused epilogues ------
// EPI 0: outf = acc + bias + add_src[qidx[row]]   (proj -> g_act)
// EPI 1: relu(acc + bias) -> fp16 outh            (ff1), pitch opitch
// EPI 2: outf = acc + bias + add_src[row]         (ff2 -> d_out)
// EPI 3: outf = acc + bias                        (q -> g_q)
template<int EPI>
__global__ __launch_bounds__(256, 2)
void mmagemm_kernel(const __half* __restrict__ Ah, int K,
                    const __half* __restrict__ Bh, const __half* __restrict__ Bl,
                    const float* __restrict__ bias,
                    const float* __restrict__ add_src, const int* __restrict__ qidx,
                    float* __restrict__ outf, __half* __restrict__ outh, int opitch) {
    extern __shared__ __align__(16) char gsm[];
    uint32_t sb = smem_u32(gsm);
    int t = threadIdx.x;
    int warp = t >> 5, lane = t & 31;
    int n0 = blockIdx.x * 128;
    int m0 = blockIdx.y * 128;

    auto load_chunk = [&](int kc, int buf) {
        uint32_t base = sb + buf * STAGE_BYTES;
#pragma unroll
        for (int i = 0; i < 2; i++) {
            int u = t + i * 256;
            int row = u >> 2, seg = u & 3;
            size_t go = (size_t)(m0 + row) * K + kc * 32 + seg * 8;
            uint32_t so = base + (row * APITCH + seg * 8) * 2;
            cpasync16(so, Ah + go);
            size_t gb = (size_t)(n0 + row) * K + kc * 32 + seg * 8;
            uint32_t sob = base + MAT_BYTES + (row * APITCH + seg * 8) * 2;
            cpasync16(sob,             Bh + gb);
            cpasync16(sob + MAT_BYTES, Bl + gb);
        }
    };

    int wm = warp & 1, wn = warp >> 1;
    float acc[4][4][4];
#pragma unroll
    for (int a = 0; a < 4; a++)
#pragma unroll
        for (int bq = 0; bq < 4; bq++)
#pragma unroll
            for (int cq = 0; cq < 4; cq++) acc[a][bq][cq] = 0.0f;

    int nchunks = K >> 5;
    load_chunk(0, 0); CP_COMMIT();

    for (int kc = 0; kc < nchunks; kc++) {
        int buf = kc & 1;
        if (kc < nchunks - 1) { load_chunk(kc + 1, buf ^ 1); CP_COMMIT(); CP_WAIT(1); }
        else                  { CP_WAIT(0); }
        __syncthreads();

        uint32_t abase = sb + buf * STAGE_BYTES;
        uint32_t bbase = abase + MAT_BYTES;
        uint32_t bh[4][4], bl[4][4];
#pragma unroll
        for (int ni = 0; ni < 4; ni++) {
            int nrow = wn * 32 + ni * 8 + (lane & 7);
            int koff = (lane >> 3) * 8;
            uint32_t ad = bbase + (nrow * APITCH + koff) * 2;
            ldsm4(bh[ni], ad);
            ldsm4(bl[ni], ad + MAT_BYTES);
        }
#pragma unroll
        for (int s = 0; s < 2; s++) {
#pragma unroll
            for (int mi = 0; mi < 4; mi++) {
                int arow = wm * 64 + mi * 16 + (lane & 15);
                int koff = s * 16 + (lane >> 4) * 8;
                uint32_t ah[4];
                ldsm4(ah, abase + (arow * APITCH + koff) * 2);
#pragma unroll
                for (int ni = 0; ni < 4; ni++) {
                    mma16816(acc[mi][ni], ah, &bh[ni][s*2]);
                    mma16816(acc[mi][ni], ah, &bl[ni][s*2]);
                }
            }
        }
        __syncthreads();
    }

#pragma unroll
    for (int mi = 0; mi < 4; mi++) {
#pragma unroll
        for (int ni = 0; ni < 4; ni++) {
            int col = n0 + wn * 32 + ni * 8 + (lane & 3) * 2;
            float b0 = bias[col], b1 = bias[col + 1];
#pragma unroll
            for (int half = 0; half < 2; half++) {
                int r = m0 + wm * 64 + mi * 16 + (lane >> 2) + half * 8;
                float v0 = acc[mi][ni][half*2+0] + b0;
                float v1 = acc[mi][ni][half*2+1] + b1;
                if (EPI == 0) {
                    size_t voff = (size_t)qidx[r] * 256 + col;
                    v0 += add_src[voff];
                    v1 += add_src[voff + 1];
                    *(float2*)(outf + (size_t)r * 256 + col) = make_float2(v0, v1);
                } else if (EPI == 1) {
                    v0 = fmaxf(v0, 0.0f);
                    v1 = fmaxf(v1, 0.0f);
                    *(__half2*)(outh + (size_t)r * opitch + col) = __floats2half2_rn(v0, v1);
                } else if (EPI == 2) {
                    size_t aoff = (size_t)r * 256 + col;
                    v0 += add_src[aoff];
                    v1 += add_src[aoff + 1];
                    *(float2*)(outf + aoff) = make_float2(v0, v1);
                } else {
                    *(float2*)(outf + (size_t)r * 256 + col) = make_float2(v0, v1);
                }
            }
        }
    }
}

// ---------------- kernel 4: attention per query ----------------
#define KPITCH 260
__global__ __launch_bounds__(256)
void attn_kernel(const int* __restrict__ gidx, const int* __restrict__ gmask,
                 const int* __restrict__ rel_x, const int* __restrict__ rel_y,
                 const int* __restrict__ rel_z,
                 const float* __restrict__ bk, const float* __restrict__ bv,
                 const float* __restrict__ pkx, const float* __restrict__ pky,
                 const float* __restrict__ pkz) {
    extern __shared__ float sm4[];
    float* k_s = sm4;
    float* v_s = sm4 + 32 * KPITCH;
    __shared__ float q_s[256];
    __shared__ float qp_s[296];
    __shared__ float attn_s[HH][KNN];
    __shared__ int idx_s[32], msk_s[32], rx_s[32], ry_s[32], rz_s[32];
    int n = blockIdx.x, t = threadIdx.x;
    if (t < 32) {
        idx_s[t] = gidx[n*KNN + t];
        msk_s[t] = gmask[n*KNN + t];
        rx_s[t]  = rel_x[n*KNN + t];
        ry_s[t]  = rel_y[n*KNN + t];
        rz_s[t]  = rel_z[n*KNN + t];
    } else if (t < 96) {
        int i = t - 32;
        ((float4*)q_s)[i] = ((const float4*)(g_q + (size_t)n * C))[i];
    } else if (t < 170) {
        int i = t - 96;
        ((float4*)qp_s)[i] = ((const float4*)(g_qp + (size_t)n * 296))[i];
    }
    __syncthreads();
#pragma unroll
    for (int i = 0; i < 8; i++) {
        int u = t + i * 256;
        int row = u >> 6, seg = u & 63;
        bool m = (msk_s[row] != 0);
        const float4* ks = m ? (const float4*)bk
                             : (const float4*)(g_kall + (size_t)idx_s[row] * C);
        const float4* vs = m ? (const float4*)bv
                             : (const float4*)(g_vall + (size_t)idx_s[row] * C);
        ((float4*)(k_s + row * KPITCH))[seg] = __ldg(&ks[seg]);
        ((float4*)(v_s + row * KPITCH))[seg] = __ldg(&vs[seg]);
    }
    __syncthreads();

    int h = t >> 5, lane = t & 31;
    {
        int rx = rx_s[lane], ry = ry_s[lane], rz = rz_s[lane];
        bool msk = (msk_s[lane] != 0);
        const float* krow = k_s + lane * KPITCH + h * DHD;
        const float* qh   = q_s + h * DHD;
        const float* pbx = pkx + h * DHD * 15 + rx;
        const float* pby = pky + h * DHD * 15 + ry;
        const float* pbz = pkz + h * DHD * 7  + rz;
        float qk = 0.0f, bias = 0.0f;
#pragma unroll
        for (int d = 0; d < DHD; d++) {
            float kv = krow[d];
            qk = fmaf(qh[d], kv, qk);
            float pw = __ldg(pbx + d * 15) + __ldg(pby + d * 15) + __ldg(pbz + d * 7);
            bias = fmaf(kv, pw, bias);
        }
        const float* qpn = qp_s + h * 37;
        float logit = qk * 0.17677669529663687f + qpn[rx] + qpn[15 + ry] + qpn[30 + rz] + bias;
        if (msk) logit = -1e9f;
        float m = logit;
#pragma unroll
        for (int o = 16; o > 0; o >>= 1) m = fmaxf(m, __shfl_xor_sync(0xffffffffu, m, o));
        float p = expf(logit - m);
        float s = p;
#pragma unroll
        for (int o = 16; o > 0; o >>= 1) s += __shfl_xor_sync(0xffffffffu, s, o);
        attn_s[h][lane] = p / s;
    }
    __syncwarp();
    {
        float o = 0.0f;
        const float* vcol = v_s + h * DHD + lane;
        const float* aw = attn_s[h];
#pragma unroll
        for (int kk = 0; kk < KNN; kk++) o = fmaf(aw[kk], vcol[kk * KPITCH], o);
        g_ao[(size_t)n * C + h * DHD + lane] = __float2half(o);
    }
}

// ---------------- kernel: LN2 over ACT -> fp16 ----------------
__global__ void ln2_kernel(const float* __restrict__ g, const float* __restrict__ b) {
    int row = blockIdx.x * 8 + (threadIdx.x >> 5);
    int lane = threadIdx.x & 31;
    const float4* xr = (const float4*)(g_act + (size_t)row * C);
    float4 v0 = xr[lane];
    float4 v1 = xr[lane + 32];
    float s = v0.x + v0.y + v0.z + v0.w + v1.x + v1.y + v1.z + v1.w;
    float q = v0.x*v0.x + v0.y*v0.y + v0.z*v0.z + v0.w*v0.w
            + v1.x*v1.x + v1.y*v1.y + v1.z*v1.z + v1.w*v1.w;
#pragma unroll
    for (int o = 16; o > 0; o >>= 1) {
        s += __shfl_xor_sync(0xffffffffu, s, o);
        q += __shfl_xor_sync(0xffffffffu, q, o);
    }
    float mu = s * (1.0f / C);
    float rs = rsqrtf(q * (1.0f / C) - mu * mu + 1e-5f);
    int c0 = lane * 4, c1 = 128 + lane * 4;
    __half2* hrow = (__half2*)(g_x + (size_t)row * C);
    hrow[lane*2+0]  = __floats2half2_rn((v0.x - mu) * rs * g[c0+0] + b[c0+0],
                                        (v0.y - mu) * rs * g[c0+1] + b[c0+1]);
    hrow[lane*2+1]  = __floats2half2_rn((v0.z - mu) * rs * g[c0+2] + b[c0+2],
                                        (v0.w - mu) * rs * g[c0+3] + b[c0+3]);
    hrow[64+lane*2] = __floats2half2_rn((v1.x - mu) * rs * g[c1+0] + b[c1+0],
                                        (v1.y - mu) * rs * g[c1+1] + b[c1+1]);
    hrow[65+lane*2] = __floats2half2_rn((v1.z - mu) * rs * g[c1+2] + b[c1+2],
                                        (v1.w - mu) * rs * g[c1+3] + b[c1+3]);
}

// ---------------- launch ----------------
extern "C" void kernel_launch(void* const* d_in, const int* in_sizes, int n_in,
                              void* d_out, int out_size) {
    const float* voxel  = (const float*)d_in[0];
    const float* coords = (const float*)d_in[1];
    const int*   qidx   = (const int*)d_in[2];
    const int*   gidx   = (const int*)d_in[3];
    const int*   gmask  = (const int*)d_in[4];
    const int*   rel_x  = (const int*)d_in[5];
    const int*   rel_y  = (const int*)d_in[6];
    const int*   rel_z  = (const int*)d_in[7];
    const float* w_pos  = (const float*)d_in[8];
    const float* b_pos  = (const float*)d_in[9];
    const float* w_q    = (const float*)d_in[10];
    const float* b_q    = (const float*)d_in[11];
    const float* w_k    = (const float*)d_in[12];
    const float* b_k    = (const float*)d_in[13];
    const float* w_v    = (const float*)d_in[14];
    const float* b_v    = (const float*)d_in[15];
    const float* w_proj = (const float*)d_in[16];
    const float* b_proj = (const float*)d_in[17];
    const float* ln1g   = (const float*)d_in[18];
    const float* ln1b   = (const float*)d_in[19];
    const float* ln2g   = (const float*)d_in[20];
    const float* ln2b   = (const float*)d_in[21];
    const float* w_ff1  = (const float*)d_in[22];
    const float* b_ff1  = (const float*)d_in[23];
    const float* w_ff2  = (const float*)d_in[24];
    const float* b_ff2  = (const float*)d_in[25];
    const float* pqx    = (const float*)d_in[26];
    const float* pqy    = (const float*)d_in[27];
    const float* pqz    = (const float*)d_in[28];
    const float* pkx    = (const float*)d_in[29];
    const float* pky    = (const float*)d_in[30];
    const float* pkz    = (const float*)d_in[31];
    float* out = (float*)d_out;

    cudaFuncSetAttribute(kvgemm_kernel,     cudaFuncAttributeMaxDynamicSharedMemorySize, 2 * STAGE_BYTES);
    cudaFuncSetAttribute(mmagemm_kernel<0>, cudaFuncAttributeMaxDynamicSharedMemorySize, 2 * STAGE_BYTES);
    cudaFuncSetAttribute(mmagemm_kernel<1>, cudaFuncAttributeMaxDynamicSharedMemorySize, 2 * STAGE_BYTES);
    cudaFuncSetAttribute(mmagemm_kernel<2>, cudaFuncAttributeMaxDynamicSharedMemorySize, 2 * STAGE_BYTES);
    cudaFuncSetAttribute(mmagemm_kernel<3>, cudaFuncAttributeMaxDynamicSharedMemorySize, 2 * STAGE_BYTES);
    cudaFuncSetAttribute(attn_kernel,       cudaFuncAttributeMaxDynamicSharedMemorySize, 2 * 32 * KPITCH * 4);

    __half *Bh, *Bl, *Wqh, *Wql, *Wph, *Wpl, *W1h, *W1l, *W2h, *W2l;
    __half *qin, *ao, *xh, *fh;
    float *act, *qv;
    cudaGetSymbolAddress((void**)&Bh, g_Bh);   cudaGetSymbolAddress((void**)&Bl, g_Bl);
    cudaGetSymbolAddress((void**)&Wqh, g_Wqh); cudaGetSymbolAddress((void**)&Wql, g_Wql);
    cudaGetSymbolAddress((void**)&Wph, g_Wph); cudaGetSymbolAddress((void**)&Wpl, g_Wpl);
    cudaGetSymbolAddress((void**)&W1h, g_W1h); cudaGetSymbolAddress((void**)&W1l, g_W1l);
    cudaGetSymbolAddress((void**)&W2h, g_W2h); cudaGetSymbolAddress((void**)&W2l, g_W2l);
    cudaGetSymbolAddress((void**)&qin, g_qin); cudaGetSymbolAddress((void**)&ao, g_ao);
    cudaGetSymbolAddress((void**)&xh, g_x);    cudaGetSymbolAddress((void**)&fh, g_f);
    cudaGetSymbolAddress((void**)&act, g_act); cudaGetSymbolAddress((void**)&qv, g_q);

    bprep_kernel<<<512, 256>>>(w_k, w_v);
    wprep_kernel<<<256, 256>>>(w_q, 256, 256, Wqh, Wql);
    wprep_kernel<<<256, 256>>>(w_proj, 256, 256, Wph, Wpl);
    wprep_kernel<<<512, 256>>>(w_ff1, 512, 256, W1h, W1l);
    wprep_kernel<<<512, 256>>>(w_ff2, 256, 512, W2h, W2l);
    ln_kernel<<<(M_VOX + 7) / 8, 256>>>(voxel, ln1g, ln1b);
    qin_kernel<<<NQ, 256>>>(coords, qidx, w_pos, b_pos);
    // q = qin @ w_q + b_q
    mmagemm_kernel<3><<<dim3(2, NQ / 128), 256, 2 * STAGE_BYTES>>>(
        qin, 256, Wqh, Wql, b_q, nullptr, nullptr, qv, nullptr, 0);
    qp_kernel<<<NQ / 32, 256>>>(pqx, pqy, pqz);
    kvgemm_kernel<<<dim3(4, (M_VOX + 127) / 128), 256, 2 * STAGE_BYTES>>>(b_k, b_v);
    attn_kernel<<<NQ, 256, 2 * 32 * KPITCH * 4>>>(gidx, gmask, rel_x, rel_y, rel_z,
                                                  b_k, b_v, pkx, pky, pkz);
    // proj: ACT = ao @ w_proj + b_proj + voxel[qidx]
    mmagemm_kernel<0><<<dim3(2, NQ / 128), 256, 2 * STAGE_BYTES>>>(
        ao, 256, Wph, Wpl, b_proj, voxel, qidx, act, nullptr, 0);
    ln2_kernel<<<NQ / 8, 256>>>(ln2g, ln2b);
    // ff1: F = relu(X @ w_ff1 + b_ff1)
    mmagemm_kernel<1><<<dim3(4, NQ / 128), 256, 2 * STAGE_BYTES>>>(
        xh, 256, W1h, W1l, b_ff1, nullptr, nullptr, nullptr, fh, 512);
    // ff2: out = ACT + F @ w_ff2 + b_ff2
    mmagemm_kernel<2><<<dim3(2, NQ / 128), 256, 2 * STAGE_BYTES>>>(
        fh, 512, W2h, W2l, b_ff2, act, nullptr, out, nullptr, 0);
}

// round 8
// speedup vs baseline: 4.7882x; 1.1779x over previous
#include <cuda_runtime.h>
#include <cuda_fp16.h>
#include <cstdint>

#define M_VOX 100000
#define NQ    8192
#define KNN   32
#define C     256
#define HH    8
#define DHD   32
#define FF    512

// ---------------- scratch (device globals; no allocations allowed) ----------------
__device__ __half g_lnh[(size_t)M_VOX * C];      // fp16 LN(voxel_features)
__device__ __half g_kall[(size_t)M_VOX * C];     // k projection of ALL voxels (fp16)
__device__ __half g_vall[(size_t)M_VOX * C];     // v projection of ALL voxels (fp16)
__device__ __half g_bkvh[512];                   // fp16 [b_k | b_v] (masked-row content)
__device__ __half g_qin[(size_t)NQ * C];         // q-input fp16
__device__ float g_q [(size_t)NQ * C];           // q projections fp32
__device__ float g_qp[(size_t)NQ * HH * 37];     // q-side pos bias
__device__ __half g_ao[(size_t)NQ * C];          // attention out fp16
__device__ float g_act[(size_t)NQ * C];          // ACT = voxel[qidx] + proj(ao)
__device__ __half g_x[(size_t)NQ * C];           // LN2(ACT) fp16
__device__ __half g_f[(size_t)NQ * FF];          // relu(ff1) fp16
// weights transposed + fp16-split, layout [n][k]
__device__ __half g_Bh[512 * 256];               // [wk|wv]
__device__ __half g_Bl[512 * 256];
__device__ __half g_Wqh[256 * 256];
__device__ __half g_Wql[256 * 256];
__device__ __half g_Wph[256 * 256];
__device__ __half g_Wpl[256 * 256];
__device__ __half g_W1h[512 * 256];
__device__ __half g_W1l[512 * 256];
__device__ __half g_W2h[256 * 512];
__device__ __half g_W2l[256 * 512];

// ---------------- helpers ----------------
__device__ __forceinline__ uint32_t smem_u32(const void* p) {
    uint32_t a;
    asm("{ .reg .u64 t; cvta.to.shared.u64 t, %1; cvt.u32.u64 %0, t; }" : "=r"(a) : "l"(p));
    return a;
}
__device__ __forceinline__ void cpasync16(uint32_t dst, const void* src) {
    asm volatile("cp.async.cg.shared.global [%0], [%1], 16;" :: "r"(dst), "l"(src));
}
#define CP_COMMIT()  asm volatile("cp.async.commit_group;" ::: "memory")
#define CP_WAIT(n)   asm volatile("cp.async.wait_group %0;" :: "n"(n) : "memory")

__device__ __forceinline__ void ldsm4(uint32_t* r, uint32_t addr) {
    asm volatile("ldmatrix.sync.aligned.m8n8.x4.shared.b16 {%0,%1,%2,%3}, [%4];"
        : "=r"(r[0]), "=r"(r[1]), "=r"(r[2]), "=r"(r[3]) : "r"(addr));
}
__device__ __forceinline__ void mma16816(float* c, const uint32_t* a, const uint32_t* b) {
    asm volatile(
        "mma.sync.aligned.m16n8k16.row.col.f32.f16.f16.f32 "
        "{%0,%1,%2,%3}, {%4,%5,%6,%7}, {%8,%9}, {%0,%1,%2,%3};"
        : "+f"(c[0]), "+f"(c[1]), "+f"(c[2]), "+f"(c[3])
        : "r"(a[0]), "r"(a[1]), "r"(a[2]), "r"(a[3]), "r"(b[0]), "r"(b[1]));
}

// ---------------- weight prep: transpose + fp16 split ----------------
__global__ void bprep_kernel(const float* __restrict__ wk, const float* __restrict__ wv,
                             const float* __restrict__ bk, const float* __restrict__ bv) {
    int idx = blockIdx.x * 256 + threadIdx.x;   // 512*256
    int n = idx >> 8, k = idx & 255;
    float val = (n < 256) ? wk[k * 256 + n] : wv[k * 256 + (n - 256)];
    __half h = __float2half(val);
    g_Bh[idx] = h;
    g_Bl[idx] = __float2half(val - __half2float(h));
    if (idx < 512)
        g_bkvh[idx] = __float2half((idx < 256) ? bk[idx] : bv[idx - 256]);
}
// src [K][N] row-major -> dst [N][K]
__global__ void wprep_kernel(const float* __restrict__ src, int N, int K,
                             __half* __restrict__ dh, __half* __restrict__ dl) {
    int idx = blockIdx.x * 256 + threadIdx.x;
    int n = idx / K, k = idx - n * K;
    float val = src[k * N + n];
    __half h = __float2half(val);
    dh[idx] = h;
    dl[idx] = __float2half(val - __half2float(h));
}

// ---------------- kernel 1: LayerNorm over all M voxels -> fp16 ----------------
__global__ void ln_kernel(const float* __restrict__ x,
                          const float* __restrict__ g,
                          const float* __restrict__ b) {
    int row = blockIdx.x * 8 + (threadIdx.x >> 5);
    if (row >= M_VOX) return;
    int lane = threadIdx.x & 31;
    const float4* xr = (const float4*)(x + (size_t)row * C);
    float4 v0 = xr[lane];
    float4 v1 = xr[lane + 32];
    float s = v0.x + v0.y + v0.z + v0.w + v1.x + v1.y + v1.z + v1.w;
    float q = v0.x*v0.x + v0.y*v0.y + v0.z*v0.z + v0.w*v0.w
            + v1.x*v1.x + v1.y*v1.y + v1.z*v1.z + v1.w*v1.w;
#pragma unroll
    for (int o = 16; o > 0; o >>= 1) {
        s += __shfl_xor_sync(0xffffffffu, s, o);
        q += __shfl_xor_sync(0xffffffffu, q, o);
    }
    float mu = s * (1.0f / C);
    float rs = rsqrtf(q * (1.0f / C) - mu * mu + 1e-5f);
    int c0 = lane * 4, c1 = 128 + lane * 4;
    __half2* hrow = (__half2*)(g_lnh + (size_t)row * C);
    hrow[lane*2+0]  = __floats2half2_rn((v0.x - mu) * rs * g[c0+0] + b[c0+0],
                                        (v0.y - mu) * rs * g[c0+1] + b[c0+1]);
    hrow[lane*2+1]  = __floats2half2_rn((v0.z - mu) * rs * g[c0+2] + b[c0+2],
                                        (v0.w - mu) * rs * g[c0+3] + b[c0+3]);
    hrow[64+lane*2] = __floats2half2_rn((v1.x - mu) * rs * g[c1+0] + b[c1+0],
                                        (v1.y - mu) * rs * g[c1+1] + b[c1+1]);
    hrow[65+lane*2] = __floats2half2_rn((v1.z - mu) * rs * g[c1+2] + b[c1+2],
                                        (v1.w - mu) * rs * g[c1+3] + b[c1+3]);
}

// ---------------- kernel: qin = ln[qidx] + relu(coords @ w_pos + b_pos) ---------
__global__ void qin_kernel(const float* __restrict__ coords, const int* __restrict__ qidx,
                           const float* __restrict__ w_pos, const float* __restrict__ b_pos) {
    int n = blockIdx.x, t = threadIdx.x;
    float cx = coords[n*3+0], cy = coords[n*3+1], cz = coords[n*3+2];
    float p = cx * w_pos[t] + cy * w_pos[C + t] + cz * w_pos[2*C + t] + b_pos[t];
    p = fmaxf(p, 0.0f);
    float lnv = __half2float(g_lnh[(size_t)qidx[n] * C + t]);
    g_qin[(size_t)n * C + t] = __float2half(lnv + p);
}

// ---------------- kernel: q-side positional bias (reads g_q) ----------------
__global__ void qp_kernel(const float* __restrict__ pqx, const float* __restrict__ pqy,
                          const float* __restrict__ pqz) {
    __shared__ float qs[32 * C];
    int t = threadIdx.x;
    int n0 = blockIdx.x * 32;
    for (int i = t; i < 32 * C; i += 256) qs[i] = g_q[(size_t)n0 * C + i];
    __syncthreads();
    for (int idx = t; idx < 32 * HH * 37; idx += 256) {
        int r   = idx / (HH * 37);
        int rem = idx - r * (HH * 37);
        int h   = rem / 37;
        int j   = rem - h * 37;
        const float* tab; int rr, stride;
        if (j < 15)      { tab = pqx + h * DHD * 15; rr = j;      stride = 15; }
        else if (j < 30) { tab = pqy + h * DHD * 15; rr = j - 15; stride = 15; }
        else             { tab = pqz + h * DHD * 7;  rr = j - 30; stride = 7;  }
        float s = 0.0f;
        const float* qrow = qs + r*C + h*DHD;
#pragma unroll
        for (int d = 0; d < DHD; d++) s = fmaf(qrow[d], __ldg(&tab[d*stride + rr]), s);
        g_qp[((size_t)(n0 + r)*HH + h)*37 + j] = s;
    }
}

// ---------------- shared MMA tile config (2-term fp16: A, Bh, Bl) ----------------
#define APITCH 40
#define MAT_BYTES (128 * APITCH * 2)        // 10240
#define STAGE_BYTES (3 * MAT_BYTES)         // 30720; 2 stages = 61440

// ---------------- kernel 3: K/V projection GEMM for ALL voxels -> fp16 out --------
__global__ __launch_bounds__(256, 2)
void kvgemm_kernel(const float* __restrict__ bk, const float* __restrict__ bv) {
    extern __shared__ __align__(16) char gsm[];
    uint32_t sb = smem_u32(gsm);
    int t = threadIdx.x;
    int warp = t >> 5, lane = t & 31;
    int n0 = blockIdx.x * 128;
    int m0 = blockIdx.y * 128;

    auto load_chunk = [&](int kc, int buf) {
        uint32_t base = sb + buf * STAGE_BYTES;
#pragma unroll
        for (int i = 0; i < 2; i++) {
            int u = t + i * 256;
            int row = u >> 2, seg = u & 3;
            int gr = m0 + row; if (gr >= M_VOX) gr = 0;
            size_t go = (size_t)gr * 256 + kc * 32 + seg * 8;
            uint32_t so = base + (row * APITCH + seg * 8) * 2;
            cpasync16(so, g_lnh + go);
            size_t gb = (size_t)(n0 + row) * 256 + kc * 32 + seg * 8;
            uint32_t sob = base + MAT_BYTES + (row * APITCH + seg * 8) * 2;
            cpasync16(sob,             g_Bh + gb);
            cpasync16(sob + MAT_BYTES, g_Bl + gb);
        }
    };

    int wm = warp & 1, wn = warp >> 1;
    float acc[4][4][4];
#pragma unroll
    for (int a = 0; a < 4; a++)
#pragma unroll
        for (int bq = 0; bq < 4; bq++)
#pragma unroll
            for (int cq = 0; cq < 4; cq++) acc[a][bq][cq] = 0.0f;

    load_chunk(0, 0); CP_COMMIT();

    for (int kc = 0; kc < 8; kc++) {
        int buf = kc & 1;
        if (kc < 7) { load_chunk(kc + 1, buf ^ 1); CP_COMMIT(); CP_WAIT(1); }
        else        { CP_WAIT(0); }
        __syncthreads();

        uint32_t abase = sb + buf * STAGE_BYTES;
        uint32_t bbase = abase + MAT_BYTES;
        uint32_t bh[4][4], bl[4][4];
#pragma unroll
        for (int ni = 0; ni < 4; ni++) {
            int nrow = wn * 32 + ni * 8 + (lane & 7);
            int koff = (lane >> 3) * 8;
            uint32_t ad = bbase + (nrow * APITCH + koff) * 2;
            ldsm4(bh[ni], ad);
            ldsm4(bl[ni], ad + MAT_BYTES);
        }
#pragma unroll
        for (int s = 0; s < 2; s++) {
#pragma unroll
            for (int mi = 0; mi < 4; mi++) {
                int arow = wm * 64 + mi * 16 + (lane & 15);
                int koff = s * 16 + (lane >> 4) * 8;
                uint32_t ah[4];
                ldsm4(ah, abase + (arow * APITCH + koff) * 2);
#pragma unroll
                for (int ni = 0; ni < 4; ni++) {
                    mma16816(acc[mi][ni], ah, &bh[ni][s*2]);
                    mma16816(acc[mi][ni], ah, &bl[ni][s*2]);
                }
            }
        }
        __syncthreads();
    }

    __half* dst = (n0 < 256) ? g_kall : g_vall;
    const float* bias = (n0 < 256) ? bk : bv;
    int cb = n0 & 255;
#pragma unroll
    for (int mi = 0; mi < 4; mi++) {
#pragma unroll
        for (int ni = 0; ni < 4; ni++) {
            int col = cb + wn * 32 + ni * 8 + (lane & 3) * 2;
            float b0 = bias[col], b1 = bias[col + 1];
            int r0 = m0 + wm * 64 + mi * 16 + (lane >> 2);
            if (r0 < M_VOX)
                *(__half2*)(dst + (size_t)r0 * 256 + col) =
                    __floats2half2_rn(acc[mi][ni][0] + b0, acc[mi][ni][1] + b1);
            int r1 = r0 + 8;
            if (r1 < M_VOX)
                *(__half2*)(dst + (size_t)r1 * 256 + col) =
                    __floats2half2_rn(acc[mi][ni][2] + b0, acc[mi][ni][3] + b1);
        }
    }
}

// ---------------- generic 2-term fp16 MMA GEMM (8192 rows), fused epilogues ------
// EPI 0: outf = acc + bias + add_src[qidx[row]]   (proj -> g_act)
// EPI 1: relu(acc + bias) -> fp16 outh            (ff1), pitch opitch
// EPI 2: outf = acc + bias + add_src[row]         (ff2 -> d_out)
// EPI 3: outf = acc + bias                        (q -> g_q)
template<int EPI>
__global__ __launch_bounds__(256, 2)
void mmagemm_kernel(const __half* __restrict__ Ah, int K,
                    const __half* __restrict__ Bh, const __half* __restrict__ Bl,
                    const float* __restrict__ bias,
                    const float* __restrict__ add_src, const int* __restrict__ qidx,
                    float* __restrict__ outf, __half* __restrict__ outh, int opitch) {
    extern __shared__ __align__(16) char gsm[];
    uint32_t sb = smem_u32(gsm);
    int t = threadIdx.x;
    int warp = t >> 5, lane = t & 31;
    int n0 = blockIdx.x * 128;
    int m0 = blockIdx.y * 128;

    auto load_chunk = [&](int kc, int buf) {
        uint32_t base = sb + buf * STAGE_BYTES;
#pragma unroll
        for (int i = 0; i < 2; i++) {
            int u = t + i * 256;
            int row = u >> 2, seg = u & 3;
            size_t go = (size_t)(m0 + row) * K + kc * 32 + seg * 8;
            uint32_t so = base + (row * APITCH + seg * 8) * 2;
            cpasync16(so, Ah + go);
            size_t gb = (size_t)(n0 + row) * K + kc * 32 + seg * 8;
            uint32_t sob = base + MAT_BYTES + (row * APITCH + seg * 8) * 2;
            cpasync16(sob,             Bh + gb);
            cpasync16(sob + MAT_BYTES, Bl + gb);
        }
    };

    int wm = warp & 1, wn = warp >> 1;
    float acc[4][4][4];
#pragma unroll
    for (int a = 0; a < 4; a++)
#pragma unroll
        for (int bq = 0; bq < 4; bq++)
#pragma unroll
            for (int cq = 0; cq < 4; cq++) acc[a][bq][cq] = 0.0f;

    int nchunks = K >> 5;
    load_chunk(0, 0); CP_COMMIT();

    for (int kc = 0; kc < nchunks; kc++) {
        int buf = kc & 1;
        if (kc < nchunks - 1) { load_chunk(kc + 1, buf ^ 1); CP_COMMIT(); CP_WAIT(1); }
        else                  { CP_WAIT(0); }
        __syncthreads();

        uint32_t abase = sb + buf * STAGE_BYTES;
        uint32_t bbase = abase + MAT_BYTES;
        uint32_t bh[4][4], bl[4][4];
#pragma unroll
        for (int ni = 0; ni < 4; ni++) {
            int nrow = wn * 32 + ni * 8 + (lane & 7);
            int koff = (lane >> 3) * 8;
            uint32_t ad = bbase + (nrow * APITCH + koff) * 2;
            ldsm4(bh[ni], ad);
            ldsm4(bl[ni], ad + MAT_BYTES);
        }
#pragma unroll
        for (int s = 0; s < 2; s++) {
#pragma unroll
            for (int mi = 0; mi < 4; mi++) {
                int arow = wm * 64 + mi * 16 + (lane & 15);
                int koff = s * 16 + (lane >> 4) * 8;
                uint32_t ah[4];
                ldsm4(ah, abase + (arow * APITCH + koff) * 2);
#pragma unroll
                for (int ni = 0; ni < 4; ni++) {
                    mma16816(acc[mi][ni], ah, &bh[ni][s*2]);
                    mma16816(acc[mi][ni], ah, &bl[ni][s*2]);
                }
            }
        }
        __syncthreads();
    }

#pragma unroll
    for (int mi = 0; mi < 4; mi++) {
#pragma unroll
        for (int ni = 0; ni < 4; ni++) {
            int col = n0 + wn * 32 + ni * 8 + (lane & 3) * 2;
            float b0 = bias[col], b1 = bias[col + 1];
#pragma unroll
            for (int half = 0; half < 2; half++) {
                int r = m0 + wm * 64 + mi * 16 + (lane >> 2) + half * 8;
                float v0 = acc[mi][ni][half*2+0] + b0;
                float v1 = acc[mi][ni][half*2+1] + b1;
                if (EPI == 0) {
                    size_t voff = (size_t)qidx[r] * 256 + col;
                    v0 += add_src[voff];
                    v1 += add_src[voff + 1];
                    *(float2*)(outf + (size_t)r * 256 + col) = make_float2(v0, v1);
                } else if (EPI == 1) {
                    v0 = fmaxf(v0, 0.0f);
                    v1 = fmaxf(v1, 0.0f);
                    *(__half2*)(outh + (size_t)r * opitch + col) = __floats2half2_rn(v0, v1);
                } else if (EPI == 2) {
                    size_t aoff = (size_t)r * 256 + col;
                    v0 += add_src[aoff];
                    v1 += add_src[aoff + 1];
                    *(float2*)(outf + aoff) = make_float2(v0, v1);
                } else {
                    *(float2*)(outf + (size_t)r * 256 + col) = make_float2(v0, v1);
                }
            }
        }
    }
}

// ---------------- kernel 4: attention per query (fp16 k/v staging) ----------------
#define KPITCH 264   // halfs per row (528B)
__global__ __launch_bounds__(256)
void attn_kernel(const int* __restrict__ gidx, const int* __restrict__ gmask,
                 const int* __restrict__ rel_x, const int* __restrict__ rel_y,
                 const int* __restrict__ rel_z,
                 const float* __restrict__ pkx, const float* __restrict__ pky,
                 const float* __restrict__ pkz) {
    extern __shared__ __half sm4h[];
    __half* k_s = sm4h;                   // 32 x KPITCH halfs
    __half* v_s = sm4h + 32 * KPITCH;
    __shared__ float q_s[256];
    __shared__ float qp_s[296];
    __shared__ float attn_s[HH][KNN];
    __shared__ int idx_s[32], msk_s[32], rx_s[32], ry_s[32], rz_s[32];
    int n = blockIdx.x, t = threadIdx.x;
    if (t < 32) {
        idx_s[t] = gidx[n*KNN + t];
        msk_s[t] = gmask[n*KNN + t];
        rx_s[t]  = rel_x[n*KNN + t];
        ry_s[t]  = rel_y[n*KNN + t];
        rz_s[t]  = rel_z[n*KNN + t];
    } else if (t < 96) {
        int i = t - 32;
        ((float4*)q_s)[i] = ((const float4*)(g_q + (size_t)n * C))[i];
    } else if (t < 170) {
        int i = t - 96;
        ((float4*)qp_s)[i] = ((const float4*)(g_qp + (size_t)n * 296))[i];
    }
    __syncthreads();
    // stage k/v: 32 rows x 32 segs of 8 halfs per matrix; 4 segs per thread each
#pragma unroll
    for (int i = 0; i < 4; i++) {
        int u = t + i * 256;
        int row = u >> 5, seg = u & 31;
        bool m = (msk_s[row] != 0);
        const uint4* ks = m ? (const uint4*)(g_bkvh)
                            : (const uint4*)(g_kall + (size_t)idx_s[row] * C);
        const uint4* vs = m ? (const uint4*)(g_bkvh + 256)
                            : (const uint4*)(g_vall + (size_t)idx_s[row] * C);
        *(uint4*)(k_s + row * KPITCH + seg * 8) = __ldg(&ks[seg]);
        *(uint4*)(v_s + row * KPITCH + seg * 8) = __ldg(&vs[seg]);
    }
    __syncthreads();

    int h = t >> 5, lane = t & 31;
    {
        int rx = rx_s[lane], ry = ry_s[lane], rz = rz_s[lane];
        bool msk = (msk_s[lane] != 0);
        const __half2* krow = (const __half2*)(k_s + lane * KPITCH + h * DHD);
        const float* qh   = q_s + h * DHD;
        const float* pbx = pkx + h * DHD * 15 + rx;
        const float* pby = pky + h * DHD * 15 + ry;
        const float* pbz = pkz + h * DHD * 7  + rz;
        float qk = 0.0f, bias = 0.0f;
#pragma unroll
        for (int d2 = 0; d2 < DHD / 2; d2++) {
            float2 kv = __half22float2(krow[d2]);
            qk = fmaf(qh[d2*2+0], kv.x, qk);
            qk = fmaf(qh[d2*2+1], kv.y, qk);
            float pw0 = __ldg(pbx + (d2*2+0) * 15) + __ldg(pby + (d2*2+0) * 15) + __ldg(pbz + (d2*2+0) * 7);
            float pw1 = __ldg(pbx + (d2*2+1) * 15) + __ldg(pby + (d2*2+1) * 15) + __ldg(pbz + (d2*2+1) * 7);
            bias = fmaf(kv.x, pw0, bias);
            bias = fmaf(kv.y, pw1, bias);
        }
        const float* qpn = qp_s + h * 37;
        float logit = qk * 0.17677669529663687f + qpn[rx] + qpn[15 + ry] + qpn[30 + rz] + bias;
        if (msk) logit = -1e9f;
        float m = logit;
#pragma unroll
        for (int o = 16; o > 0; o >>= 1) m = fmaxf(m, __shfl_xor_sync(0xffffffffu, m, o));
        float p = expf(logit - m);
        float s = p;
#pragma unroll
        for (int o = 16; o > 0; o >>= 1) s += __shfl_xor_sync(0xffffffffu, s, o);
        attn_s[h][lane] = p / s;
    }
    __syncwarp();
    {
        float o = 0.0f;
        const __half* vcol = v_s + h * DHD + lane;
        const float* aw = attn_s[h];
#pragma unroll
        for (int kk = 0; kk < KNN; kk++)
            o = fmaf(aw[kk], __half2float(vcol[kk * KPITCH]), o);
        g_ao[(size_t)n * C + h * DHD + lane] = __float2half(o);
    }
}

// ---------------- kernel: LN2 over ACT -> fp16 ----------------
__global__ void ln2_kernel(const float* __restrict__ g, const float* __restrict__ b) {
    int row = blockIdx.x * 8 + (threadIdx.x >> 5);
    int lane = threadIdx.x & 31;
    const float4* xr = (const float4*)(g_act + (size_t)row * C);
    float4 v0 = xr[lane];
    float4 v1 = xr[lane + 32];
    float s = v0.x + v0.y + v0.z + v0.w + v1.x + v1.y + v1.z + v1.w;
    float q = v0.x*v0.x + v0.y*v0.y + v0.z*v0.z + v0.w*v0.w
            + v1.x*v1.x + v1.y*v1.y + v1.z*v1.z + v1.w*v1.w;
#pragma unroll
    for (int o = 16; o > 0; o >>= 1) {
        s += __shfl_xor_sync(0xffffffffu, s, o);
        q += __shfl_xor_sync(0xffffffffu, q, o);
    }
    float mu = s * (1.0f / C);
    float rs = rsqrtf(q * (1.0f / C) - mu * mu + 1e-5f);
    int c0 = lane * 4, c1 = 128 + lane * 4;
    __half2* hrow = (__half2*)(g_x + (size_t)row * C);
    hrow[lane*2+0]  = __floats2half2_rn((v0.x - mu) * rs * g[c0+0] + b[c0+0],
                                        (v0.y - mu) * rs * g[c0+1] + b[c0+1]);
    hrow[lane*2+1]  = __floats2half2_rn((v0.z - mu) * rs * g[c0+2] + b[c0+2],
                                        (v0.w - mu) * rs * g[c0+3] + b[c0+3]);
    hrow[64+lane*2] = __floats2half2_rn((v1.x - mu) * rs * g[c1+0] + b[c1+0],
                                        (v1.y - mu) * rs * g[c1+1] + b[c1+1]);
    hrow[65+lane*2] = __floats2half2_rn((v1.z - mu) * rs * g[c1+2] + b[c1+2],
                                        (v1.w - mu) * rs * g[c1+3] + b[c1+3]);
}

// ---------------- launch ----------------
extern "C" void kernel_launch(void* const* d_in, const int* in_sizes, int n_in,
                              void* d_out, int out_size) {
    const float* voxel  = (const float*)d_in[0];
    const float* coords = (const float*)d_in[1];
    const int*   qidx   = (const int*)d_in[2];
    const int*   gidx   = (const int*)d_in[3];
    const int*   gmask  = (const int*)d_in[4];
    const int*   rel_x  = (const int*)d_in[5];
    const int*   rel_y  = (const int*)d_in[6];
    const int*   rel_z  = (const int*)d_in[7];
    const float* w_pos  = (const float*)d_in[8];
    const float* b_pos  = (const float*)d_in[9];
    const float* w_q    = (const float*)d_in[10];
    const float* b_q    = (const float*)d_in[11];
    const float* w_k    = (const float*)d_in[12];
    const float* b_k    = (const float*)d_in[13];
    const float* w_v    = (const float*)d_in[14];
    const float* b_v    = (const float*)d_in[15];
    const float* w_proj = (const float*)d_in[16];
    const float* b_proj = (const float*)d_in[17];
    const float* ln1g   = (const float*)d_in[18];
    const float* ln1b   = (const float*)d_in[19];
    const float* ln2g   = (const float*)d_in[20];
    const float* ln2b   = (const float*)d_in[21];
    const float* w_ff1  = (const float*)d_in[22];
    const float* b_ff1  = (const float*)d_in[23];
    const float* w_ff2  = (const float*)d_in[24];
    const float* b_ff2  = (const float*)d_in[25];
    const float* pqx    = (const float*)d_in[26];
    const float* pqy    = (const float*)d_in[27];
    const float* pqz    = (const float*)d_in[28];
    const float* pkx    = (const float*)d_in[29];
    const float* pky    = (const float*)d_in[30];
    const float* pkz    = (const float*)d_in[31];
    float* out = (float*)d_out;

    int attn_smem = 2 * 32 * KPITCH * 2;   // two half matrices

    cudaFuncSetAttribute(kvgemm_kernel,     cudaFuncAttributeMaxDynamicSharedMemorySize, 2 * STAGE_BYTES);
    cudaFuncSetAttribute(mmagemm_kernel<0>, cudaFuncAttributeMaxDynamicSharedMemorySize, 2 * STAGE_BYTES);
    cudaFuncSetAttribute(mmagemm_kernel<1>, cudaFuncAttributeMaxDynamicSharedMemorySize, 2 * STAGE_BYTES);
    cudaFuncSetAttribute(mmagemm_kernel<2>, cudaFuncAttributeMaxDynamicSharedMemorySize, 2 * STAGE_BYTES);
    cudaFuncSetAttribute(mmagemm_kernel<3>, cudaFuncAttributeMaxDynamicSharedMemorySize, 2 * STAGE_BYTES);
    cudaFuncSetAttribute(attn_kernel,       cudaFuncAttributeMaxDynamicSharedMemorySize, attn_smem);

    __half *Bh, *Bl, *Wqh, *Wql, *Wph, *Wpl, *W1h, *W1l, *W2h, *W2l;
    __half *qin, *ao, *xh, *fh;
    float *act, *qv;
    cudaGetSymbolAddress((void**)&Bh, g_Bh);   cudaGetSymbolAddress((void**)&Bl, g_Bl);
    cudaGetSymbolAddress((void**)&Wqh, g_Wqh); cudaGetSymbolAddress((void**)&Wql, g_Wql);
    cudaGetSymbolAddress((void**)&Wph, g_Wph); cudaGetSymbolAddress((void**)&Wpl, g_Wpl);
    cudaGetSymbolAddress((void**)&W1h, g_W1h); cudaGetSymbolAddress((void**)&W1l, g_W1l);
    cudaGetSymbolAddress((void**)&W2h, g_W2h); cudaGetSymbolAddress((void**)&W2l, g_W2l);
    cudaGetSymbolAddress((void**)&qin, g_qin); cudaGetSymbolAddress((void**)&ao, g_ao);
    cudaGetSymbolAddress((void**)&xh, g_x);    cudaGetSymbolAddress((void**)&fh, g_f);
    cudaGetSymbolAddress((void**)&act, g_act); cudaGetSymbolAddress((void**)&qv, g_q);

    bprep_kernel<<<512, 256>>>(w_k, w_v, b_k, b_v);
    wprep_kernel<<<256, 256>>>(w_q, 256, 256, Wqh, Wql);
    wprep_kernel<<<256, 256>>>(w_proj, 256, 256, Wph, Wpl);
    wprep_kernel<<<512, 256>>>(w_ff1, 512, 256, W1h, W1l);
    wprep_kernel<<<512, 256>>>(w_ff2, 256, 512, W2h, W2l);
    ln_kernel<<<(M_VOX + 7) / 8, 256>>>(voxel, ln1g, ln1b);
    qin_kernel<<<NQ, 256>>>(coords, qidx, w_pos, b_pos);
    // q = qin @ w_q + b_q
    mmagemm_kernel<3><<<dim3(2, NQ / 128), 256, 2 * STAGE_BYTES>>>(
        qin, 256, Wqh, Wql, b_q, nullptr, nullptr, qv, nullptr, 0);
    qp_kernel<<<NQ / 32, 256>>>(pqx, pqy, pqz);
    kvgemm_kernel<<<dim3(4, (M_VOX + 127) / 128), 256, 2 * STAGE_BYTES>>>(b_k, b_v);
    attn_kernel<<<NQ, 256, attn_smem>>>(gidx, gmask, rel_x, rel_y, rel_z,
                                        pkx, pky, pkz);
    // proj: ACT = ao @ w_proj + b_proj + voxel[qidx]
    mmagemm_kernel<0><<<dim3(2, NQ / 128), 256, 2 * STAGE_BYTES>>>(
        ao, 256, Wph, Wpl, b_proj, voxel, qidx, act, nullptr, 0);
    ln2_kernel<<<NQ / 8, 256>>>(ln2g, ln2b);
    // ff1: F = relu(X @ w_ff1 + b_ff1)
    mmagemm_kernel<1><<<dim3(4, NQ / 128), 256, 2 * STAGE_BYTES>>>(
        xh, 256, W1h, W1l, b_ff1, nullptr, nullptr, nullptr, fh, 512);
    // ff2: out = ACT + F @ w_ff2 + b_ff2
    mmagemm_kernel<2><<<dim3(2, NQ / 128), 256, 2 * STAGE_BYTES>>>(
        fh, 512, W2h, W2l, b_ff2, act, nullptr, out, nullptr, 0);
}

// round 9
// speedup vs baseline: 4.7937x; 1.0012x over previous
#include <cuda_runtime.h>
#include <cuda_fp16.h>
#include <cstdint>

#define M_VOX 100000
#define NQ    8192
#define KNN   32
#define C     256
#define HH    8
#define DHD   32
#define FF    512

// ---------------- scratch (device globals; no allocations allowed) ----------------
__device__ __half g_lnh[(size_t)M_VOX * C];      // fp16 LN(voxel_features)
__device__ __half g_kall[(size_t)M_VOX * C];     // k projection of ALL voxels (fp16)
__device__ __half g_vall[(size_t)M_VOX * C];     // v projection of ALL voxels (fp16)
__device__ __half g_bkvh[512];                   // fp16 [b_k | b_v] (masked-row content)
__device__ __half g_qin[(size_t)NQ * C];         // q-input fp16
__device__ float g_q [(size_t)NQ * C];           // q projections fp32
__device__ float g_qp[(size_t)NQ * HH * 37];     // q-side pos bias
__device__ __half g_ao[(size_t)NQ * C];          // attention out fp16
__device__ float g_act[(size_t)NQ * C];          // ACT = voxel[qidx] + proj(ao)
__device__ __half g_x[(size_t)NQ * C];           // LN2(ACT) fp16
__device__ __half g_f[(size_t)NQ * FF];          // relu(ff1) fp16
// weights transposed + fp16-split, layout [n][k]
__device__ __half g_Bh[512 * 256];               // [wk|wv]
__device__ __half g_Bl[512 * 256];
__device__ __half g_Wqh[256 * 256];
__device__ __half g_Wql[256 * 256];
__device__ __half g_Wph[256 * 256];
__device__ __half g_Wpl[256 * 256];
__device__ __half g_W1h[512 * 256];
__device__ __half g_W1l[512 * 256];
__device__ __half g_W2h[256 * 512];
__device__ __half g_W2l[256 * 512];

// ---------------- helpers ----------------
__device__ __forceinline__ uint32_t smem_u32(const void* p) {
    uint32_t a;
    asm("{ .reg .u64 t; cvta.to.shared.u64 t, %1; cvt.u32.u64 %0, t; }" : "=r"(a) : "l"(p));
    return a;
}
__device__ __forceinline__ void cpasync16(uint32_t dst, const void* src) {
    asm volatile("cp.async.cg.shared.global [%0], [%1], 16;" :: "r"(dst), "l"(src));
}
#define CP_COMMIT()  asm volatile("cp.async.commit_group;" ::: "memory")
#define CP_WAIT(n)   asm volatile("cp.async.wait_group %0;" :: "n"(n) : "memory")

__device__ __forceinline__ void ldsm4(uint32_t* r, uint32_t addr) {
    asm volatile("ldmatrix.sync.aligned.m8n8.x4.shared.b16 {%0,%1,%2,%3}, [%4];"
        : "=r"(r[0]), "=r"(r[1]), "=r"(r[2]), "=r"(r[3]) : "r"(addr));
}
__device__ __forceinline__ void mma16816(float* c, const uint32_t* a, const uint32_t* b) {
    asm volatile(
        "mma.sync.aligned.m16n8k16.row.col.f32.f16.f16.f32 "
        "{%0,%1,%2,%3}, {%4,%5,%6,%7}, {%8,%9}, {%0,%1,%2,%3};"
        : "+f"(c[0]), "+f"(c[1]), "+f"(c[2]), "+f"(c[3])
        : "r"(a[0]), "r"(a[1]), "r"(a[2]), "r"(a[3]), "r"(b[0]), "r"(b[1]));
}

// ---------------- fused weight prep: all transposes + fp16 splits in ONE kernel ----
// blocks [0,512): [wk|wv] -> g_Bh/g_Bl (+ bias rows)
// [512,768): w_q       [768,1024): w_proj
// [1024,1536): w_ff1   [1536,2048): w_ff2
__global__ void prep_kernel(const float* __restrict__ wk, const float* __restrict__ wv,
                            const float* __restrict__ bk, const float* __restrict__ bv,
                            const float* __restrict__ wq, const float* __restrict__ wp,
                            const float* __restrict__ w1, const float* __restrict__ w2) {
    int b = blockIdx.x, t = threadIdx.x;
    if (b < 512) {
        int idx = b * 256 + t;
        int n = idx >> 8, k = idx & 255;
        float val = (n < 256) ? wk[k * 256 + n] : wv[k * 256 + (n - 256)];
        __half h = __float2half(val);
        g_Bh[idx] = h;
        g_Bl[idx] = __float2half(val - __half2float(h));
        if (idx < 512)
            g_bkvh[idx] = __float2half((idx < 256) ? bk[idx] : bv[idx - 256]);
        return;
    }
    const float* src; __half* dh; __half* dl; int N, K, idx;
    if (b < 768)       { src = wq; dh = g_Wqh; dl = g_Wql; N = 256; K = 256; idx = (b - 512) * 256 + t; }
    else if (b < 1024) { src = wp; dh = g_Wph; dl = g_Wpl; N = 256; K = 256; idx = (b - 768) * 256 + t; }
    else if (b < 1536) { src = w1; dh = g_W1h; dl = g_W1l; N = 512; K = 256; idx = (b - 1024) * 256 + t; }
    else               { src = w2; dh = g_W2h; dl = g_W2l; N = 256; K = 512; idx = (b - 1536) * 256 + t; }
    int n = idx / K, k = idx - n * K;
    float val = src[k * N + n];
    __half h = __float2half(val);
    dh[idx] = h;
    dl[idx] = __float2half(val - __half2float(h));
}

// ---------------- kernel 1: LayerNorm over all M voxels -> fp16 (2 rows/warp) -----
__global__ void ln_kernel(const float* __restrict__ x,
                          const float* __restrict__ g,
                          const float* __restrict__ b) {
    int wid = threadIdx.x >> 5, lane = threadIdx.x & 31;
    int r0 = blockIdx.x * 16 + wid * 2;          // 6250 blocks * 16 rows = 100000 exactly
    const float4* xr0 = (const float4*)(x + (size_t)r0 * C);
    const float4* xr1 = (const float4*)(x + (size_t)(r0 + 1) * C);
    float4 a0 = xr0[lane], a1 = xr0[lane + 32];
    float4 c0 = xr1[lane], c1 = xr1[lane + 32];
    float sA = a0.x + a0.y + a0.z + a0.w + a1.x + a1.y + a1.z + a1.w;
    float qA = a0.x*a0.x + a0.y*a0.y + a0.z*a0.z + a0.w*a0.w
             + a1.x*a1.x + a1.y*a1.y + a1.z*a1.z + a1.w*a1.w;
    float sB = c0.x + c0.y + c0.z + c0.w + c1.x + c1.y + c1.z + c1.w;
    float qB = c0.x*c0.x + c0.y*c0.y + c0.z*c0.z + c0.w*c0.w
             + c1.x*c1.x + c1.y*c1.y + c1.z*c1.z + c1.w*c1.w;
#pragma unroll
    for (int o = 16; o > 0; o >>= 1) {
        sA += __shfl_xor_sync(0xffffffffu, sA, o);
        qA += __shfl_xor_sync(0xffffffffu, qA, o);
        sB += __shfl_xor_sync(0xffffffffu, sB, o);
        qB += __shfl_xor_sync(0xffffffffu, qB, o);
    }
    float muA = sA * (1.0f / C);
    float rsA = rsqrtf(qA * (1.0f / C) - muA * muA + 1e-5f);
    float muB = sB * (1.0f / C);
    float rsB = rsqrtf(qB * (1.0f / C) - muB * muB + 1e-5f);
    int cc0 = lane * 4, cc1 = 128 + lane * 4;
    float g0 = g[cc0+0], g1 = g[cc0+1], g2 = g[cc0+2], g3 = g[cc0+3];
    float g4 = g[cc1+0], g5 = g[cc1+1], g6 = g[cc1+2], g7 = g[cc1+3];
    float b0 = b[cc0+0], b1 = b[cc0+1], b2 = b[cc0+2], b3 = b[cc0+3];
    float b4 = b[cc1+0], b5 = b[cc1+1], b6 = b[cc1+2], b7 = b[cc1+3];
    __half2* h0 = (__half2*)(g_lnh + (size_t)r0 * C);
    __half2* h1 = (__half2*)(g_lnh + (size_t)(r0 + 1) * C);
    h0[lane*2+0]  = __floats2half2_rn((a0.x - muA)*rsA*g0 + b0, (a0.y - muA)*rsA*g1 + b1);
    h0[lane*2+1]  = __floats2half2_rn((a0.z - muA)*rsA*g2 + b2, (a0.w - muA)*rsA*g3 + b3);
    h0[64+lane*2] = __floats2half2_rn((a1.x - muA)*rsA*g4 + b4, (a1.y - muA)*rsA*g5 + b5);
    h0[65+lane*2] = __floats2half2_rn((a1.z - muA)*rsA*g6 + b6, (a1.w - muA)*rsA*g7 + b7);
    h1[lane*2+0]  = __floats2half2_rn((c0.x - muB)*rsB*g0 + b0, (c0.y - muB)*rsB*g1 + b1);
    h1[lane*2+1]  = __floats2half2_rn((c0.z - muB)*rsB*g2 + b2, (c0.w - muB)*rsB*g3 + b3);
    h1[64+lane*2] = __floats2half2_rn((c1.x - muB)*rsB*g4 + b4, (c1.y - muB)*rsB*g5 + b5);
    h1[65+lane*2] = __floats2half2_rn((c1.z - muB)*rsB*g6 + b6, (c1.w - muB)*rsB*g7 + b7);
}

// ---------------- kernel: qin = ln[qidx] + relu(coords @ w_pos + b_pos) ---------
__global__ void qin_kernel(const float* __restrict__ coords, const int* __restrict__ qidx,
                           const float* __restrict__ w_pos, const float* __restrict__ b_pos) {
    int n = blockIdx.x, t = threadIdx.x;
    float cx = coords[n*3+0], cy = coords[n*3+1], cz = coords[n*3+2];
    float p = cx * w_pos[t] + cy * w_pos[C + t] + cz * w_pos[2*C + t] + b_pos[t];
    p = fmaxf(p, 0.0f);
    float lnv = __half2float(g_lnh[(size_t)qidx[n] * C + t]);
    g_qin[(size_t)n * C + t] = __float2half(lnv + p);
}

// ---------------- kernel: q-side positional bias (reads g_q) ----------------
__global__ void qp_kernel(const float* __restrict__ pqx, const float* __restrict__ pqy,
                          const float* __restrict__ pqz) {
    __shared__ float qs[32 * C];
    int t = threadIdx.x;
    int n0 = blockIdx.x * 32;
    for (int i = t; i < 32 * C; i += 256) qs[i] = g_q[(size_t)n0 * C + i];
    __syncthreads();
    for (int idx = t; idx < 32 * HH * 37; idx += 256) {
        int r   = idx / (HH * 37);
        int rem = idx - r * (HH * 37);
        int h   = rem / 37;
        int j   = rem - h * 37;
        const float* tab; int rr, stride;
        if (j < 15)      { tab = pqx + h * DHD * 15; rr = j;      stride = 15; }
        else if (j < 30) { tab = pqy + h * DHD * 15; rr = j - 15; stride = 15; }
        else             { tab = pqz + h * DHD * 7;  rr = j - 30; stride = 7;  }
        float s = 0.0f;
        const float* qrow = qs + r*C + h*DHD;
#pragma unroll
        for (int d = 0; d < DHD; d++) s = fmaf(qrow[d], __ldg(&tab[d*stride + rr]), s);
        g_qp[((size_t)(n0 + r)*HH + h)*37 + j] = s;
    }
}

// ---------------- MMA tile configs (2-term fp16: A, Bh, Bl) ----------------
#define APITCH 40
// kvgemm: 128-row A tile
#define MAT_BYTES (128 * APITCH * 2)        // 10240
#define STAGE_BYTES (3 * MAT_BYTES)         // 30720; 2 stages = 61440
// NQ gemms: 64-row A tile
#define MATA64 (64 * APITCH * 2)            // 5120
#define STAGE64 (MATA64 + 2 * MAT_BYTES)    // 25600; 2 stages = 51200

// ---------------- kernel 3: K/V projection GEMM for ALL voxels -> fp16 out --------
__global__ __launch_bounds__(256, 2)
void kvgemm_kernel(const float* __restrict__ bk, const float* __restrict__ bv) {
    extern __shared__ __align__(16) char gsm[];
    uint32_t sb = smem_u32(gsm);
    int t = threadIdx.x;
    int warp = t >> 5, lane = t & 31;
    int n0 = blockIdx.x * 128;
    int m0 = blockIdx.y * 128;

    auto load_chunk = [&](int kc, int buf) {
        uint32_t base = sb + buf * STAGE_BYTES;
#pragma unroll
        for (int i = 0; i < 2; i++) {
            int u = t + i * 256;
            int row = u >> 2, seg = u & 3;
            int gr = m0 + row; if (gr >= M_VOX) gr = 0;
            size_t go = (size_t)gr * 256 + kc * 32 + seg * 8;
            uint32_t so = base + (row * APITCH + seg * 8) * 2;
            cpasync16(so, g_lnh + go);
            size_t gb = (size_t)(n0 + row) * 256 + kc * 32 + seg * 8;
            uint32_t sob = base + MAT_BYTES + (row * APITCH + seg * 8) * 2;
            cpasync16(sob,             g_Bh + gb);
            cpasync16(sob + MAT_BYTES, g_Bl + gb);
        }
    };

    int wm = warp & 1, wn = warp >> 1;
    float acc[4][4][4];
#pragma unroll
    for (int a = 0; a < 4; a++)
#pragma unroll
        for (int bq = 0; bq < 4; bq++)
#pragma unroll
            for (int cq = 0; cq < 4; cq++) acc[a][bq][cq] = 0.0f;

    load_chunk(0, 0); CP_COMMIT();

    for (int kc = 0; kc < 8; kc++) {
        int buf = kc & 1;
        if (kc < 7) { load_chunk(kc + 1, buf ^ 1); CP_COMMIT(); CP_WAIT(1); }
        else        { CP_WAIT(0); }
        __syncthreads();

        uint32_t abase = sb + buf * STAGE_BYTES;
        uint32_t bbase = abase + MAT_BYTES;
        uint32_t bh[4][4], bl[4][4];
#pragma unroll
        for (int ni = 0; ni < 4; ni++) {
            int nrow = wn * 32 + ni * 8 + (lane & 7);
            int koff = (lane >> 3) * 8;
            uint32_t ad = bbase + (nrow * APITCH + koff) * 2;
            ldsm4(bh[ni], ad);
            ldsm4(bl[ni], ad + MAT_BYTES);
        }
#pragma unroll
        for (int s = 0; s < 2; s++) {
#pragma unroll
            for (int mi = 0; mi < 4; mi++) {
                int arow = wm * 64 + mi * 16 + (lane & 15);
                int koff = s * 16 + (lane >> 4) * 8;
                uint32_t ah[4];
                ldsm4(ah, abase + (arow * APITCH + koff) * 2);
#pragma unroll
                for (int ni = 0; ni < 4; ni++) {
                    mma16816(acc[mi][ni], ah, &bh[ni][s*2]);
                    mma16816(acc[mi][ni], ah, &bl[ni][s*2]);
                }
            }
        }
        __syncthreads();
    }

    __half* dst = (n0 < 256) ? g_kall : g_vall;
    const float* bias = (n0 < 256) ? bk : bv;
    int cb = n0 & 255;
#pragma unroll
    for (int mi = 0; mi < 4; mi++) {
#pragma unroll
        for (int ni = 0; ni < 4; ni++) {
            int col = cb + wn * 32 + ni * 8 + (lane & 3) * 2;
            float b0 = bias[col], b1 = bias[col + 1];
            int r0 = m0 + wm * 64 + mi * 16 + (lane >> 2);
            if (r0 < M_VOX)
                *(__half2*)(dst + (size_t)r0 * 256 + col) =
                    __floats2half2_rn(acc[mi][ni][0] + b0, acc[mi][ni][1] + b1);
            int r1 = r0 + 8;
            if (r1 < M_VOX)
                *(__half2*)(dst + (size_t)r1 * 256 + col) =
                    __floats2half2_rn(acc[mi][ni][2] + b0, acc[mi][ni][3] + b1);
        }
    }
}

// ---------------- generic 2-term fp16 MMA GEMM, 64-row tiles, fused epilogues -----
// EPI 0: outf = acc + bias + add_src[qidx[row]]   (proj -> g_act)
// EPI 1: relu(acc + bias) -> fp16 outh            (ff1), pitch opitch
// EPI 2: outf = acc + bias + add_src[row]         (ff2 -> d_out)
// EPI 3: outf = acc + bias                        (q -> g_q)
template<int EPI>
__global__ __launch_bounds__(256, 2)
void mmagemm_kernel(const __half* __restrict__ Ah, int K,
                    const __half* __restrict__ Bh, const __half* __restrict__ Bl,
                    const float* __restrict__ bias,
                    const float* __restrict__ add_src, const int* __restrict__ qidx,
                    float* __restrict__ outf, __half* __restrict__ outh, int opitch) {
    extern __shared__ __align__(16) char gsm[];
    uint32_t sb = smem_u32(gsm);
    int t = threadIdx.x;
    int warp = t >> 5, lane = t & 31;
    int n0 = blockIdx.x * 128;
    int m0 = blockIdx.y * 64;

    auto load_chunk = [&](int kc, int buf) {
        uint32_t base = sb + buf * STAGE64;
        // A: 64 rows x 4 segs = 256 units (one per thread)
        {
            int row = t >> 2, seg = t & 3;
            size_t go = (size_t)(m0 + row) * K + kc * 32 + seg * 8;
            cpasync16(base + (row * APITCH + seg * 8) * 2, Ah + go);
        }
        // B: 128 rows x 4 segs = 512 units
#pragma unroll
        for (int i = 0; i < 2; i++) {
            int u = t + i * 256;
            int row = u >> 2, seg = u & 3;
            size_t gb = (size_t)(n0 + row) * K + kc * 32 + seg * 8;
            uint32_t sob = base + MATA64 + (row * APITCH + seg * 8) * 2;
            cpasync16(sob,             Bh + gb);
            cpasync16(sob + MAT_BYTES, Bl + gb);
        }
    };

    int wm = warp & 1, wn = warp >> 1;   // 2m x 4n over 64x128
    float acc[2][4][4];
#pragma unroll
    for (int a = 0; a < 2; a++)
#pragma unroll
        for (int bq = 0; bq < 4; bq++)
#pragma unroll
            for (int cq = 0; cq < 4; cq++) acc[a][bq][cq] = 0.0f;

    int nchunks = K >> 5;
    load_chunk(0, 0); CP_COMMIT();

    for (int kc = 0; kc < nchunks; kc++) {
        int buf = kc & 1;
        if (kc < nchunks - 1) { load_chunk(kc + 1, buf ^ 1); CP_COMMIT(); CP_WAIT(1); }
        else                  { CP_WAIT(0); }
        __syncthreads();

        uint32_t abase = sb + buf * STAGE64;
        uint32_t bbase = abase + MATA64;
        uint32_t bh[4][4], bl[4][4];
#pragma unroll
        for (int ni = 0; ni < 4; ni++) {
            int nrow = wn * 32 + ni * 8 + (lane & 7);
            int koff = (lane >> 3) * 8;
            uint32_t ad = bbase + (nrow * APITCH + koff) * 2;
            ldsm4(bh[ni], ad);
            ldsm4(bl[ni], ad + MAT_BYTES);
        }
#pragma unroll
        for (int s = 0; s < 2; s++) {
#pragma unroll
            for (int mi = 0; mi < 2; mi++) {
                int arow = wm * 32 + mi * 16 + (lane & 15);
                int koff = s * 16 + (lane >> 4) * 8;
                uint32_t ah[4];
                ldsm4(ah, abase + (arow * APITCH + koff) * 2);
#pragma unroll
                for (int ni = 0; ni < 4; ni++) {
                    mma16816(acc[mi][ni], ah, &bh[ni][s*2]);
                    mma16816(acc[mi][ni], ah, &bl[ni][s*2]);
                }
            }
        }
        __syncthreads();
    }

#pragma unroll
    for (int mi = 0; mi < 2; mi++) {
#pragma unroll
        for (int ni = 0; ni < 4; ni++) {
            int col = n0 + wn * 32 + ni * 8 + (lane & 3) * 2;
            float b0 = bias[col], b1 = bias[col + 1];
#pragma unroll
            for (int half = 0; half < 2; half++) {
                int r = m0 + wm * 32 + mi * 16 + (lane >> 2) + half * 8;
                float v0 = acc[mi][ni][half*2+0] + b0;
                float v1 = acc[mi][ni][half*2+1] + b1;
                if (EPI == 0) {
                    size_t voff = (size_t)qidx[r] * 256 + col;
                    v0 += add_src[voff];
                    v1 += add_src[voff + 1];
                    *(float2*)(outf + (size_t)r * 256 + col) = make_float2(v0, v1);
                } else if (EPI == 1) {
                    v0 = fmaxf(v0, 0.0f);
                    v1 = fmaxf(v1, 0.0f);
                    *(__half2*)(outh + (size_t)r * opitch + col) = __floats2half2_rn(v0, v1);
                } else if (EPI == 2) {
                    size_t aoff = (size_t)r * 256 + col;
                    v0 += add_src[aoff];
                    v1 += add_src[aoff + 1];
                    *(float2*)(outf + aoff) = make_float2(v0, v1);
                } else {
                    *(float2*)(outf + (size_t)r * 256 + col) = make_float2(v0, v1);
                }
            }
        }
    }
}

// ---------------- kernel 4: attention per query (fp16 k/v staging) ----------------
#define KPITCH 264   // halfs per row (528B)
__global__ __launch_bounds__(256)
void attn_kernel(const int* __restrict__ gidx, const int* __restrict__ gmask,
                 const int* __restrict__ rel_x, const int* __restrict__ rel_y,
                 const int* __restrict__ rel_z,
                 const float* __restrict__ pkx, const float* __restrict__ pky,
                 const float* __restrict__ pkz) {
    extern __shared__ __half sm4h[];
    __half* k_s = sm4h;                   // 32 x KPITCH halfs
    __half* v_s = sm4h + 32 * KPITCH;
    __shared__ float q_s[256];
    __shared__ float qp_s[296];
    __shared__ float attn_s[HH][KNN];
    __shared__ int idx_s[32], msk_s[32], rx_s[32], ry_s[32], rz_s[32];
    int n = blockIdx.x, t = threadIdx.x;
    if (t < 32) {
        idx_s[t] = gidx[n*KNN + t];
        msk_s[t] = gmask[n*KNN + t];
        rx_s[t]  = rel_x[n*KNN + t];
        ry_s[t]  = rel_y[n*KNN + t];
        rz_s[t]  = rel_z[n*KNN + t];
    } else if (t < 96) {
        int i = t - 32;
        ((float4*)q_s)[i] = ((const float4*)(g_q + (size_t)n * C))[i];
    } else if (t < 170) {
        int i = t - 96;
        ((float4*)qp_s)[i] = ((const float4*)(g_qp + (size_t)n * 296))[i];
    }
    __syncthreads();
#pragma unroll
    for (int i = 0; i < 4; i++) {
        int u = t + i * 256;
        int row = u >> 5, seg = u & 31;
        bool m = (msk_s[row] != 0);
        const uint4* ks = m ? (const uint4*)(g_bkvh)
                            : (const uint4*)(g_kall + (size_t)idx_s[row] * C);
        const uint4* vs = m ? (const uint4*)(g_bkvh + 256)
                            : (const uint4*)(g_vall + (size_t)idx_s[row] * C);
        *(uint4*)(k_s + row * KPITCH + seg * 8) = __ldg(&ks[seg]);
        *(uint4*)(v_s + row * KPITCH + seg * 8) = __ldg(&vs[seg]);
    }
    __syncthreads();

    int h = t >> 5, lane = t & 31;
    {
        int rx = rx_s[lane], ry = ry_s[lane], rz = rz_s[lane];
        bool msk = (msk_s[lane] != 0);
        const __half2* krow = (const __half2*)(k_s + lane * KPITCH + h * DHD);
        const float* qh   = q_s + h * DHD;
        const float* pbx = pkx + h * DHD * 15 + rx;
        const float* pby = pky + h * DHD * 15 + ry;
        const float* pbz = pkz + h * DHD * 7  + rz;
        float qk = 0.0f, bias = 0.0f;
#pragma unroll
        for (int d2 = 0; d2 < DHD / 2; d2++) {
            float2 kv = __half22float2(krow[d2]);
            qk = fmaf(qh[d2*2+0], kv.x, qk);
            qk = fmaf(qh[d2*2+1], kv.y, qk);
            float pw0 = __ldg(pbx + (d2*2+0) * 15) + __ldg(pby + (d2*2+0) * 15) + __ldg(pbz + (d2*2+0) * 7);
            float pw1 = __ldg(pbx + (d2*2+1) * 15) + __ldg(pby + (d2*2+1) * 15) + __ldg(pbz + (d2*2+1) * 7);
            bias = fmaf(kv.x, pw0, bias);
            bias = fmaf(kv.y, pw1, bias);
        }
        const float* qpn = qp_s + h * 37;
        float logit = qk * 0.17677669529663687f + qpn[rx] + qpn[15 + ry] + qpn[30 + rz] + bias;
        if (msk) logit = -1e9f;
        float m = logit;
#pragma unroll
        for (int o = 16; o > 0; o >>= 1) m = fmaxf(m, __shfl_xor_sync(0xffffffffu, m, o));
        float p = expf(logit - m);
        float s = p;
#pragma unroll
        for (int o = 16; o > 0; o >>= 1) s += __shfl_xor_sync(0xffffffffu, s, o);
        attn_s[h][lane] = p / s;
    }
    __syncwarp();
    {
        float o = 0.0f;
        const __half* vcol = v_s + h * DHD + lane;
        const float* aw = attn_s[h];
#pragma unroll
        for (int kk = 0; kk < KNN; kk++)
            o = fmaf(aw[kk], __half2float(vcol[kk * KPITCH]), o);
        g_ao[(size_t)n * C + h * DHD + lane] = __float2half(o);
    }
}

// ---------------- kernel: LN2 over ACT -> fp16 ----------------
__global__ void ln2_kernel(const float* __restrict__ g, const float* __restrict__ b) {
    int row = blockIdx.x * 8 + (threadIdx.x >> 5);
    int lane = threadIdx.x & 31;
    const float4* xr = (const float4*)(g_act + (size_t)row * C);
    float4 v0 = xr[lane];
    float4 v1 = xr[lane + 32];
    float s = v0.x + v0.y + v0.z + v0.w + v1.x + v1.y + v1.z + v1.w;
    float q = v0.x*v0.x + v0.y*v0.y + v0.z*v0.z + v0.w*v0.w
            + v1.x*v1.x + v1.y*v1.y + v1.z*v1.z + v1.w*v1.w;
#pragma unroll
    for (int o = 16; o > 0; o >>= 1) {
        s += __shfl_xor_sync(0xffffffffu, s, o);
        q += __shfl_xor_sync(0xffffffffu, q, o);
    }
    float mu = s * (1.0f / C);
    float rs = rsqrtf(q * (1.0f / C) - mu * mu + 1e-5f);
    int c0 = lane * 4, c1 = 128 + lane * 4;
    __half2* hrow = (__half2*)(g_x + (size_t)row * C);
    hrow[lane*2+0]  = __floats2half2_rn((v0.x - mu) * rs * g[c0+0] + b[c0+0],
                                        (v0.y - mu) * rs * g[c0+1] + b[c0+1]);
    hrow[lane*2+1]  = __floats2half2_rn((v0.z - mu) * rs * g[c0+2] + b[c0+2],
                                        (v0.w - mu) * rs * g[c0+3] + b[c0+3]);
    hrow[64+lane*2] = __floats2half2_rn((v1.x - mu) * rs * g[c1+0] + b[c1+0],
                                        (v1.y - mu) * rs * g[c1+1] + b[c1+1]);
    hrow[65+lane*2] = __floats2half2_rn((v1.z - mu) * rs * g[c1+2] + b[c1+2],
                                        (v1.w - mu) * rs * g[c1+3] + b[c1+3]);
}

// ---------------- launch ----------------
extern "C" void kernel_launch(void* const* d_in, const int* in_sizes, int n_in,
                              void* d_out, int out_size) {
    const float* voxel  = (const float*)d_in[0];
    const float* coords = (const float*)d_in[1];
    const int*   qidx   = (const int*)d_in[2];
    const int*   gidx   = (const int*)d_in[3];
    const int*   gmask  = (const int*)d_in[4];
    const int*   rel_x  = (const int*)d_in[5];
    const int*   rel_y  = (const int*)d_in[6];
    const int*   rel_z  = (const int*)d_in[7];
    const float* w_pos  = (const float*)d_in[8];
    const float* b_pos  = (const float*)d_in[9];
    const float* w_q    = (const float*)d_in[10];
    const float* b_q    = (const float*)d_in[11];
    const float* w_k    = (const float*)d_in[12];
    const float* b_k    = (const float*)d_in[13];
    const float* w_v    = (const float*)d_in[14];
    const float* b_v    = (const float*)d_in[15];
    const float* w_proj = (const float*)d_in[16];
    const float* b_proj = (const float*)d_in[17];
    const float* ln1g   = (const float*)d_in[18];
    const float* ln1b   = (const float*)d_in[19];
    const float* ln2g   = (const float*)d_in[20];
    const float* ln2b   = (const float*)d_in[21];
    const float* w_ff1  = (const float*)d_in[22];
    const float* b_ff1  = (const float*)d_in[23];
    const float* w_ff2  = (const float*)d_in[24];
    const float* b_ff2  = (const float*)d_in[25];
    const float* pqx    = (const float*)d_in[26];
    const float* pqy    = (const float*)d_in[27];
    const float* pqz    = (const float*)d_in[28];
    const float* pkx    = (const float*)d_in[29];
    const float* pky    = (const float*)d_in[30];
    const float* pkz    = (const float*)d_in[31];
    float* out = (float*)d_out;

    int attn_smem = 2 * 32 * KPITCH * 2;   // two half matrices

    cudaFuncSetAttribute(kvgemm_kernel,     cudaFuncAttributeMaxDynamicSharedMemorySize, 2 * STAGE_BYTES);
    cudaFuncSetAttribute(mmagemm_kernel<0>, cudaFuncAttributeMaxDynamicSharedMemorySize, 2 * STAGE64);
    cudaFuncSetAttribute(mmagemm_kernel<1>, cudaFuncAttributeMaxDynamicSharedMemorySize, 2 * STAGE64);
    cudaFuncSetAttribute(mmagemm_kernel<2>, cudaFuncAttributeMaxDynamicSharedMemorySize, 2 * STAGE64);
    cudaFuncSetAttribute(mmagemm_kernel<3>, cudaFuncAttributeMaxDynamicSharedMemorySize, 2 * STAGE64);
    cudaFuncSetAttribute(attn_kernel,       cudaFuncAttributeMaxDynamicSharedMemorySize, attn_smem);

    __half *Bh, *Bl, *Wqh, *Wql, *Wph, *Wpl, *W1h, *W1l, *W2h, *W2l;
    __half *qin, *ao, *xh, *fh;
    float *act, *qv;
    cudaGetSymbolAddress((void**)&Bh, g_Bh);   cudaGetSymbolAddress((void**)&Bl, g_Bl);
    cudaGetSymbolAddress((void**)&Wqh, g_Wqh); cudaGetSymbolAddress((void**)&Wql, g_Wql);
    cudaGetSymbolAddress((void**)&Wph, g_Wph); cudaGetSymbolAddress((void**)&Wpl, g_Wpl);
    cudaGetSymbolAddress((void**)&W1h, g_W1h); cudaGetSymbolAddress((void**)&W1l, g_W1l);
    cudaGetSymbolAddress((void**)&W2h, g_W2h); cudaGetSymbolAddress((void**)&W2l, g_W2l);
    cudaGetSymbolAddress((void**)&qin, g_qin); cudaGetSymbolAddress((void**)&ao, g_ao);
    cudaGetSymbolAddress((void**)&xh, g_x);    cudaGetSymbolAddress((void**)&fh, g_f);
    cudaGetSymbolAddress((void**)&act, g_act); cudaGetSymbolAddress((void**)&qv, g_q);

    prep_kernel<<<2048, 256>>>(w_k, w_v, b_k, b_v, w_q, w_proj, w_ff1, w_ff2);
    ln_kernel<<<M_VOX / 16, 256>>>(voxel, ln1g, ln1b);
    qin_kernel<<<NQ, 256>>>(coords, qidx, w_pos, b_pos);
    // q = qin @ w_q + b_q
    mmagemm_kernel<3><<<dim3(2, NQ / 64), 256, 2 * STAGE64>>>(
        qin, 256, Wqh, Wql, b_q, nullptr, nullptr, qv, nullptr, 0);
    qp_kernel<<<NQ / 32, 256>>>(pqx, pqy, pqz);
    kvgemm_kernel<<<dim3(4, (M_VOX + 127) / 128), 256, 2 * STAGE_BYTES>>>(b_k, b_v);
    attn_kernel<<<NQ, 256, attn_smem>>>(gidx, gmask, rel_x, rel_y, rel_z,
                                        pkx, pky, pkz);
    // proj: ACT = ao @ w_proj + b_proj + voxel[qidx]
    mmagemm_kernel<0><<<dim3(2, NQ / 64), 256, 2 * STAGE64>>>(
        ao, 256, Wph, Wpl, b_proj, voxel, qidx, act, nullptr, 0);
    ln2_kernel<<<NQ / 8, 256>>>(ln2g, ln2b);
    // ff1: F = relu(X @ w_ff1 + b_ff1)
    mmagemm_kernel<1><<<dim3(4, NQ / 64), 256, 2 * STAGE64>>>(
        xh, 256, W1h, W1l, b_ff1, nullptr, nullptr, nullptr, fh, 512);
    // ff2: out = ACT + F @ w_ff2 + b_ff2
    mmagemm_kernel<2><<<dim3(2, NQ / 64), 256, 2 * STAGE64>>>(
        fh, 512, W2h, W2l, b_ff2, act, nullptr, out, nullptr, 0);
}

// round 11
// speedup vs baseline: 5.7643x; 1.2025x over previous
#include <cuda_runtime.h>
#include <cuda_fp16.h>
#include <cstdint>

#define M_VOX 100000
#define NQ    8192
#define KNN   32
#define C     256
#define HH    8
#define DHD   32
#define FF    512

// ---------------- scratch (device globals; no allocations allowed) ----------------
__device__ __half g_lnh[(size_t)M_VOX * C];      // fp16 LN(voxel_features)
__device__ __half g_kall[(size_t)M_VOX * C];     // k projection of ALL voxels (fp16)
__device__ __half g_vall[(size_t)M_VOX * C];     // v projection of ALL voxels (fp16)
__device__ __half g_bkvh[512];                   // fp16 [b_k | b_v] (masked-row content)
__device__ __half g_qin[(size_t)NQ * C];         // q-input fp16
__device__ float g_q [(size_t)NQ * C];           // q projections fp32
__device__ float g_qp[(size_t)NQ * HH * 37];     // q-side pos bias
__device__ __half g_ao[(size_t)NQ * C];          // attention out fp16
__device__ float g_act[(size_t)NQ * C];          // ACT = voxel[qidx] + proj(ao)
__device__ __half g_x[(size_t)NQ * C];           // LN2(ACT) fp16
__device__ __half g_f[(size_t)NQ * FF];          // relu(ff1) fp16
// weights transposed + fp16(-split), layout [n][k]
__device__ __half g_Bh[512 * 256];               // [wk|wv] single fp16 (no lo term)
__device__ __half g_Wqh[256 * 256];              // w_q single fp16
__device__ __half g_Wph[256 * 256];
__device__ __half g_Wpl[256 * 256];
__device__ __half g_W1h[512 * 256];
__device__ __half g_W1l[512 * 256];
__device__ __half g_W2h[256 * 512];
__device__ __half g_W2l[256 * 512];

// ---------------- helpers ----------------
__device__ __forceinline__ uint32_t smem_u32(const void* p) {
    uint32_t a;
    asm("{ .reg .u64 t; cvta.to.shared.u64 t, %1; cvt.u32.u64 %0, t; }" : "=r"(a) : "l"(p));
    return a;
}
__device__ __forceinline__ void cpasync16(uint32_t dst, const void* src) {
    asm volatile("cp.async.cg.shared.global [%0], [%1], 16;" :: "r"(dst), "l"(src));
}
#define CP_COMMIT()  asm volatile("cp.async.commit_group;" ::: "memory")
#define CP_WAIT(n)   asm volatile("cp.async.wait_group %0;" :: "n"(n) : "memory")

__device__ __forceinline__ void ldsm4(uint32_t* r, uint32_t addr) {
    asm volatile("ldmatrix.sync.aligned.m8n8.x4.shared.b16 {%0,%1,%2,%3}, [%4];"
        : "=r"(r[0]), "=r"(r[1]), "=r"(r[2]), "=r"(r[3]) : "r"(addr));
}
__device__ __forceinline__ void mma16816(float* c, const uint32_t* a, const uint32_t* b) {
    asm volatile(
        "mma.sync.aligned.m16n8k16.row.col.f32.f16.f16.f32 "
        "{%0,%1,%2,%3}, {%4,%5,%6,%7}, {%8,%9}, {%0,%1,%2,%3};"
        : "+f"(c[0]), "+f"(c[1]), "+f"(c[2]), "+f"(c[3])
        : "r"(a[0]), "r"(a[1]), "r"(a[2]), "r"(a[3]), "r"(b[0]), "r"(b[1]));
}

// ---------------- fused weight prep ----------------
// blocks [0,512): [wk|wv] -> g_Bh (fp16 only) + bias rows
// [512,768): w_q (fp16 only)   [768,1024): w_proj (split)
// [1024,1536): w_ff1 (split)   [1536,2048): w_ff2 (split)
__global__ void prep_kernel(const float* __restrict__ wk, const float* __restrict__ wv,
                            const float* __restrict__ bk, const float* __restrict__ bv,
                            const float* __restrict__ wq, const float* __restrict__ wp,
                            const float* __restrict__ w1, const float* __restrict__ w2) {
    int b = blockIdx.x, t = threadIdx.x;
    if (b < 512) {
        int idx = b * 256 + t;
        int n = idx >> 8, k = idx & 255;
        float val = (n < 256) ? wk[k * 256 + n] : wv[k * 256 + (n - 256)];
        g_Bh[idx] = __float2half(val);
        if (idx < 512)
            g_bkvh[idx] = __float2half((idx < 256) ? bk[idx] : bv[idx - 256]);
        return;
    }
    if (b < 768) {
        int idx = (b - 512) * 256 + t;
        int n = idx >> 8, k = idx & 255;
        g_Wqh[idx] = __float2half(wq[k * 256 + n]);
        return;
    }
    const float* src; __half* dh; __half* dl; int N, K, idx;
    if (b < 1024)      { src = wp; dh = g_Wph; dl = g_Wpl; N = 256; K = 256; idx = (b - 768) * 256 + t; }
    else if (b < 1536) { src = w1; dh = g_W1h; dl = g_W1l; N = 512; K = 256; idx = (b - 1024) * 256 + t; }
    else               { src = w2; dh = g_W2h; dl = g_W2l; N = 256; K = 512; idx = (b - 1536) * 256 + t; }
    int n = idx / K, k = idx - n * K;
    float val = src[k * N + n];
    __half h = __float2half(val);
    dh[idx] = h;
    dl[idx] = __float2half(val - __half2float(h));
}

// ---------------- kernel 1: LayerNorm over all M voxels -> fp16 (2 rows/warp) -----
__global__ void ln_kernel(const float* __restrict__ x,
                          const float* __restrict__ g,
                          const float* __restrict__ b) {
    int wid = threadIdx.x >> 5, lane = threadIdx.x & 31;
    int r0 = blockIdx.x * 16 + wid * 2;
    const float4* xr0 = (const float4*)(x + (size_t)r0 * C);
    const float4* xr1 = (const float4*)(x + (size_t)(r0 + 1) * C);
    float4 a0 = xr0[lane], a1 = xr0[lane + 32];
    float4 c0 = xr1[lane], c1 = xr1[lane + 32];
    float sA = a0.x + a0.y + a0.z + a0.w + a1.x + a1.y + a1.z + a1.w;
    float qA = a0.x*a0.x + a0.y*a0.y + a0.z*a0.z + a0.w*a0.w
             + a1.x*a1.x + a1.y*a1.y + a1.z*a1.z + a1.w*a1.w;
    float sB = c0.x + c0.y + c0.z + c0.w + c1.x + c1.y + c1.z + c1.w;
    float qB = c0.x*c0.x + c0.y*c0.y + c0.z*c0.z + c0.w*c0.w
             + c1.x*c1.x + c1.y*c1.y + c1.z*c1.z + c1.w*c1.w;
#pragma unroll
    for (int o = 16; o > 0; o >>= 1) {
        sA += __shfl_xor_sync(0xffffffffu, sA, o);
        qA += __shfl_xor_sync(0xffffffffu, qA, o);
        sB += __shfl_xor_sync(0xffffffffu, sB, o);
        qB += __shfl_xor_sync(0xffffffffu, qB, o);
    }
    float muA = sA * (1.0f / C);
    float rsA = rsqrtf(qA * (1.0f / C) - muA * muA + 1e-5f);
    float muB = sB * (1.0f / C);
    float rsB = rsqrtf(qB * (1.0f / C) - muB * muB + 1e-5f);
    int cc0 = lane * 4, cc1 = 128 + lane * 4;
    float g0 = g[cc0+0], g1 = g[cc0+1], g2 = g[cc0+2], g3 = g[cc0+3];
    float g4 = g[cc1+0], g5 = g[cc1+1], g6 = g[cc1+2], g7 = g[cc1+3];
    float b0 = b[cc0+0], b1 = b[cc0+1], b2 = b[cc0+2], b3 = b[cc0+3];
    float b4 = b[cc1+0], b5 = b[cc1+1], b6 = b[cc1+2], b7 = b[cc1+3];
    __half2* h0 = (__half2*)(g_lnh + (size_t)r0 * C);
    __half2* h1 = (__half2*)(g_lnh + (size_t)(r0 + 1) * C);
    h0[lane*2+0]  = __floats2half2_rn((a0.x - muA)*rsA*g0 + b0, (a0.y - muA)*rsA*g1 + b1);
    h0[lane*2+1]  = __floats2half2_rn((a0.z - muA)*rsA*g2 + b2, (a0.w - muA)*rsA*g3 + b3);
    h0[64+lane*2] = __floats2half2_rn((a1.x - muA)*rsA*g4 + b4, (a1.y - muA)*rsA*g5 + b5);
    h0[65+lane*2] = __floats2half2_rn((a1.z - muA)*rsA*g6 + b6, (a1.w - muA)*rsA*g7 + b7);
    h1[lane*2+0]  = __floats2half2_rn((c0.x - muB)*rsB*g0 + b0, (c0.y - muB)*rsB*g1 + b1);
    h1[lane*2+1]  = __floats2half2_rn((c0.z - muB)*rsB*g2 + b2, (c0.w - muB)*rsB*g3 + b3);
    h1[64+lane*2] = __floats2half2_rn((c1.x - muB)*rsB*g4 + b4, (c1.y - muB)*rsB*g5 + b5);
    h1[65+lane*2] = __floats2half2_rn((c1.z - muB)*rsB*g6 + b6, (c1.w - muB)*rsB*g7 + b7);
}

// ---------------- kernel: qin = ln[qidx] + relu(coords @ w_pos + b_pos) ---------
__global__ void qin_kernel(const float* __restrict__ coords, const int* __restrict__ qidx,
                           const float* __restrict__ w_pos, const float* __restrict__ b_pos) {
    int n = blockIdx.x, t = threadIdx.x;
    float cx = coords[n*3+0], cy = coords[n*3+1], cz = coords[n*3+2];
    float p = cx * w_pos[t] + cy * w_pos[C + t] + cz * w_pos[2*C + t] + b_pos[t];
    p = fmaxf(p, 0.0f);
    float lnv = __half2float(g_lnh[(size_t)qidx[n] * C + t]);
    g_qin[(size_t)n * C + t] = __float2half(lnv + p);
}

// ---------------- kernel: q-side positional bias (reads g_q) ----------------
__global__ void qp_kernel(const float* __restrict__ pqx, const float* __restrict__ pqy,
                          const float* __restrict__ pqz) {
    __shared__ float qs[32 * C];
    int t = threadIdx.x;
    int n0 = blockIdx.x * 32;
    for (int i = t; i < 32 * C; i += 256) qs[i] = g_q[(size_t)n0 * C + i];
    __syncthreads();
    for (int idx = t; idx < 32 * HH * 37; idx += 256) {
        int r   = idx / (HH * 37);
        int rem = idx - r * (HH * 37);
        int h   = rem / 37;
        int j   = rem - h * 37;
        const float* tab; int rr, stride;
        if (j < 15)      { tab = pqx + h * DHD * 15; rr = j;      stride = 15; }
        else if (j < 30) { tab = pqy + h * DHD * 15; rr = j - 15; stride = 15; }
        else             { tab = pqz + h * DHD * 7;  rr = j - 30; stride = 7;  }
        float s = 0.0f;
        const float* qrow = qs + r*C + h*DHD;
#pragma unroll
        for (int d = 0; d < DHD; d++) s = fmaf(qrow[d], __ldg(&tab[d*stride + rr]), s);
        g_qp[((size_t)(n0 + r)*HH + h)*37 + j] = s;
    }
}

// ---------------- MMA tile configs ----------------
#define APITCH 40
#define MAT_BYTES (128 * APITCH * 2)        // 10240
// kvgemm (single-fp16 B): A + Bh per stage
#define KVSTAGE (2 * MAT_BYTES)             // 20480; 2 stages = 40960
// NQ gemms: 64-row A tile
#define MATA64 (64 * APITCH * 2)            // 5120

// ---------------- kernel 3: K/V projection GEMM (single-fp16 B) -> fp16 out -------
__global__ __launch_bounds__(256, 2)
void kvgemm_kernel(const float* __restrict__ bk, const float* __restrict__ bv) {
    extern __shared__ __align__(16) char gsm[];
    uint32_t sb = smem_u32(gsm);
    int t = threadIdx.x;
    int warp = t >> 5, lane = t & 31;
    int n0 = blockIdx.x * 128;
    int m0 = blockIdx.y * 128;

    auto load_chunk = [&](int kc, int buf) {
        uint32_t base = sb + buf * KVSTAGE;
#pragma unroll
        for (int i = 0; i < 2; i++) {
            int u = t + i * 256;
            int row = u >> 2, seg = u & 3;
            int gr = m0 + row; if (gr >= M_VOX) gr = 0;
            size_t go = (size_t)gr * 256 + kc * 32 + seg * 8;
            cpasync16(base + (row * APITCH + seg * 8) * 2, g_lnh + go);
            size_t gb = (size_t)(n0 + row) * 256 + kc * 32 + seg * 8;
            cpasync16(base + MAT_BYTES + (row * APITCH + seg * 8) * 2, g_Bh + gb);
        }
    };

    int wm = warp & 1, wn = warp >> 1;
    float acc[4][4][4];
#pragma unroll
    for (int a = 0; a < 4; a++)
#pragma unroll
        for (int bq = 0; bq < 4; bq++)
#pragma unroll
            for (int cq = 0; cq < 4; cq++) acc[a][bq][cq] = 0.0f;

    load_chunk(0, 0); CP_COMMIT();

    for (int kc = 0; kc < 8; kc++) {
        int buf = kc & 1;
        if (kc < 7) { load_chunk(kc + 1, buf ^ 1); CP_COMMIT(); CP_WAIT(1); }
        else        { CP_WAIT(0); }
        __syncthreads();

        uint32_t abase = sb + buf * KVSTAGE;
        uint32_t bbase = abase + MAT_BYTES;
        uint32_t bh[4][4];
#pragma unroll
        for (int ni = 0; ni < 4; ni++) {
            int nrow = wn * 32 + ni * 8 + (lane & 7);
            int koff = (lane >> 3) * 8;
            ldsm4(bh[ni], bbase + (nrow * APITCH + koff) * 2);
        }
#pragma unroll
        for (int s = 0; s < 2; s++) {
#pragma unroll
            for (int mi = 0; mi < 4; mi++) {
                int arow = wm * 64 + mi * 16 + (lane & 15);
                int koff = s * 16 + (lane >> 4) * 8;
                uint32_t ah[4];
                ldsm4(ah, abase + (arow * APITCH + koff) * 2);
#pragma unroll
                for (int ni = 0; ni < 4; ni++)
                    mma16816(acc[mi][ni], ah, &bh[ni][s*2]);
            }
        }
        __syncthreads();
    }

    __half* dst = (n0 < 256) ? g_kall : g_vall;
    const float* bias = (n0 < 256) ? bk : bv;
    int cb = n0 & 255;
#pragma unroll
    for (int mi = 0; mi < 4; mi++) {
#pragma unroll
        for (int ni = 0; ni < 4; ni++) {
            int col = cb + wn * 32 + ni * 8 + (lane & 3) * 2;
            float b0 = bias[col], b1 = bias[col + 1];
            int r0 = m0 + wm * 64 + mi * 16 + (lane >> 2);
            if (r0 < M_VOX)
                *(__half2*)(dst + (size_t)r0 * 256 + col) =
                    __floats2half2_rn(acc[mi][ni][0] + b0, acc[mi][ni][1] + b1);
            int r1 = r0 + 8;
            if (r1 < M_VOX)
                *(__half2*)(dst + (size_t)r1 * 256 + col) =
                    __floats2half2_rn(acc[mi][ni][2] + b0, acc[mi][ni][3] + b1);
        }
    }
}

// ---------------- generic fp16 MMA GEMM, 64-row tiles, fused epilogues ------------
// SPLIT: 2-term B (hi+lo) vs single-fp16 B
// EPI 0: outf = acc + bias + add_src[qidx[row]]   (proj -> g_act)
// EPI 1: relu(acc + bias) -> fp16 outh            (ff1), pitch opitch
// EPI 2: outf = acc + bias + add_src[row]         (ff2 -> d_out)
// EPI 3: outf = acc + bias                        (q -> g_q)
template<int EPI, bool SPLIT>
__global__ __launch_bounds__(256, 2)
void mmagemm_kernel(const __half* __restrict__ Ah, int K,
                    const __half* __restrict__ Bh, const __half* __restrict__ Bl,
                    const float* __restrict__ bias,
                    const float* __restrict__ add_src, const int* __restrict__ qidx,
                    float* __restrict__ outf, __half* __restrict__ outh, int opitch) {
    constexpr int BBYTES = SPLIT ? 2 * MAT_BYTES : MAT_BYTES;
    constexpr int STAGE  = MATA64 + BBYTES;
    extern __shared__ __align__(16) char gsm[];
    uint32_t sb = smem_u32(gsm);
    int t = threadIdx.x;
    int warp = t >> 5, lane = t & 31;
    int n0 = blockIdx.x * 128;
    int m0 = blockIdx.y * 64;

    auto load_chunk = [&](int kc, int buf) {
        uint32_t base = sb + buf * STAGE;
        {
            int row = t >> 2, seg = t & 3;
            size_t go = (size_t)(m0 + row) * K + kc * 32 + seg * 8;
            cpasync16(base + (row * APITCH + seg * 8) * 2, Ah + go);
        }
#pragma unroll
        for (int i = 0; i < 2; i++) {
            int u = t + i * 256;
            int row = u >> 2, seg = u & 3;
            size_t gb = (size_t)(n0 + row) * K + kc * 32 + seg * 8;
            uint32_t sob = base + MATA64 + (row * APITCH + seg * 8) * 2;
            cpasync16(sob, Bh + gb);
            if (SPLIT) cpasync16(sob + MAT_BYTES, Bl + gb);
        }
    };

    int wm = warp & 1, wn = warp >> 1;
    float acc[2][4][4];
#pragma unroll
    for (int a = 0; a < 2; a++)
#pragma unroll
        for (int bq = 0; bq < 4; bq++)
#pragma unroll
            for (int cq = 0; cq < 4; cq++) acc[a][bq][cq] = 0.0f;

    int nchunks = K >> 5;
    load_chunk(0, 0); CP_COMMIT();

    for (int kc = 0; kc < nchunks; kc++) {
        int buf = kc & 1;
        if (kc < nchunks - 1) { load_chunk(kc + 1, buf ^ 1); CP_COMMIT(); CP_WAIT(1); }
        else                  { CP_WAIT(0); }
        __syncthreads();

        uint32_t abase = sb + buf * STAGE;
        uint32_t bbase = abase + MATA64;
        uint32_t bh[4][4], bl[4][4];
#pragma unroll
        for (int ni = 0; ni < 4; ni++) {
            int nrow = wn * 32 + ni * 8 + (lane & 7);
            int koff = (lane >> 3) * 8;
            uint32_t ad = bbase + (nrow * APITCH + koff) * 2;
            ldsm4(bh[ni], ad);
            if (SPLIT) ldsm4(bl[ni], ad + MAT_BYTES);
        }
#pragma unroll
        for (int s = 0; s < 2; s++) {
#pragma unroll
            for (int mi = 0; mi < 2; mi++) {
                int arow = wm * 32 + mi * 16 + (lane & 15);
                int koff = s * 16 + (lane >> 4) * 8;
                uint32_t ah[4];
                ldsm4(ah, abase + (arow * APITCH + koff) * 2);
#pragma unroll
                for (int ni = 0; ni < 4; ni++) {
                    mma16816(acc[mi][ni], ah, &bh[ni][s*2]);
                    if (SPLIT) mma16816(acc[mi][ni], ah, &bl[ni][s*2]);
                }
            }
        }
        __syncthreads();
    }

#pragma unroll
    for (int mi = 0; mi < 2; mi++) {
#pragma unroll
        for (int ni = 0; ni < 4; ni++) {
            int col = n0 + wn * 32 + ni * 8 + (lane & 3) * 2;
            float b0 = bias[col], b1 = bias[col + 1];
#pragma unroll
            for (int half = 0; half < 2; half++) {
                int r = m0 + wm * 32 + mi * 16 + (lane >> 2) + half * 8;
                float v0 = acc[mi][ni][half*2+0] + b0;
                float v1 = acc[mi][ni][half*2+1] + b1;
                if (EPI == 0) {
                    size_t voff = (size_t)qidx[r] * 256 + col;
                    v0 += add_src[voff];
                    v1 += add_src[voff + 1];
                    *(float2*)(outf + (size_t)r * 256 + col) = make_float2(v0, v1);
                } else if (EPI == 1) {
                    v0 = fmaxf(v0, 0.0f);
                    v1 = fmaxf(v1, 0.0f);
                    *(__half2*)(outh + (size_t)r * opitch + col) = __floats2half2_rn(v0, v1);
                } else if (EPI == 2) {
                    size_t aoff = (size_t)r * 256 + col;
                    v0 += add_src[aoff];
                    v1 += add_src[aoff + 1];
                    *(float2*)(outf + aoff) = make_float2(v0, v1);
                } else {
                    *(float2*)(outf + (size_t)r * 256 + col) = make_float2(v0, v1);
                }
            }
        }
    }
}

// ---------------- kernel 4: attention per query (fp16 k/v staging) ----------------
#define KPITCH 264   // halfs per row (528B)
__global__ __launch_bounds__(256)
void attn_kernel(const int* __restrict__ gidx, const int* __restrict__ gmask,
                 const int* __restrict__ rel_x, const int* __restrict__ rel_y,
                 const int* __restrict__ rel_z,
                 const float* __restrict__ pkx, const float* __restrict__ pky,
                 const float* __restrict__ pkz) {
    extern __shared__ __half sm4h[];
    __half* k_s = sm4h;                   // 32 x KPITCH halfs
    __half* v_s = sm4h + 32 * KPITCH;
    __shared__ float q_s[256];
    __shared__ float qp_s[296];
    __shared__ float attn_s[HH][KNN];
    __shared__ int idx_s[32], msk_s[32], rx_s[32], ry_s[32], rz_s[32];
    int n = blockIdx.x, t = threadIdx.x;
    if (t < 32) {
        idx_s[t] = gidx[n*KNN + t];
        msk_s[t] = gmask[n*KNN + t];
        rx_s[t]  = rel_x[n*KNN + t];
        ry_s[t]  = rel_y[n*KNN + t];
        rz_s[t]  = rel_z[n*KNN + t];
    } else if (t < 96) {
        int i = t - 32;
        ((float4*)q_s)[i] = ((const float4*)(g_q + (size_t)n * C))[i];
    } else if (t < 170) {
        int i = t - 96;
        ((float4*)qp_s)[i] = ((const float4*)(g_qp + (size_t)n * 296))[i];
    }
    __syncthreads();
#pragma unroll
    for (int i = 0; i < 4; i++) {
        int u = t + i * 256;
        int row = u >> 5, seg = u & 31;
        bool m = (msk_s[row] != 0);
        const uint4* ks = m ? (const uint4*)(g_bkvh)
                            : (const uint4*)(g_kall + (size_t)idx_s[row] * C);
        const uint4* vs = m ? (const uint4*)(g_bkvh + 256)
                            : (const uint4*)(g_vall + (size_t)idx_s[row] * C);
        *(uint4*)(k_s + row * KPITCH + seg * 8) = __ldg(&ks[seg]);
        *(uint4*)(v_s + row * KPITCH + seg * 8) = __ldg(&vs[seg]);
    }
    __syncthreads();

    int h = t >> 5, lane = t & 31;
    {
        int rx = rx_s[lane], ry = ry_s[lane], rz = rz_s[lane];
        bool msk = (msk_s[lane] != 0);
        const __half2* krow = (const __half2*)(k_s + lane * KPITCH + h * DHD);
        const float* qh   = q_s + h * DHD;
        const float* pbx = pkx + h * DHD * 15 + rx;
        const float* pby = pky + h * DHD * 15 + ry;
        const float* pbz = pkz + h * DHD * 7  + rz;
        float qk = 0.0f, bias = 0.0f;
#pragma unroll
        for (int d2 = 0; d2 < DHD / 2; d2++) {
            float2 kv = __half22float2(krow[d2]);
            qk = fmaf(qh[d2*2+0], kv.x, qk);
            qk = fmaf(qh[d2*2+1], kv.y, qk);
            float pw0 = __ldg(pbx + (d2*2+0) * 15) + __ldg(pby + (d2*2+0) * 15) + __ldg(pbz + (d2*2+0) * 7);
            float pw1 = __ldg(pbx + (d2*2+1) * 15) + __ldg(pby + (d2*2+1) * 15) + __ldg(pbz + (d2*2+1) * 7);
            bias = fmaf(kv.x, pw0, bias);
            bias = fmaf(kv.y, pw1, bias);
        }
        const float* qpn = qp_s + h * 37;
        float logit = qk * 0.17677669529663687f + qpn[rx] + qpn[15 + ry] + qpn[30 + rz] + bias;
        if (msk) logit = -1e9f;
        float m = logit;
#pragma unroll
        for (int o = 16; o > 0; o >>= 1) m = fmaxf(m, __shfl_xor_sync(0xffffffffu, m, o));
        float p = expf(logit - m);
        float s = p;
#pragma unroll
        for (int o = 16; o > 0; o >>= 1) s += __shfl_xor_sync(0xffffffffu, s, o);
        attn_s[h][lane] = p / s;
    }
    __syncwarp();
    {
        float o = 0.0f;
        const __half* vcol = v_s + h * DHD + lane;
        const float* aw = attn_s[h];
#pragma unroll
        for (int kk = 0; kk < KNN; kk++)
            o = fmaf(aw[kk], __half2float(vcol[kk * KPITCH]), o);
        g_ao[(size_t)n * C + h * DHD + lane] = __float2half(o);
    }
}

// ---------------- kernel: LN2 over ACT -> fp16 ----------------
__global__ void ln2_kernel(const float* __restrict__ g, const float* __restrict__ b) {
    int row = blockIdx.x * 8 + (threadIdx.x >> 5);
    int lane = threadIdx.x & 31;
    const float4* xr = (const float4*)(g_act + (size_t)row * C);
    float4 v0 = xr[lane];
    float4 v1 = xr[lane + 32];
    float s = v0.x + v0.y + v0.z + v0.w + v1.x + v1.y + v1.z + v1.w;
    float q = v0.x*v0.x + v0.y*v0.y + v0.z*v0.z + v0.w*v0.w
            + v1.x*v1.x + v1.y*v1.y + v1.z*v1.z + v1.w*v1.w;
#pragma unroll
    for (int o = 16; o > 0; o >>= 1) {
        s += __shfl_xor_sync(0xffffffffu, s, o);
        q += __shfl_xor_sync(0xffffffffu, q, o);
    }
    float mu = s * (1.0f / C);
    float rs = rsqrtf(q * (1.0f / C) - mu * mu + 1e-5f);
    int c0 = lane * 4, c1 = 128 + lane * 4;
    __half2* hrow = (__half2*)(g_x + (size_t)row * C);
    hrow[lane*2+0]  = __floats2half2_rn((v0.x - mu) * rs * g[c0+0] + b[c0+0],
                                        (v0.y - mu) * rs * g[c0+1] + b[c0+1]);
    hrow[lane*2+1]  = __floats2half2_rn((v0.z - mu) * rs * g[c0+2] + b[c0+2],
                                        (v0.w - mu) * rs * g[c0+3] + b[c0+3]);
    hrow[64+lane*2] = __floats2half2_rn((v1.x - mu) * rs * g[c1+0] + b[c1+0],
                                        (v1.y - mu) * rs * g[c1+1] + b[c1+1]);
    hrow[65+lane*2] = __floats2half2_rn((v1.z - mu) * rs * g[c1+2] + b[c1+2],
                                        (v1.w - mu) * rs * g[c1+3] + b[c1+3]);
}

// ---------------- launch ----------------
extern "C" void kernel_launch(void* const* d_in, const int* in_sizes, int n_in,
                              void* d_out, int out_size) {
    const float* voxel  = (const float*)d_in[0];
    const float* coords = (const float*)d_in[1];
    const int*   qidx   = (const int*)d_in[2];
    const int*   gidx   = (const int*)d_in[3];
    const int*   gmask  = (const int*)d_in[4];
    const int*   rel_x  = (const int*)d_in[5];
    const int*   rel_y  = (const int*)d_in[6];
    const int*   rel_z  = (const int*)d_in[7];
    const float* w_pos  = (const float*)d_in[8];
    const float* b_pos  = (const float*)d_in[9];
    const float* w_q    = (const float*)d_in[10];
    const float* b_q    = (const float*)d_in[11];
    const float* w_k    = (const float*)d_in[12];
    const float* b_k    = (const float*)d_in[13];
    const float* w_v    = (const float*)d_in[14];
    const float* b_v    = (const float*)d_in[15];
    const float* w_proj = (const float*)d_in[16];
    const float* b_proj = (const float*)d_in[17];
    const float* ln1g   = (const float*)d_in[18];
    const float* ln1b   = (const float*)d_in[19];
    const float* ln2g   = (const float*)d_in[20];
    const float* ln2b   = (const float*)d_in[21];
    const float* w_ff1  = (const float*)d_in[22];
    const float* b_ff1  = (const float*)d_in[23];
    const float* w_ff2  = (const float*)d_in[24];
    const float* b_ff2  = (const float*)d_in[25];
    const float* pqx    = (const float*)d_in[26];
    const float* pqy    = (const float*)d_in[27];
    const float* pqz    = (const float*)d_in[28];
    const float* pkx    = (const float*)d_in[29];
    const float* pky    = (const float*)d_in[30];
    const float* pkz    = (const float*)d_in[31];
    float* out = (float*)d_out;

    int attn_smem = 2 * 32 * KPITCH * 2;
    int stage_split  = 2 * (MATA64 + 2 * MAT_BYTES);   // 51200
    int stage_single = 2 * (MATA64 + MAT_BYTES);       // 30720

    cudaFuncSetAttribute(kvgemm_kernel,            cudaFuncAttributeMaxDynamicSharedMemorySize, 2 * KVSTAGE);
    cudaFuncSetAttribute(mmagemm_kernel<0, true>,  cudaFuncAttributeMaxDynamicSharedMemorySize, stage_split);
    cudaFuncSetAttribute(mmagemm_kernel<1, true>,  cudaFuncAttributeMaxDynamicSharedMemorySize, stage_split);
    cudaFuncSetAttribute(mmagemm_kernel<2, true>,  cudaFuncAttributeMaxDynamicSharedMemorySize, stage_split);
    cudaFuncSetAttribute(mmagemm_kernel<3, false>, cudaFuncAttributeMaxDynamicSharedMemorySize, stage_single);
    cudaFuncSetAttribute(attn_kernel,              cudaFuncAttributeMaxDynamicSharedMemorySize, attn_smem);

    __half *Wqh, *Wph, *Wpl, *W1h, *W1l, *W2h, *W2l;
    __half *qin, *ao, *xh, *fh;
    float *act, *qv;
    cudaGetSymbolAddress((void**)&Wqh, g_Wqh);
    cudaGetSymbolAddress((void**)&Wph, g_Wph); cudaGetSymbolAddress((void**)&Wpl, g_Wpl);
    cudaGetSymbolAddress((void**)&W1h, g_W1h); cudaGetSymbolAddress((void**)&W1l, g_W1l);
    cudaGetSymbolAddress((void**)&W2h, g_W2h); cudaGetSymbolAddress((void**)&W2l, g_W2l);
    cudaGetSymbolAddress((void**)&qin, g_qin); cudaGetSymbolAddress((void**)&ao, g_ao);
    cudaGetSymbolAddress((void**)&xh, g_x);    cudaGetSymbolAddress((void**)&fh, g_f);
    cudaGetSymbolAddress((void**)&act, g_act); cudaGetSymbolAddress((void**)&qv, g_q);

    prep_kernel<<<2048, 256>>>(w_k, w_v, b_k, b_v, w_q, w_proj, w_ff1, w_ff2);
    ln_kernel<<<M_VOX / 16, 256>>>(voxel, ln1g, ln1b);
    qin_kernel<<<NQ, 256>>>(coords, qidx, w_pos, b_pos);
    // q = qin @ w_q + b_q  (single-fp16 B)
    mmagemm_kernel<3, false><<<dim3(2, NQ / 64), 256, stage_single>>>(
        qin, 256, Wqh, nullptr, b_q, nullptr, nullptr, qv, nullptr, 0);
    qp_kernel<<<NQ / 32, 256>>>(pqx, pqy, pqz);
    kvgemm_kernel<<<dim3(4, (M_VOX + 127) / 128), 256, 2 * KVSTAGE>>>(b_k, b_v);
    attn_kernel<<<NQ, 256, attn_smem>>>(gidx, gmask, rel_x, rel_y, rel_z,
                                        pkx, pky, pkz);
    // proj: ACT = ao @ w_proj + b_proj + voxel[qidx]
    mmagemm_kernel<0, true><<<dim3(2, NQ / 64), 256, stage_split>>>(
        ao, 256, Wph, Wpl, b_proj, voxel, qidx, act, nullptr, 0);
    ln2_kernel<<<NQ / 8, 256>>>(ln2g, ln2b);
    // ff1: F = relu(X @ w_ff1 + b_ff1)
    mmagemm_kernel<1, true><<<dim3(4, NQ / 64), 256, stage_split>>>(
        xh, 256, W1h, W1l, b_ff1, nullptr, nullptr, nullptr, fh, 512);
    // ff2: out = ACT + F @ w_ff2 + b_ff2
    mmagemm_kernel<2, true><<<dim3(2, NQ / 64), 256, stage_split>>>(
        fh, 512, W2h, W2l, b_ff2, act, nullptr, out, nullptr, 0);
}

// round 14
// speedup vs baseline: 5.9321x; 1.0291x over previous
#include <cuda_runtime.h>
#include <cuda_fp16.h>
#include <cstdint>

#define M_VOX 100000
#define NQ    8192
#define KNN   32
#define C     256
#define HH    8
#define DHD   32
#define FF    512

// ---------------- scratch (device globals; no allocations allowed) ----------------
__device__ __half g_lnh[(size_t)M_VOX * C];      // fp16 LN(voxel_features)
__device__ __half g_kall[(size_t)M_VOX * C];     // k projection of ALL voxels (fp16)
__device__ __half g_vall[(size_t)M_VOX * C];     // v projection of ALL voxels (fp16)
__device__ __half g_bkvh[512];                   // fp16 [b_k | b_v] (masked-row content)
__device__ __half g_qin[(size_t)NQ * C];         // q-input fp16
__device__ float g_q [(size_t)NQ * C];           // q projections fp32
__device__ float g_qp[(size_t)NQ * HH * 37];     // q-side pos bias
__device__ __half g_ao[(size_t)NQ * C];          // attention out fp16
__device__ float g_act[(size_t)NQ * C];          // ACT = voxel[qidx] + proj(ao)
__device__ __half g_x[(size_t)NQ * C];           // LN2(ACT) fp16
__device__ __half g_f[(size_t)NQ * FF];          // relu(ff1) fp16
// weights transposed, single fp16, layout [n][k]
__device__ __half g_Bh[512 * 256];               // [wk|wv]
__device__ __half g_Wqh[256 * 256];
__device__ __half g_Wph[256 * 256];
__device__ __half g_W1h[512 * 256];
__device__ __half g_W2h[256 * 512];

// ---------------- helpers ----------------
__device__ __forceinline__ uint32_t smem_u32(const void* p) {
    uint32_t a;
    asm("{ .reg .u64 t; cvta.to.shared.u64 t, %1; cvt.u32.u64 %0, t; }" : "=r"(a) : "l"(p));
    return a;
}
__device__ __forceinline__ void cpasync16(uint32_t dst, const void* src) {
    asm volatile("cp.async.cg.shared.global [%0], [%1], 16;" :: "r"(dst), "l"(src));
}
#define CP_COMMIT()  asm volatile("cp.async.commit_group;" ::: "memory")
#define CP_WAIT(n)   asm volatile("cp.async.wait_group %0;" :: "n"(n) : "memory")

__device__ __forceinline__ void ldsm4(uint32_t* r, uint32_t addr) {
    asm volatile("ldmatrix.sync.aligned.m8n8.x4.shared.b16 {%0,%1,%2,%3}, [%4];"
        : "=r"(r[0]), "=r"(r[1]), "=r"(r[2]), "=r"(r[3]) : "r"(addr));
}
__device__ __forceinline__ void mma16816(float* c, const uint32_t* a, const uint32_t* b) {
    asm volatile(
        "mma.sync.aligned.m16n8k16.row.col.f32.f16.f16.f32 "
        "{%0,%1,%2,%3}, {%4,%5,%6,%7}, {%8,%9}, {%0,%1,%2,%3};"
        : "+f"(c[0]), "+f"(c[1]), "+f"(c[2]), "+f"(c[3])
        : "r"(a[0]), "r"(a[1]), "r"(a[2]), "r"(a[3]), "r"(b[0]), "r"(b[1]));
}

// ---------------- fused weight prep (all single fp16, transposed [n][k]) ----------
// blocks [0,512): [wk|wv] + bias rows   [512,768): w_q
// [768,1024): w_proj   [1024,1536): w_ff1   [1536,2048): w_ff2
__global__ void prep_kernel(const float* __restrict__ wk, const float* __restrict__ wv,
                            const float* __restrict__ bk, const float* __restrict__ bv,
                            const float* __restrict__ wq, const float* __restrict__ wp,
                            const float* __restrict__ w1, const float* __restrict__ w2) {
    int b = blockIdx.x, t = threadIdx.x;
    if (b < 512) {
        int idx = b * 256 + t;
        int n = idx >> 8, k = idx & 255;
        float val = (n < 256) ? wk[k * 256 + n] : wv[k * 256 + (n - 256)];
        g_Bh[idx] = __float2half(val);
        if (idx < 512)
            g_bkvh[idx] = __float2half((idx < 256) ? bk[idx] : bv[idx - 256]);
        return;
    }
    const float* src; __half* dh; int N, K, idx;
    if (b < 768)       { src = wq; dh = g_Wqh; N = 256; K = 256; idx = (b - 512) * 256 + t; }
    else if (b < 1024) { src = wp; dh = g_Wph; N = 256; K = 256; idx = (b - 768) * 256 + t; }
    else if (b < 1536) { src = w1; dh = g_W1h; N = 512; K = 256; idx = (b - 1024) * 256 + t; }
    else               { src = w2; dh = g_W2h; N = 256; K = 512; idx = (b - 1536) * 256 + t; }
    int n = idx / K, k = idx - n * K;
    dh[idx] = __float2half(src[k * N + n]);
}

// ---------------- kernel 1: LayerNorm over all M voxels -> fp16 (2 rows/warp) -----
__global__ void ln_kernel(const float* __restrict__ x,
                          const float* __restrict__ g,
                          const float* __restrict__ b) {
    int wid = threadIdx.x >> 5, lane = threadIdx.x & 31;
    int r0 = blockIdx.x * 16 + wid * 2;
    const float4* xr0 = (const float4*)(x + (size_t)r0 * C);
    const float4* xr1 = (const float4*)(x + (size_t)(r0 + 1) * C);
    float4 a0 = xr0[lane], a1 = xr0[lane + 32];
    float4 c0 = xr1[lane], c1 = xr1[lane + 32];
    float sA = a0.x + a0.y + a0.z + a0.w + a1.x + a1.y + a1.z + a1.w;
    float qA = a0.x*a0.x + a0.y*a0.y + a0.z*a0.z + a0.w*a0.w
             + a1.x*a1.x + a1.y*a1.y + a1.z*a1.z + a1.w*a1.w;
    float sB = c0.x + c0.y + c0.z + c0.w + c1.x + c1.y + c1.z + c1.w;
    float qB = c0.x*c0.x + c0.y*c0.y + c0.z*c0.z + c0.w*c0.w
             + c1.x*c1.x + c1.y*c1.y + c1.z*c1.z + c1.w*c1.w;
#pragma unroll
    for (int o = 16; o > 0; o >>= 1) {
        sA += __shfl_xor_sync(0xffffffffu, sA, o);
        qA += __shfl_xor_sync(0xffffffffu, qA, o);
        sB += __shfl_xor_sync(0xffffffffu, sB, o);
        qB += __shfl_xor_sync(0xffffffffu, qB, o);
    }
    float muA = sA * (1.0f / C);
    float rsA = rsqrtf(qA * (1.0f / C) - muA * muA + 1e-5f);
    float muB = sB * (1.0f / C);
    float rsB = rsqrtf(qB * (1.0f / C) - muB * muB + 1e-5f);
    int cc0 = lane * 4, cc1 = 128 + lane * 4;
    float g0 = g[cc0+0], g1 = g[cc0+1], g2 = g[cc0+2], g3 = g[cc0+3];
    float g4 = g[cc1+0], g5 = g[cc1+1], g6 = g[cc1+2], g7 = g[cc1+3];
    float b0 = b[cc0+0], b1 = b[cc0+1], b2 = b[cc0+2], b3 = b[cc0+3];
    float b4 = b[cc1+0], b5 = b[cc1+1], b6 = b[cc1+2], b7 = b[cc1+3];
    __half2* h0 = (__half2*)(g_lnh + (size_t)r0 * C);
    __half2* h1 = (__half2*)(g_lnh + (size_t)(r0 + 1) * C);
    h0[lane*2+0]  = __floats2half2_rn((a0.x - muA)*rsA*g0 + b0, (a0.y - muA)*rsA*g1 + b1);
    h0[lane*2+1]  = __floats2half2_rn((a0.z - muA)*rsA*g2 + b2, (a0.w - muA)*rsA*g3 + b3);
    h0[64+lane*2] = __floats2half2_rn((a1.x - muA)*rsA*g4 + b4, (a1.y - muA)*rsA*g5 + b5);
    h0[65+lane*2] = __floats2half2_rn((a1.z - muA)*rsA*g6 + b6, (a1.w - muA)*rsA*g7 + b7);
    h1[lane*2+0]  = __floats2half2_rn((c0.x - muB)*rsB*g0 + b0, (c0.y - muB)*rsB*g1 + b1);
    h1[lane*2+1]  = __floats2half2_rn((c0.z - muB)*rsB*g2 + b2, (c0.w - muB)*rsB*g3 + b3);
    h1[64+lane*2] = __floats2half2_rn((c1.x - muB)*rsB*g4 + b4, (c1.y - muB)*rsB*g5 + b5);
    h1[65+lane*2] = __floats2half2_rn((c1.z - muB)*rsB*g6 + b6, (c1.w - muB)*rsB*g7 + b7);
}

// ---------------- kernel: qin = ln[qidx] + relu(coords @ w_pos + b_pos) ---------
__global__ void qin_kernel(const float* __restrict__ coords, const int* __restrict__ qidx,
                           const float* __restrict__ w_pos, const float* __restrict__ b_pos) {
    int n = blockIdx.x, t = threadIdx.x;
    float cx = coords[n*3+0], cy = coords[n*3+1], cz = coords[n*3+2];
    float p = cx * w_pos[t] + cy * w_pos[C + t] + cz * w_pos[2*C + t] + b_pos[t];
    p = fmaxf(p, 0.0f);
    float lnv = __half2float(g_lnh[(size_t)qidx[n] * C + t]);
    g_qin[(size_t)n * C + t] = __float2half(lnv + p);
}

// ---------------- kernel: q-side positional bias (reads g_q) ----------------
__global__ void qp_kernel(const float* __restrict__ pqx, const float* __restrict__ pqy,
                          const float* __restrict__ pqz) {
    __shared__ float qs[32 * C];
    int t = threadIdx.x;
    int n0 = blockIdx.x * 32;
    for (int i = t; i < 32 * C; i += 256) qs[i] = g_q[(size_t)n0 * C + i];
    __syncthreads();
    for (int idx = t; idx < 32 * HH * 37; idx += 256) {
        int r   = idx / (HH * 37);
        int rem = idx - r * (HH * 37);
        int h   = rem / 37;
        int j   = rem - h * 37;
        const float* tab; int rr, stride;
        if (j < 15)      { tab = pqx + h * DHD * 15; rr = j;      stride = 15; }
        else if (j < 30) { tab = pqy + h * DHD * 15; rr = j - 15; stride = 15; }
        else             { tab = pqz + h * DHD * 7;  rr = j - 30; stride = 7;  }
        float s = 0.0f;
        const float* qrow = qs + r*C + h*DHD;
#pragma unroll
        for (int d = 0; d < DHD; d++) s = fmaf(qrow[d], __ldg(&tab[d*stride + rr]), s);
        g_qp[((size_t)(n0 + r)*HH + h)*37 + j] = s;
    }
}

// ---------------- MMA tile configs ----------------
#define APITCH 40
#define MAT_BYTES (128 * APITCH * 2)        // 10240  (128 rows x 32 cols fp16 @ pitch 40)
#define MATA64 (64 * APITCH * 2)            // 5120
// kvgemm v2: full A resident (8 chunks) + B double buffer
#define KV_SMEM (8 * MAT_BYTES + 2 * MAT_BYTES)   // 102400

// ---------------- kernel 3: K/V GEMM, A-resident, 4 n-tiles per CTA ---------------
__global__ __launch_bounds__(256, 2)
void kvgemm_kernel(const float* __restrict__ bk, const float* __restrict__ bv) {
    extern __shared__ __align__(16) char gsm[];
    uint32_t sb = smem_u32(gsm);
    uint32_t bbase0 = sb + 8 * MAT_BYTES;
    int t = threadIdx.x;
    int warp = t >> 5, lane = t & 31;
    int m0 = blockIdx.x * 128;

    // load full A tile: 128 rows x 256 cols = 8 chunks of (128 x 32)
#pragma unroll
    for (int i = 0; i < 16; i++) {
        int u = t + i * 256;          // 0..4095 16B-units
        int kc = u >> 9;
        int rem = u & 511;
        int row = rem >> 2, seg = rem & 3;
        int gr = m0 + row; if (gr >= M_VOX) gr = 0;
        size_t go = (size_t)gr * 256 + kc * 32 + seg * 8;
        cpasync16(sb + kc * MAT_BYTES + (row * APITCH + seg * 8) * 2, g_lnh + go);
    }
    auto loadB = [&](int j, int buf) {
        int nt = j >> 3, kc = j & 7;
#pragma unroll
        for (int i = 0; i < 2; i++) {
            int u = t + i * 256;
            int row = u >> 2, seg = u & 3;
            size_t gb = (size_t)(nt * 128 + row) * 256 + kc * 32 + seg * 8;
            cpasync16(bbase0 + buf * MAT_BYTES + (row * APITCH + seg * 8) * 2, g_Bh + gb);
        }
    };
    loadB(0, 0); CP_COMMIT();        // group 0 = A + B(0)

    int wm = warp & 1, wn = warp >> 1;
    float acc[4][4][4];
#pragma unroll
    for (int a = 0; a < 4; a++)
#pragma unroll
        for (int bq = 0; bq < 4; bq++)
#pragma unroll
            for (int cq = 0; cq < 4; cq++) acc[a][bq][cq] = 0.0f;

    for (int j = 0; j < 32; j++) {
        int buf = j & 1;
        if (j < 31) { loadB(j + 1, buf ^ 1); CP_COMMIT(); CP_WAIT(1); }
        else        { CP_WAIT(0); }
        __syncthreads();
        int kc = j & 7;
        uint32_t abase = sb + kc * MAT_BYTES;
        uint32_t bb = bbase0 + buf * MAT_BYTES;
        uint32_t bh[4][4];
#pragma unroll
        for (int ni = 0; ni < 4; ni++) {
            int nrow = wn * 32 + ni * 8 + (lane & 7);
            int koff = (lane >> 3) * 8;
            ldsm4(bh[ni], bb + (nrow * APITCH + koff) * 2);
        }
#pragma unroll
        for (int s = 0; s < 2; s++) {
#pragma unroll
            for (int mi = 0; mi < 4; mi++) {
                int arow = wm * 64 + mi * 16 + (lane & 15);
                int koff = s * 16 + (lane >> 4) * 8;
                uint32_t ah[4];
                ldsm4(ah, abase + (arow * APITCH + koff) * 2);
#pragma unroll
                for (int ni = 0; ni < 4; ni++)
                    mma16816(acc[mi][ni], ah, &bh[ni][s*2]);
            }
        }
        __syncthreads();

        if (kc == 7) {
            int nt = j >> 3;
            __half* dst = (nt < 2) ? g_kall : g_vall;
            const float* bias = (nt < 2) ? bk : bv;
            int cb = (nt & 1) * 128;
#pragma unroll
            for (int mi = 0; mi < 4; mi++) {
#pragma unroll
                for (int ni = 0; ni < 4; ni++) {
                    int col = cb + wn * 32 + ni * 8 + (lane & 3) * 2;
                    float b0 = bias[col], b1 = bias[col + 1];
                    int r0 = m0 + wm * 64 + mi * 16 + (lane >> 2);
                    if (r0 < M_VOX)
                        *(__half2*)(dst + (size_t)r0 * 256 + col) =
                            __floats2half2_rn(acc[mi][ni][0] + b0, acc[mi][ni][1] + b1);
                    int r1 = r0 + 8;
                    if (r1 < M_VOX)
                        *(__half2*)(dst + (size_t)r1 * 256 + col) =
                            __floats2half2_rn(acc[mi][ni][2] + b0, acc[mi][ni][3] + b1);
#pragma unroll
                    for (int cq = 0; cq < 4; cq++) acc[mi][ni][cq] = 0.0f;
                }
            }
        }
    }
}

// ---------------- generic single-fp16 MMA GEMM, 64-row tiles, fused epilogues -----
// EPI 0: outf = acc + bias + add_src[qidx[row]]   (proj -> g_act)
// EPI 1: relu(acc + bias) -> fp16 outh            (ff1), pitch opitch
// EPI 2: outf = acc + bias + add_src[row]         (ff2 -> d_out)
// EPI 3: outf = acc + bias                        (q -> g_q)
template<int EPI>
__global__ __launch_bounds__(256, 2)
void mmagemm_kernel(const __half* __restrict__ Ah, int K,
                    const __half* __restrict__ Bh,
                    const float* __restrict__ bias,
                    const float* __restrict__ add_src, const int* __restrict__ qidx,
                    float* __restrict__ outf, __half* __restrict__ outh, int opitch) {
    constexpr int STAGE = MATA64 + MAT_BYTES;       // 15360
    extern __shared__ __align__(16) char gsm[];
    uint32_t sb = smem_u32(gsm);
    int t = threadIdx.x;
    int warp = t >> 5, lane = t & 31;
    int n0 = blockIdx.x * 128;
    int m0 = blockIdx.y * 64;

    auto load_chunk = [&](int kc, int buf) {
        uint32_t base = sb + buf * STAGE;
        {
            int row = t >> 2, seg = t & 3;
            size_t go = (size_t)(m0 + row) * K + kc * 32 + seg * 8;
            cpasync16(base + (row * APITCH + seg * 8) * 2, Ah + go);
        }
#pragma unroll
        for (int i = 0; i < 2; i++) {
            int u = t + i * 256;
            int row = u >> 2, seg = u & 3;
            size_t gb = (size_t)(n0 + row) * K + kc * 32 + seg * 8;
            cpasync16(base + MATA64 + (row * APITCH + seg * 8) * 2, Bh + gb);
        }
    };

    int wm = warp & 1, wn = warp >> 1;
    float acc[2][4][4];
#pragma unroll
    for (int a = 0; a < 2; a++)
#pragma unroll
        for (int bq = 0; bq < 4; bq++)
#pragma unroll
            for (int cq = 0; cq < 4; cq++) acc[a][bq][cq] = 0.0f;

    int nchunks = K >> 5;
    load_chunk(0, 0); CP_COMMIT();

    for (int kc = 0; kc < nchunks; kc++) {
        int buf = kc & 1;
        if (kc < nchunks - 1) { load_chunk(kc + 1, buf ^ 1); CP_COMMIT(); CP_WAIT(1); }
        else                  { CP_WAIT(0); }
        __syncthreads();

        uint32_t abase = sb + buf * STAGE;
        uint32_t bbase = abase + MATA64;
        uint32_t bh[4][4];
#pragma unroll
        for (int ni = 0; ni < 4; ni++) {
            int nrow = wn * 32 + ni * 8 + (lane & 7);
            int koff = (lane >> 3) * 8;
            ldsm4(bh[ni], bbase + (nrow * APITCH + koff) * 2);
        }
#pragma unroll
        for (int s = 0; s < 2; s++) {
#pragma unroll
            for (int mi = 0; mi < 2; mi++) {
                int arow = wm * 32 + mi * 16 + (lane & 15);
                int koff = s * 16 + (lane >> 4) * 8;
                uint32_t ah[4];
                ldsm4(ah, abase + (arow * APITCH + koff) * 2);
#pragma unroll
                for (int ni = 0; ni < 4; ni++)
                    mma16816(acc[mi][ni], ah, &bh[ni][s*2]);
            }
        }
        __syncthreads();
    }

#pragma unroll
    for (int mi = 0; mi < 2; mi++) {
#pragma unroll
        for (int ni = 0; ni < 4; ni++) {
            int col = n0 + wn * 32 + ni * 8 + (lane & 3) * 2;
            float b0 = bias[col], b1 = bias[col + 1];
#pragma unroll
            for (int half = 0; half < 2; half++) {
                int r = m0 + wm * 32 + mi * 16 + (lane >> 2) + half * 8;
                float v0 = acc[mi][ni][half*2+0] + b0;
                float v1 = acc[mi][ni][half*2+1] + b1;
                if (EPI == 0) {
                    size_t voff = (size_t)qidx[r] * 256 + col;
                    v0 += add_src[voff];
                    v1 += add_src[voff + 1];
                    *(float2*)(outf + (size_t)r * 256 + col) = make_float2(v0, v1);
                } else if (EPI == 1) {
                    v0 = fmaxf(v0, 0.0f);
                    v1 = fmaxf(v1, 0.0f);
                    *(__half2*)(outh + (size_t)r * opitch + col) = __floats2half2_rn(v0, v1);
                } else if (EPI == 2) {
                    size_t aoff = (size_t)r * 256 + col;
                    v0 += add_src[aoff];
                    v1 += add_src[aoff + 1];
                    *(float2*)(outf + aoff) = make_float2(v0, v1);
                } else {
                    *(float2*)(outf + (size_t)r * 256 + col) = make_float2(v0, v1);
                }
            }
        }
    }
}

// ---------------- kernel 4: attention per query (fp16 k/v staging) ----------------
#define KPITCH 264   // halfs per row (528B)
__global__ __launch_bounds__(256)
void attn_kernel(const int* __restrict__ gidx, const int* __restrict__ gmask,
                 const int* __restrict__ rel_x, const int* __restrict__ rel_y,
                 const int* __restrict__ rel_z,
                 const float* __restrict__ pkx, const float* __restrict__ pky,
                 const float* __restrict__ pkz) {
    extern __shared__ __half sm4h[];
    __half* k_s = sm4h;                   // 32 x KPITCH halfs
    __half* v_s = sm4h + 32 * KPITCH;
    __shared__ float q_s[256];
    __shared__ float qp_s[296];
    __shared__ float attn_s[HH][KNN];
    __shared__ int idx_s[32], msk_s[32], rx_s[32], ry_s[32], rz_s[32];
    int n = blockIdx.x, t = threadIdx.x;
    if (t < 32) {
        idx_s[t] = gidx[n*KNN + t];
        msk_s[t] = gmask[n*KNN + t];
        rx_s[t]  = rel_x[n*KNN + t];
        ry_s[t]  = rel_y[n*KNN + t];
        rz_s[t]  = rel_z[n*KNN + t];
    } else if (t < 96) {
        int i = t - 32;
        ((float4*)q_s)[i] = ((const float4*)(g_q + (size_t)n * C))[i];
    } else if (t < 170) {
        int i = t - 96;
        ((float4*)qp_s)[i] = ((const float4*)(g_qp + (size_t)n * 296))[i];
    }
    __syncthreads();
#pragma unroll
    for (int i = 0; i < 4; i++) {
        int u = t + i * 256;
        int row = u >> 5, seg = u & 31;
        bool m = (msk_s[row] != 0);
        const uint4* ks = m ? (const uint4*)(g_bkvh)
                            : (const uint4*)(g_kall + (size_t)idx_s[row] * C);
        const uint4* vs = m ? (const uint4*)(g_bkvh + 256)
                            : (const uint4*)(g_vall + (size_t)idx_s[row] * C);
        *(uint4*)(k_s + row * KPITCH + seg * 8) = __ldg(&ks[seg]);
        *(uint4*)(v_s + row * KPITCH + seg * 8) = __ldg(&vs[seg]);
    }
    __syncthreads();

    int h = t >> 5, lane = t & 31;
    {
        int rx = rx_s[lane], ry = ry_s[lane], rz = rz_s[lane];
        bool msk = (msk_s[lane] != 0);
        const __half2* krow = (const __half2*)(k_s + lane * KPITCH + h * DHD);
        const float* qh   = q_s + h * DHD;
        const float* pbx = pkx + h * DHD * 15 + rx;
        const float* pby = pky + h * DHD * 15 + ry;
        const float* pbz = pkz + h * DHD * 7  + rz;
        float qk = 0.0f, bias = 0.0f;
#pragma unroll
        for (int d2 = 0; d2 < DHD / 2; d2++) {
            float2 kv = __half22float2(krow[d2]);
            qk = fmaf(qh[d2*2+0], kv.x, qk);
            qk = fmaf(qh[d2*2+1], kv.y, qk);
            float pw0 = __ldg(pbx + (d2*2+0) * 15) + __ldg(pby + (d2*2+0) * 15) + __ldg(pbz + (d2*2+0) * 7);
            float pw1 = __ldg(pbx + (d2*2+1) * 15) + __ldg(pby + (d2*2+1) * 15) + __ldg(pbz + (d2*2+1) * 7);
            bias = fmaf(kv.x, pw0, bias);
            bias = fmaf(kv.y, pw1, bias);
        }
        const float* qpn = qp_s + h * 37;
        float logit = qk * 0.17677669529663687f + qpn[rx] + qpn[15 + ry] + qpn[30 + rz] + bias;
        if (msk) logit = -1e9f;
        float m = logit;
#pragma unroll
        for (int o = 16; o > 0; o >>= 1) m = fmaxf(m, __shfl_xor_sync(0xffffffffu, m, o));
        float p = expf(logit - m);
        float s = p;
#pragma unroll
        for (int o = 16; o > 0; o >>= 1) s += __shfl_xor_sync(0xffffffffu, s, o);
        attn_s[h][lane] = p / s;
    }
    __syncwarp();
    {
        float o = 0.0f;
        const __half* vcol = v_s + h * DHD + lane;
        const float* aw = attn_s[h];
#pragma unroll
        for (int kk = 0; kk < KNN; kk++)
            o = fmaf(aw[kk], __half2float(vcol[kk * KPITCH]), o);
        g_ao[(size_t)n * C + h * DHD + lane] = __float2half(o);
    }
}

// ---------------- kernel: LN2 over ACT -> fp16 ----------------
__global__ void ln2_kernel(const float* __restrict__ g, const float* __restrict__ b) {
    int row = blockIdx.x * 8 + (threadIdx.x >> 5);
    int lane = threadIdx.x & 31;
    const float4* xr = (const float4*)(g_act + (size_t)row * C);
    float4 v0 = xr[lane];
    float4 v1 = xr[lane + 32];
    float s = v0.x + v0.y + v0.z + v0.w + v1.x + v1.y + v1.z + v1.w;
    float q = v0.x*v0.x + v0.y*v0.y + v0.z*v0.z + v0.w*v0.w
            + v1.x*v1.x + v1.y*v1.y + v1.z*v1.z + v1.w*v1.w;
#pragma unroll
    for (int o = 16; o > 0; o >>= 1) {
        s += __shfl_xor_sync(0xffffffffu, s, o);
        q += __shfl_xor_sync(0xffffffffu, q, o);
    }
    float mu = s * (1.0f / C);
    float rs = rsqrtf(q * (1.0f / C) - mu * mu + 1e-5f);
    int c0 = lane * 4, c1 = 128 + lane * 4;
    __half2* hrow = (__half2*)(g_x + (size_t)row * C);
    hrow[lane*2+0]  = __floats2half2_rn((v0.x - mu) * rs * g[c0+0] + b[c0+0],
                                        (v0.y - mu) * rs * g[c0+1] + b[c0+1]);
    hrow[lane*2+1]  = __floats2half2_rn((v0.z - mu) * rs * g[c0+2] + b[c0+2],
                                        (v0.w - mu) * rs * g[c0+3] + b[c0+3]);
    hrow[64+lane*2] = __floats2half2_rn((v1.x - mu) * rs * g[c1+0] + b[c1+0],
                                        (v1.y - mu) * rs * g[c1+1] + b[c1+1]);
    hrow[65+lane*2] = __floats2half2_rn((v1.z - mu) * rs * g[c1+2] + b[c1+2],
                                        (v1.w - mu) * rs * g[c1+3] + b[c1+3]);
}

// ---------------- launch ----------------
extern "C" void kernel_launch(void* const* d_in, const int* in_sizes, int n_in,
                              void* d_out, int out_size) {
    const float* voxel  = (const float*)d_in[0];
    const float* coords = (const float*)d_in[1];
    const int*   qidx   = (const int*)d_in[2];
    const int*   gidx   = (const int*)d_in[3];
    const int*   gmask  = (const int*)d_in[4];
    const int*   rel_x  = (const int*)d_in[5];
    const int*   rel_y  = (const int*)d_in[6];
    const int*   rel_z  = (const int*)d_in[7];
    const float* w_pos  = (const float*)d_in[8];
    const float* b_pos  = (const float*)d_in[9];
    const float* w_q    = (const float*)d_in[10];
    const float* b_q    = (const float*)d_in[11];
    const float* w_k    = (const float*)d_in[12];
    const float* b_k    = (const float*)d_in[13];
    const float* w_v    = (const float*)d_in[14];
    const float* b_v    = (const float*)d_in[15];
    const float* w_proj = (const float*)d_in[16];
    const float* b_proj = (const float*)d_in[17];
    const float* ln1g   = (const float*)d_in[18];
    const float* ln1b   = (const float*)d_in[19];
    const float* ln2g   = (const float*)d_in[20];
    const float* ln2b   = (const float*)d_in[21];
    const float* w_ff1  = (const float*)d_in[22];
    const float* b_ff1  = (const float*)d_in[23];
    const float* w_ff2  = (const float*)d_in[24];
    const float* b_ff2  = (const float*)d_in[25];
    const float* pqx    = (const float*)d_in[26];
    const float* pqy    = (const float*)d_in[27];
    const float* pqz    = (const float*)d_in[28];
    const float* pkx    = (const float*)d_in[29];
    const float* pky    = (const float*)d_in[30];
    const float* pkz    = (const float*)d_in[31];
    float* out = (float*)d_out;

    int attn_smem = 2 * 32 * KPITCH * 2;
    int stage2 = 2 * (MATA64 + MAT_BYTES);     // 30720

    cudaFuncSetAttribute(kvgemm_kernel,     cudaFuncAttributeMaxDynamicSharedMemorySize, KV_SMEM);
    cudaFuncSetAttribute(mmagemm_kernel<0>, cudaFuncAttributeMaxDynamicSharedMemorySize, stage2);
    cudaFuncSetAttribute(mmagemm_kernel<1>, cudaFuncAttributeMaxDynamicSharedMemorySize, stage2);
    cudaFuncSetAttribute(mmagemm_kernel<2>, cudaFuncAttributeMaxDynamicSharedMemorySize, stage2);
    cudaFuncSetAttribute(mmagemm_kernel<3>, cudaFuncAttributeMaxDynamicSharedMemorySize, stage2);
    cudaFuncSetAttribute(attn_kernel,       cudaFuncAttributeMaxDynamicSharedMemorySize, attn_smem);

    __half *Wqh, *Wph, *W1h, *W2h;
    __half *qin, *ao, *xh, *fh;
    float *act, *qv;
    cudaGetSymbolAddress((void**)&Wqh, g_Wqh);
    cudaGetSymbolAddress((void**)&Wph, g_Wph);
    cudaGetSymbolAddress((void**)&W1h, g_W1h);
    cudaGetSymbolAddress((void**)&W2h, g_W2h);
    cudaGetSymbolAddress((void**)&qin, g_qin); cudaGetSymbolAddress((void**)&ao, g_ao);
    cudaGetSymbolAddress((void**)&xh, g_x);    cudaGetSymbolAddress((void**)&fh, g_f);
    cudaGetSymbolAddress((void**)&act, g_act); cudaGetSymbolAddress((void**)&qv, g_q);

    prep_kernel<<<2048, 256>>>(w_k, w_v, b_k, b_v, w_q, w_proj, w_ff1, w_ff2);
    ln_kernel<<<M_VOX / 16, 256>>>(voxel, ln1g, ln1b);
    qin_kernel<<<NQ, 256>>>(coords, qidx, w_pos, b_pos);
    // q = qin @ w_q + b_q
    mmagemm_kernel<3><<<dim3(2, NQ / 64), 256, stage2>>>(
        qin, 256, Wqh, b_q, nullptr, nullptr, qv, nullptr, 0);
    qp_kernel<<<NQ / 32, 256>>>(pqx, pqy, pqz);
    kvgemm_kernel<<<(M_VOX + 127) / 128, 256, KV_SMEM>>>(b_k, b_v);
    attn_kernel<<<NQ, 256, attn_smem>>>(gidx, gmask, rel_x, rel_y, rel_z,
                                        pkx, pky, pkz);
    // proj: ACT = ao @ w_proj + b_proj + voxel[qidx]
    mmagemm_kernel<0><<<dim3(2, NQ / 64), 256, stage2>>>(
        ao, 256, Wph, b_proj, voxel, qidx, act, nullptr, 0);
    ln2_kernel<<<NQ / 8, 256>>>(ln2g, ln2b);
    // ff1: F = relu(X @ w_ff1 + b_ff1)
    mmagemm_kernel<1><<<dim3(4, NQ / 64), 256, stage2>>>(
        xh, 256, W1h, b_ff1, nullptr, nullptr, nullptr, fh, 512);
    // ff2: out = ACT + F @ w_ff2 + b_ff2
    mmagemm_kernel<2><<<dim3(2, NQ / 64), 256, stage2>>>(
        fh, 512, W2h, b_ff2, act, nullptr, out, nullptr, 0);
}